// round 2
// baseline (speedup 1.0000x reference)
#include <cuda_runtime.h>
#include <math.h>

#define SEQ 1024
#define DIM 1024
#define NB  4
#define NHEAD 16
#define HD  64
#define NEGV (-10000.0f)

// ---------------- scratch (no allocations allowed) ----------------
__device__ float g_qkv[(size_t)NB*SEQ*3*DIM];            // 48 MB
__device__ float g_scores[(size_t)NB*NHEAD*SEQ*SEQ];     // 256 MB
__device__ float g_a [(size_t)NB*SEQ*DIM];
__device__ float g_x1[(size_t)NB*SEQ*DIM];
__device__ float g_q [(size_t)NB*SEQ*DIM];
__device__ float g_kv[(size_t)NB*SEQ*2*DIM];
__device__ float g_h [(size_t)NB*SEQ*4*DIM];             // 64 MB
__device__ float g_x2[(size_t)NB*SEQ*DIM];
__device__ float g_t [(size_t)NB*SEQ*DIM];

enum { EPI_NONE=0, EPI_BIAS=1, EPI_BIAS_GELU=2, EPI_SCALE=3, EPI_SCALE_CAUSAL=4 };

__device__ __forceinline__ float gelu_tanh(float v){
    float u = 0.7978845608028654f * (v + 0.044715f * v * v * v);
    return 0.5f * v * (1.0f + tanhf(u));
}

// ---------------- generic tiled fp32 GEMM ----------------
// C[M,N] = epi( A[M,K] * op(B) )   op(B): B[K,N] (ldb) or B^T of B[N,K] (ldb)
// Batched over grid.z with (b,h) decomposition: bz -> bb=bz/nh, hh=bz%nh.
// M,N multiples of 64; K multiple of 16 (all true for this problem).
template<bool TRANSB, int EPI>
__global__ void __launch_bounds__(256) gemm64(
    const float* __restrict__ A, const float* __restrict__ Bm,
    const float* __restrict__ bias, float* __restrict__ C,
    int K, int lda, int ldb, int ldc,
    long sA1, long sA2, long sB1, long sB2, long sC1, long sC2,
    int nh, float scale)
{
    const int bz = blockIdx.z;
    const int bb = bz / nh, hh = bz - bb * nh;
    A  += bb * sA1 + hh * sA2;
    Bm += bb * sB1 + hh * sB2;
    C  += bb * sC1 + hh * sC2;

    const int row0 = blockIdx.y * 64;
    const int col0 = blockIdx.x * 64;
    const int tid  = threadIdx.x;
    const int tx   = tid & 15, ty = tid >> 4;

    // Fully-masked causal tile: skip all compute.
    if (EPI == EPI_SCALE_CAUSAL && col0 > row0 + 63) {
        #pragma unroll
        for (int i = 0; i < 4; i++) {
            int r = row0 + ty*4 + i;
            #pragma unroll
            for (int j = 0; j < 4; j++)
                C[(long)r*ldc + col0 + tx*4 + j] = NEGV;
        }
        return;
    }

    __shared__ float As[16][68];   // pad 68: <=2-way STS conflicts, 16B-aligned rows
    __shared__ float Bs[16][68];

    float acc[4][4] = {};

    for (int k0 = 0; k0 < K; k0 += 16) {
        #pragma unroll
        for (int i = 0; i < 4; i++) {
            int idx = tid + i*256;
            int m = idx >> 4, kk = idx & 15;
            As[kk][m] = A[(long)(row0 + m)*lda + k0 + kk];
        }
        if (!TRANSB) {
            #pragma unroll
            for (int i = 0; i < 4; i++) {
                int idx = tid + i*256;
                int kk = idx >> 6, n = idx & 63;
                Bs[kk][n] = Bm[(long)(k0 + kk)*ldb + col0 + n];
            }
        } else {
            #pragma unroll
            for (int i = 0; i < 4; i++) {
                int idx = tid + i*256;
                int n = idx >> 4, kk = idx & 15;
                Bs[kk][n] = Bm[(long)(col0 + n)*ldb + k0 + kk];
            }
        }
        __syncthreads();

        #pragma unroll
        for (int kk = 0; kk < 16; kk++) {
            float4 av = *(const float4*)&As[kk][ty*4];
            float4 bv = *(const float4*)&Bs[kk][tx*4];
            float a0[4] = {av.x, av.y, av.z, av.w};
            float b0[4] = {bv.x, bv.y, bv.z, bv.w};
            #pragma unroll
            for (int i = 0; i < 4; i++)
                #pragma unroll
                for (int j = 0; j < 4; j++)
                    acc[i][j] += a0[i] * b0[j];
        }
        __syncthreads();
    }

    #pragma unroll
    for (int i = 0; i < 4; i++) {
        int r = row0 + ty*4 + i;
        #pragma unroll
        for (int j = 0; j < 4; j++) {
            int c = col0 + tx*4 + j;
            float v = acc[i][j];
            if (EPI == EPI_BIAS)       v += bias[c];
            if (EPI == EPI_BIAS_GELU)  v = gelu_tanh(v + bias[c]);
            if (EPI == EPI_SCALE)      v *= scale;
            if (EPI == EPI_SCALE_CAUSAL) { v *= scale; if (c > r) v = NEGV; }
            C[(long)r*ldc + c] = v;
        }
    }
}

// ---------------- row softmax (in-place), row length 1024 ----------------
__global__ void __launch_bounds__(256) softmax_rows(float* __restrict__ s)
{
    __shared__ float red[8];
    __shared__ float bc;
    long row = blockIdx.x;
    float* p = s + row * SEQ;
    int tid = threadIdx.x, lane = tid & 31, wid = tid >> 5;

    float v[4], m = -3.4e38f;
    #pragma unroll
    for (int i = 0; i < 4; i++) { v[i] = p[tid + i*256]; m = fmaxf(m, v[i]); }
    #pragma unroll
    for (int o = 16; o > 0; o >>= 1) m = fmaxf(m, __shfl_xor_sync(0xffffffffu, m, o));
    if (lane == 0) red[wid] = m;
    __syncthreads();
    if (tid == 0) {
        float t = red[0];
        #pragma unroll
        for (int i = 1; i < 8; i++) t = fmaxf(t, red[i]);
        bc = t;
    }
    __syncthreads();
    m = bc;

    float sum = 0.f;
    #pragma unroll
    for (int i = 0; i < 4; i++) { v[i] = __expf(v[i] - m); sum += v[i]; }
    #pragma unroll
    for (int o = 16; o > 0; o >>= 1) sum += __shfl_xor_sync(0xffffffffu, sum, o);
    __syncthreads();
    if (lane == 0) red[wid] = sum;
    __syncthreads();
    if (tid == 0) {
        float t = 0.f;
        #pragma unroll
        for (int i = 0; i < 8; i++) t += red[i];
        bc = 1.0f / t;
    }
    __syncthreads();
    float inv = bc;
    #pragma unroll
    for (int i = 0; i < 4; i++) p[tid + i*256] = v[i] * inv;
}

// ---------------- fused residual add + LayerNorm (row length 1024) ----------------
__global__ void __launch_bounds__(256) add_ln(
    const float* __restrict__ x, const float* __restrict__ a,
    const float* __restrict__ g, const float* __restrict__ b,
    float* __restrict__ y)
{
    __shared__ float red[8];
    __shared__ float bc;
    long row = blockIdx.x;
    const float* xr = x + row * DIM;
    const float* ar = a + row * DIM;
    float* yr = y + row * DIM;
    int tid = threadIdx.x, lane = tid & 31, wid = tid >> 5;

    float v[4], s = 0.f;
    #pragma unroll
    for (int i = 0; i < 4; i++) { int c = tid + i*256; v[i] = xr[c] + ar[c]; s += v[i]; }
    #pragma unroll
    for (int o = 16; o > 0; o >>= 1) s += __shfl_xor_sync(0xffffffffu, s, o);
    if (lane == 0) red[wid] = s;
    __syncthreads();
    if (tid == 0) {
        float t = 0.f;
        #pragma unroll
        for (int i = 0; i < 8; i++) t += red[i];
        bc = t * (1.0f / DIM);
    }
    __syncthreads();
    float mu = bc;

    float q = 0.f;
    #pragma unroll
    for (int i = 0; i < 4; i++) { float d = v[i] - mu; q += d * d; }
    #pragma unroll
    for (int o = 16; o > 0; o >>= 1) q += __shfl_xor_sync(0xffffffffu, q, o);
    __syncthreads();
    if (lane == 0) red[wid] = q;
    __syncthreads();
    if (tid == 0) {
        float t = 0.f;
        #pragma unroll
        for (int i = 0; i < 8; i++) t += red[i];
        bc = rsqrtf(t * (1.0f / DIM) + 1e-5f);
    }
    __syncthreads();
    float inv = bc;
    #pragma unroll
    for (int i = 0; i < 4; i++) {
        int c = tid + i*256;
        yr[c] = (v[i] - mu) * inv * g[c] + b[c];
    }
}

// ---------------- host orchestration ----------------
extern "C" void kernel_launch(void* const* d_in, const int* in_sizes, int n_in,
                              void* d_out, int out_size)
{
    const float* x            = (const float*)d_in[0];
    const float* ctx          = (const float*)d_in[1];
    const float* c_attn_w     = (const float*)d_in[2];
    const float* c_attn_b     = (const float*)d_in[3];
    const float* self_proj_w  = (const float*)d_in[4];
    const float* self_proj_b  = (const float*)d_in[5];
    const float* q_w          = (const float*)d_in[6];
    const float* q_b          = (const float*)d_in[7];
    const float* kv_w         = (const float*)d_in[8];
    const float* kv_b         = (const float*)d_in[9];
    const float* cross_proj_w = (const float*)d_in[10];
    const float* cross_proj_b = (const float*)d_in[11];
    const float* fc_w         = (const float*)d_in[12];
    const float* fc_b         = (const float*)d_in[13];
    const float* mlp_proj_w   = (const float*)d_in[14];
    const float* mlp_proj_b   = (const float*)d_in[15];
    const float* ln1_g        = (const float*)d_in[16];
    const float* ln1_b        = (const float*)d_in[17];
    const float* ln2_g        = (const float*)d_in[18];
    const float* ln2_b        = (const float*)d_in[19];
    const float* ln3_g        = (const float*)d_in[20];
    const float* ln3_b        = (const float*)d_in[21];
    float* out = (float*)d_out;

    float *qkv, *scores, *abuf, *x1, *q, *kv, *h, *x2, *t;
    cudaGetSymbolAddress((void**)&qkv,    g_qkv);
    cudaGetSymbolAddress((void**)&scores, g_scores);
    cudaGetSymbolAddress((void**)&abuf,   g_a);
    cudaGetSymbolAddress((void**)&x1,     g_x1);
    cudaGetSymbolAddress((void**)&q,      g_q);
    cudaGetSymbolAddress((void**)&kv,     g_kv);
    cudaGetSymbolAddress((void**)&h,      g_h);
    cudaGetSymbolAddress((void**)&x2,     g_x2);
    cudaGetSymbolAddress((void**)&t,      g_t);

    const int M  = NB * SEQ;            // 4096 flattened rows
    const long SS = (long)SEQ * SEQ;
    const float scale = 1.0f / 8.0f;    // 1/sqrt(64)

    // 1. qkv = x @ c_attn_w + b       [4096,1024]x[1024,3072]
    gemm64<false, EPI_BIAS><<<dim3(3*DIM/64, M/64, 1), 256>>>(
        x, c_attn_w, c_attn_b, qkv, DIM, DIM, 3*DIM, 3*DIM,
        0,0, 0,0, 0,0, 1, 0.f);

    // 2. self scores = Q K^T * scale, causal   batched over B*H
    gemm64<true, EPI_SCALE_CAUSAL><<<dim3(SEQ/64, SEQ/64, NB*NHEAD), 256>>>(
        qkv, qkv + DIM, nullptr, scores, HD, 3*DIM, 3*DIM, SEQ,
        (long)SEQ*3*DIM, HD, (long)SEQ*3*DIM, HD, (long)NHEAD*SS, SS, NHEAD, scale);

    // 3. softmax
    softmax_rows<<<NB*NHEAD*SEQ, 256>>>(scores);

    // 4. a = P @ V
    gemm64<false, EPI_NONE><<<dim3(HD/64, SEQ/64, NB*NHEAD), 256>>>(
        scores, qkv + 2*DIM, nullptr, abuf, SEQ, SEQ, 3*DIM, DIM,
        (long)NHEAD*SS, SS, (long)SEQ*3*DIM, HD, (long)SEQ*DIM, HD, NHEAD, 0.f);

    // 5. t = a @ self_proj_w + b
    gemm64<false, EPI_BIAS><<<dim3(DIM/64, M/64, 1), 256>>>(
        abuf, self_proj_w, self_proj_b, t, DIM, DIM, DIM, DIM,
        0,0, 0,0, 0,0, 1, 0.f);

    // 6. x1 = LN(x + t)
    add_ln<<<M, 256>>>(x, t, ln1_g, ln1_b, x1);

    // 7. q = x1 @ q_w + b
    gemm64<false, EPI_BIAS><<<dim3(DIM/64, M/64, 1), 256>>>(
        x1, q_w, q_b, q, DIM, DIM, DIM, DIM, 0,0, 0,0, 0,0, 1, 0.f);

    // 8. kv = ctx @ kv_w + b
    gemm64<false, EPI_BIAS><<<dim3(2*DIM/64, M/64, 1), 256>>>(
        ctx, kv_w, kv_b, kv, DIM, DIM, 2*DIM, 2*DIM, 0,0, 0,0, 0,0, 1, 0.f);

    // 9. cross scores = Qc Kc^T * scale (no mask)
    gemm64<true, EPI_SCALE><<<dim3(SEQ/64, SEQ/64, NB*NHEAD), 256>>>(
        q, kv, nullptr, scores, HD, DIM, 2*DIM, SEQ,
        (long)SEQ*DIM, HD, (long)SEQ*2*DIM, HD, (long)NHEAD*SS, SS, NHEAD, scale);

    // 10. softmax
    softmax_rows<<<NB*NHEAD*SEQ, 256>>>(scores);

    // 11. a = P @ Vc
    gemm64<false, EPI_NONE><<<dim3(HD/64, SEQ/64, NB*NHEAD), 256>>>(
        scores, kv + DIM, nullptr, abuf, SEQ, SEQ, 2*DIM, DIM,
        (long)NHEAD*SS, SS, (long)SEQ*2*DIM, HD, (long)SEQ*DIM, HD, NHEAD, 0.f);

    // 12. t = a @ cross_proj_w + b
    gemm64<false, EPI_BIAS><<<dim3(DIM/64, M/64, 1), 256>>>(
        abuf, cross_proj_w, cross_proj_b, t, DIM, DIM, DIM, DIM,
        0,0, 0,0, 0,0, 1, 0.f);

    // 13. x2 = LN(x1 + t)
    add_ln<<<M, 256>>>(x1, t, ln2_g, ln2_b, x2);

    // 14. h = gelu(x2 @ fc_w + b)
    gemm64<false, EPI_BIAS_GELU><<<dim3(4*DIM/64, M/64, 1), 256>>>(
        x2, fc_w, fc_b, h, DIM, DIM, 4*DIM, 4*DIM, 0,0, 0,0, 0,0, 1, 0.f);

    // 15. t = h @ mlp_proj_w + b
    gemm64<false, EPI_BIAS><<<dim3(DIM/64, M/64, 1), 256>>>(
        h, mlp_proj_w, mlp_proj_b, t, 4*DIM, 4*DIM, DIM, DIM,
        0,0, 0,0, 0,0, 1, 0.f);

    // 16. out = LN(x2 + t)
    add_ln<<<M, 256>>>(x2, t, ln3_g, ln3_b, out);
}

// round 6
// speedup vs baseline: 2.7142x; 2.7142x over previous
#include <cuda_runtime.h>
#include <math.h>
#include <stdint.h>

#define SEQ 1024
#define DIM 1024
#define NB  4
#define NHEAD 16
#define HD  64
#define NEGV (-10000.0f)

enum { EPI_NONE=0, EPI_BIAS=1, EPI_BIAS_GELU=2, EPI_SCALE=3 };

// ---------------- scratch (no allocations allowed) ----------------
__device__ float g_qkv[(size_t)NB*SEQ*3*DIM];
__device__ float g_scores[(size_t)NB*NHEAD*SEQ*SEQ];
__device__ float g_a [(size_t)NB*SEQ*DIM];
__device__ float g_x1[(size_t)NB*SEQ*DIM];
__device__ float g_q [(size_t)NB*SEQ*DIM];
__device__ float g_kv[(size_t)NB*SEQ*2*DIM];
__device__ float g_h [(size_t)NB*SEQ*4*DIM];
__device__ float g_x2[(size_t)NB*SEQ*DIM];
__device__ float g_t [(size_t)NB*SEQ*DIM];
__device__ float g_vt[(size_t)NB*NHEAD*HD*SEQ];
__device__ float g_wt[(size_t)16*1024*1024];   // 64MB transposed weights

__device__ __forceinline__ float gelu_tanh(float v){
    float u = 0.7978845608028654f * (v + 0.044715f * v * v * v);
    return 0.5f * v * (1.0f + tanhf(u));
}

#define CP_ASYNC16(s, g)  asm volatile("cp.async.cg.shared.global [%0], [%1], 16;" :: "r"(s), "l"(__cvta_generic_to_global(g)))
#define CP_COMMIT()       asm volatile("cp.async.commit_group;")
#define CP_WAIT(n)        asm volatile("cp.async.wait_group %0;" :: "n"(n))

__device__ __forceinline__ uint32_t smem_u32(const void* p) {
    uint32_t a;
    asm("{ .reg .u64 t; cvta.to.shared.u64 t, %1; cvt.u32.u64 %0, t; }" : "=r"(a) : "l"(p));
    return a;
}

__device__ __forceinline__ void mma_tf32(float* d, const uint32_t* a, const uint32_t* b) {
    asm volatile(
        "mma.sync.aligned.m16n8k8.row.col.f32.tf32.tf32.f32 "
        "{%0,%1,%2,%3}, {%4,%5,%6,%7}, {%8,%9}, {%0,%1,%2,%3};"
        : "+f"(d[0]), "+f"(d[1]), "+f"(d[2]), "+f"(d[3])
        : "r"(a[0]), "r"(a[1]), "r"(a[2]), "r"(a[3]), "r"(b[0]), "r"(b[1]));
}

// ---------------- tf32 mma.sync GEMM ----------------
// C[M,N] = epi( A[M,K] * B^T )   A: [M,K] K-major, B: [N,K] K-major.
// CTA tile 128 x BN, K-step 16, 2-stage cp.async double buffer.
// 8 warps: 2 (m) x 4 (n); warp tile 64 x (BN/4).
template<int BN, int EPI>
__global__ void __launch_bounds__(256) gemm_mma(
    const float* __restrict__ A, const float* __restrict__ B,
    const float* __restrict__ bias, float* __restrict__ C,
    int K, int lda, int ldb, int ldc,
    long sA1, long sA2, long sB1, long sB2, long sC1, long sC2,
    int nh, float scale, int causal)
{
    constexpr int BM = 128, BK = 16;
    constexpr int WN = BN / 4;            // warp n-extent
    constexpr int NT = WN / 8;            // n-tiles per warp
    constexpr int SA = BM * 20;           // smem floats per A stage (stride 20)
    constexpr int SB = BN * 20;
    constexpr int STG = SA + SB;

    extern __shared__ float smem[];

    const int tid = threadIdx.x;
    const int bz = blockIdx.z, bb = bz / nh, hh = bz - bb*nh;
    A += bb*sA1 + hh*sA2;  B += bb*sB1 + hh*sB2;  C += bb*sC1 + hh*sC2;
    const int row0 = blockIdx.y * BM;
    const int col0 = blockIdx.x * BN;

    // fully-masked causal tile: fill NEGV and exit
    if (EPI == EPI_SCALE && causal && col0 > row0 + BM - 1) {
        float4 nv = make_float4(NEGV, NEGV, NEGV, NEGV);
        #pragma unroll
        for (int it = 0; it < (BM*BN)/(4*256); it++) {
            int lin = tid + it*256;
            int r = lin / (BN/4), j = lin % (BN/4);
            *(float4*)&C[(long)(row0+r)*ldc + col0 + j*4] = nv;
        }
        return;
    }

    const int wid = tid >> 5, lane = tid & 31;
    const int g = lane >> 2, tg = lane & 3;
    const int wm = (wid & 1) * 64;
    const int wn = (wid >> 1) * WN;

    const uint32_t sbase = smem_u32(smem);

    float acc[4][NT][4];
    #pragma unroll
    for (int mt = 0; mt < 4; mt++)
        #pragma unroll
        for (int nt = 0; nt < NT; nt++)
            #pragma unroll
            for (int i = 0; i < 4; i++) acc[mt][nt][i] = 0.f;

    auto load_stage = [&](int step) {
        int st = step & 1;
        long k0 = (long)step * BK;
        uint32_t as = sbase + st*STG*4;
        uint32_t bs = as + SA*4;
        #pragma unroll
        for (int i = 0; i < BM/64; i++) {       // A: BM*BK/4 / 256 = 2 chunks
            int c = tid + i*256;
            int r = c >> 2, kc = c & 3;
            CP_ASYNC16(as + (uint32_t)(r*20 + kc*4)*4,
                       A + (long)(row0 + r)*lda + k0 + kc*4);
        }
        #pragma unroll
        for (int i = 0; i < BN/64; i++) {       // B chunks
            int c = tid + i*256;
            int r = c >> 2, kc = c & 3;
            CP_ASYNC16(bs + (uint32_t)(r*20 + kc*4)*4,
                       B + (long)(col0 + r)*ldb + k0 + kc*4);
        }
        CP_COMMIT();
    };

    const int nsteps = K / BK;
    load_stage(0);
    if (nsteps > 1) load_stage(1);

    for (int i = 0; i < nsteps; i++) {
        if (i + 2 < nsteps) { CP_WAIT(1); } else { CP_WAIT(0); }
        __syncthreads();

        const float* As = smem + (i & 1)*STG;
        const float* Bs = As + SA;

        #pragma unroll
        for (int kk = 0; kk < 16; kk += 8) {
            uint32_t af[4][4], bf[NT][2];
            #pragma unroll
            for (int mt = 0; mt < 4; mt++) {
                int r = wm + mt*16 + g;
                af[mt][0] = __float_as_uint(As[r*20      + kk + tg    ]);
                af[mt][1] = __float_as_uint(As[(r+8)*20  + kk + tg    ]);
                af[mt][2] = __float_as_uint(As[r*20      + kk + tg + 4]);
                af[mt][3] = __float_as_uint(As[(r+8)*20  + kk + tg + 4]);
            }
            #pragma unroll
            for (int nt = 0; nt < NT; nt++) {
                int c = wn + nt*8 + g;
                bf[nt][0] = __float_as_uint(Bs[c*20 + kk + tg    ]);
                bf[nt][1] = __float_as_uint(Bs[c*20 + kk + tg + 4]);
            }
            #pragma unroll
            for (int mt = 0; mt < 4; mt++)
                #pragma unroll
                for (int nt = 0; nt < NT; nt++)
                    mma_tf32(acc[mt][nt], af[mt], bf[nt]);
        }
        __syncthreads();
        if (i + 2 < nsteps) load_stage(i + 2);
    }

    // ---- epilogue: direct float2 stores ----
    #pragma unroll
    for (int mt = 0; mt < 4; mt++) {
        #pragma unroll
        for (int nt = 0; nt < NT; nt++) {
            int Rg = row0 + wm + mt*16 + g;
            int cg = col0 + wn + nt*8 + 2*tg;
            #pragma unroll
            for (int half = 0; half < 2; half++) {
                int r = Rg + half*8;
                float v0 = acc[mt][nt][half*2 + 0];
                float v1 = acc[mt][nt][half*2 + 1];
                if (EPI == EPI_BIAS || EPI == EPI_BIAS_GELU) {
                    v0 += bias[cg];  v1 += bias[cg+1];
                    if (EPI == EPI_BIAS_GELU) { v0 = gelu_tanh(v0); v1 = gelu_tanh(v1); }
                }
                if (EPI == EPI_SCALE) {
                    v0 *= scale; v1 *= scale;
                    if (causal) {
                        if (cg     > r) v0 = NEGV;
                        if (cg + 1 > r) v1 = NEGV;
                    }
                }
                float2 o = make_float2(v0, v1);
                *(float2*)&C[(long)r*ldc + cg] = o;
            }
        }
    }
}

// ---------------- batched 32x32 tiled transpose ----------------
__global__ void transpose_b(const float* __restrict__ in, float* __restrict__ out,
                            int ldin, int ldout, long i1, long i2, long o1, long o2, int nh)
{
    __shared__ float t[32][33];
    int bz = blockIdx.z, bb = bz / nh, hh = bz - bb*nh;
    in  += bb*i1 + hh*i2;
    out += bb*o1 + hh*o2;
    int r0 = blockIdx.y*32, c0 = blockIdx.x*32;
    int x = threadIdx.x, y = threadIdx.y;
    #pragma unroll
    for (int i = 0; i < 32; i += 8) t[y+i][x] = in[(long)(r0+y+i)*ldin + c0 + x];
    __syncthreads();
    #pragma unroll
    for (int i = 0; i < 32; i += 8) out[(long)(c0+y+i)*ldout + r0 + x] = t[x][y+i];
}

// ---------------- row softmax (in-place), row length 1024 ----------------
__global__ void __launch_bounds__(256) softmax_rows(float* __restrict__ s)
{
    __shared__ float red[8];
    __shared__ float bc;
    long row = blockIdx.x;
    float* p = s + row * SEQ;
    int tid = threadIdx.x, lane = tid & 31, wid = tid >> 5;

    float v[4], m = -3.4e38f;
    #pragma unroll
    for (int i = 0; i < 4; i++) { v[i] = p[tid + i*256]; m = fmaxf(m, v[i]); }
    #pragma unroll
    for (int o = 16; o > 0; o >>= 1) m = fmaxf(m, __shfl_xor_sync(0xffffffffu, m, o));
    if (lane == 0) red[wid] = m;
    __syncthreads();
    if (tid == 0) {
        float t = red[0];
        #pragma unroll
        for (int i = 1; i < 8; i++) t = fmaxf(t, red[i]);
        bc = t;
    }
    __syncthreads();
    m = bc;

    float sum = 0.f;
    #pragma unroll
    for (int i = 0; i < 4; i++) { v[i] = __expf(v[i] - m); sum += v[i]; }
    #pragma unroll
    for (int o = 16; o > 0; o >>= 1) sum += __shfl_xor_sync(0xffffffffu, sum, o);
    __syncthreads();
    if (lane == 0) red[wid] = sum;
    __syncthreads();
    if (tid == 0) {
        float t = 0.f;
        #pragma unroll
        for (int i = 0; i < 8; i++) t += red[i];
        bc = 1.0f / t;
    }
    __syncthreads();
    float inv = bc;
    #pragma unroll
    for (int i = 0; i < 4; i++) p[tid + i*256] = v[i] * inv;
}

// ---------------- fused residual add + LayerNorm ----------------
__global__ void __launch_bounds__(256) add_ln(
    const float* __restrict__ x, const float* __restrict__ a,
    const float* __restrict__ g, const float* __restrict__ b,
    float* __restrict__ y)
{
    __shared__ float red[8];
    __shared__ float bc;
    long row = blockIdx.x;
    const float* xr = x + row * DIM;
    const float* ar = a + row * DIM;
    float* yr = y + row * DIM;
    int tid = threadIdx.x, lane = tid & 31, wid = tid >> 5;

    float v[4], s = 0.f;
    #pragma unroll
    for (int i = 0; i < 4; i++) { int c = tid + i*256; v[i] = xr[c] + ar[c]; s += v[i]; }
    #pragma unroll
    for (int o = 16; o > 0; o >>= 1) s += __shfl_xor_sync(0xffffffffu, s, o);
    if (lane == 0) red[wid] = s;
    __syncthreads();
    if (tid == 0) {
        float t = 0.f;
        #pragma unroll
        for (int i = 0; i < 8; i++) t += red[i];
        bc = t * (1.0f / DIM);
    }
    __syncthreads();
    float mu = bc;

    float q = 0.f;
    #pragma unroll
    for (int i = 0; i < 4; i++) { float d = v[i] - mu; q += d * d; }
    #pragma unroll
    for (int o = 16; o > 0; o >>= 1) q += __shfl_xor_sync(0xffffffffu, q, o);
    __syncthreads();
    if (lane == 0) red[wid] = q;
    __syncthreads();
    if (tid == 0) {
        float t = 0.f;
        #pragma unroll
        for (int i = 0; i < 8; i++) t += red[i];
        bc = rsqrtf(t * (1.0f / DIM) + 1e-5f);
    }
    __syncthreads();
    float inv = bc;
    #pragma unroll
    for (int i = 0; i < 4; i++) {
        int c = tid + i*256;
        yr[c] = (v[i] - mu) * inv * g[c] + b[c];
    }
}

// ---------------- host orchestration ----------------
extern "C" void kernel_launch(void* const* d_in, const int* in_sizes, int n_in,
                              void* d_out, int out_size)
{
    const float* x            = (const float*)d_in[0];
    const float* ctx          = (const float*)d_in[1];
    const float* c_attn_w     = (const float*)d_in[2];
    const float* c_attn_b     = (const float*)d_in[3];
    const float* self_proj_w  = (const float*)d_in[4];
    const float* self_proj_b  = (const float*)d_in[5];
    const float* q_w          = (const float*)d_in[6];
    const float* q_b          = (const float*)d_in[7];
    const float* kv_w         = (const float*)d_in[8];
    const float* kv_b         = (const float*)d_in[9];
    const float* cross_proj_w = (const float*)d_in[10];
    const float* cross_proj_b = (const float*)d_in[11];
    const float* fc_w         = (const float*)d_in[12];
    const float* fc_b         = (const float*)d_in[13];
    const float* mlp_proj_w   = (const float*)d_in[14];
    const float* mlp_proj_b   = (const float*)d_in[15];
    const float* ln1_g        = (const float*)d_in[16];
    const float* ln1_b        = (const float*)d_in[17];
    const float* ln2_g        = (const float*)d_in[18];
    const float* ln2_b        = (const float*)d_in[19];
    const float* ln3_g        = (const float*)d_in[20];
    const float* ln3_b        = (const float*)d_in[21];
    float* out = (float*)d_out;

    float *qkv, *scores, *abuf, *x1, *q, *kv, *h, *x2, *t, *vt, *wtb;
    cudaGetSymbolAddress((void**)&qkv,    g_qkv);
    cudaGetSymbolAddress((void**)&scores, g_scores);
    cudaGetSymbolAddress((void**)&abuf,   g_a);
    cudaGetSymbolAddress((void**)&x1,     g_x1);
    cudaGetSymbolAddress((void**)&q,      g_q);
    cudaGetSymbolAddress((void**)&kv,     g_kv);
    cudaGetSymbolAddress((void**)&h,      g_h);
    cudaGetSymbolAddress((void**)&x2,     g_x2);
    cudaGetSymbolAddress((void**)&t,      g_t);
    cudaGetSymbolAddress((void**)&vt,     g_vt);
    cudaGetSymbolAddress((void**)&wtb,    g_wt);

    float* cattnT = wtb;                       // [3072,1024]
    float* selfT  = wtb +  3l*1024*1024;       // [1024,1024]
    float* qT     = wtb +  4l*1024*1024;       // [1024,1024]
    float* kvT    = wtb +  5l*1024*1024;       // [2048,1024]
    float* crossT = wtb +  7l*1024*1024;       // [1024,1024]
    float* fcT    = wtb +  8l*1024*1024;       // [4096,1024]
    float* mlpT   = wtb + 12l*1024*1024;       // [1024,4096]

    const int SM128 = (128*20 + 128*20) * 2 * 4;   // 40960 B
    const int SM64  = (128*20 +  64*20) * 2 * 4;   // 30720 B

    const int M = NB * SEQ;                  // 4096
    const long SS = (long)SEQ * SEQ;
    const float scale = 0.125f;              // 1/sqrt(64)
    dim3 tb(32, 8);

    // ---- weight transposes (W[K,N] -> WT[N,K]) ----
    transpose_b<<<dim3( 96, 32, 1), tb>>>(c_attn_w,     cattnT, 3*DIM, DIM,   0,0,0,0, 1);
    transpose_b<<<dim3( 32, 32, 1), tb>>>(self_proj_w,  selfT,  DIM,   DIM,   0,0,0,0, 1);
    transpose_b<<<dim3( 32, 32, 1), tb>>>(q_w,          qT,     DIM,   DIM,   0,0,0,0, 1);
    transpose_b<<<dim3( 64, 32, 1), tb>>>(kv_w,         kvT,    2*DIM, DIM,   0,0,0,0, 1);
    transpose_b<<<dim3( 32, 32, 1), tb>>>(cross_proj_w, crossT, DIM,   DIM,   0,0,0,0, 1);
    transpose_b<<<dim3(128, 32, 1), tb>>>(fc_w,         fcT,    4*DIM, DIM,   0,0,0,0, 1);
    transpose_b<<<dim3( 32,128, 1), tb>>>(mlp_proj_w,   mlpT,   DIM,   4*DIM, 0,0,0,0, 1);

    // 1. qkv = x @ c_attn_w + b
    gemm_mma<128, EPI_BIAS><<<dim3(24, 32, 1), 256, SM128>>>(
        x, cattnT, c_attn_b, qkv, DIM, DIM, DIM, 3*DIM,
        0,0, 0,0, 0,0, 1, 0.f, 0);

    // self V transpose: vt[(b,h)][hd][S]
    transpose_b<<<dim3(2, 32, NB*NHEAD), tb>>>(qkv + 2*DIM, vt, 3*DIM, SEQ,
        (long)SEQ*3*DIM, HD, (long)NHEAD*HD*SEQ, (long)HD*SEQ, NHEAD);

    // 2. self scores = Q K^T * scale (causal)
    gemm_mma<128, EPI_SCALE><<<dim3(8, 8, NB*NHEAD), 256, SM128>>>(
        qkv, qkv + DIM, nullptr, scores, HD, 3*DIM, 3*DIM, SEQ,
        (long)SEQ*3*DIM, HD, (long)SEQ*3*DIM, HD, (long)NHEAD*SS, SS, NHEAD, scale, 1);

    // 3. softmax
    softmax_rows<<<NB*NHEAD*SEQ, 256>>>(scores);

    // 4. a = P @ V  (B = V^T, K-major)
    gemm_mma<64, EPI_NONE><<<dim3(1, 8, NB*NHEAD), 256, SM64>>>(
        scores, vt, nullptr, abuf, SEQ, SEQ, SEQ, DIM,
        (long)NHEAD*SS, SS, (long)NHEAD*HD*SEQ, (long)HD*SEQ, (long)SEQ*DIM, HD, NHEAD, 0.f, 0);

    // 5. t = a @ self_proj_w + b
    gemm_mma<128, EPI_BIAS><<<dim3(8, 32, 1), 256, SM128>>>(
        abuf, selfT, self_proj_b, t, DIM, DIM, DIM, DIM, 0,0, 0,0, 0,0, 1, 0.f, 0);

    // 6. x1 = LN(x + t)
    add_ln<<<M, 256>>>(x, t, ln1_g, ln1_b, x1);

    // 7. q = x1 @ q_w + b
    gemm_mma<128, EPI_BIAS><<<dim3(8, 32, 1), 256, SM128>>>(
        x1, qT, q_b, q, DIM, DIM, DIM, DIM, 0,0, 0,0, 0,0, 1, 0.f, 0);

    // 8. kv = ctx @ kv_w + b
    gemm_mma<128, EPI_BIAS><<<dim3(16, 32, 1), 256, SM128>>>(
        ctx, kvT, kv_b, kv, DIM, DIM, DIM, 2*DIM, 0,0, 0,0, 0,0, 1, 0.f, 0);

    // cross V transpose
    transpose_b<<<dim3(2, 32, NB*NHEAD), tb>>>(kv + DIM, vt, 2*DIM, SEQ,
        (long)SEQ*2*DIM, HD, (long)NHEAD*HD*SEQ, (long)HD*SEQ, NHEAD);

    // 9. cross scores
    gemm_mma<128, EPI_SCALE><<<dim3(8, 8, NB*NHEAD), 256, SM128>>>(
        q, kv, nullptr, scores, HD, DIM, 2*DIM, SEQ,
        (long)SEQ*DIM, HD, (long)SEQ*2*DIM, HD, (long)NHEAD*SS, SS, NHEAD, scale, 0);

    // 10. softmax
    softmax_rows<<<NB*NHEAD*SEQ, 256>>>(scores);

    // 11. a = P @ Vc
    gemm_mma<64, EPI_NONE><<<dim3(1, 8, NB*NHEAD), 256, SM64>>>(
        scores, vt, nullptr, abuf, SEQ, SEQ, SEQ, DIM,
        (long)NHEAD*SS, SS, (long)NHEAD*HD*SEQ, (long)HD*SEQ, (long)SEQ*DIM, HD, NHEAD, 0.f, 0);

    // 12. t = a @ cross_proj_w + b
    gemm_mma<128, EPI_BIAS><<<dim3(8, 32, 1), 256, SM128>>>(
        abuf, crossT, cross_proj_b, t, DIM, DIM, DIM, DIM, 0,0, 0,0, 0,0, 1, 0.f, 0);

    // 13. x2 = LN(x1 + t)
    add_ln<<<M, 256>>>(x1, t, ln2_g, ln2_b, x2);

    // 14. h = gelu(x2 @ fc_w + b)
    gemm_mma<128, EPI_BIAS_GELU><<<dim3(32, 32, 1), 256, SM128>>>(
        x2, fcT, fc_b, h, DIM, DIM, DIM, 4*DIM, 0,0, 0,0, 0,0, 1, 0.f, 0);

    // 15. t = h @ mlp_proj_w + b
    gemm_mma<128, EPI_BIAS><<<dim3(8, 32, 1), 256, SM128>>>(
        h, mlpT, mlp_proj_b, t, 4*DIM, 4*DIM, 4*DIM, DIM, 0,0, 0,0, 0,0, 1, 0.f, 0);

    // 16. out = LN(x2 + t)
    add_ln<<<M, 256>>>(x2, t, ln3_g, ln3_b, out);
}

// round 7
// speedup vs baseline: 3.3674x; 1.2406x over previous
#include <cuda_runtime.h>
#include <math.h>
#include <stdint.h>

#define SEQ 1024
#define DIM 1024
#define NB  4
#define NHEAD 16
#define HD  64
#define NEGV (-10000.0f)

enum { EPI_NONE=0, EPI_BIAS=1, EPI_BIAS_GELU=2, EPI_SCALE=3 };

// ---------------- scratch (no allocations allowed) ----------------
__device__ float g_qkv[(size_t)NB*SEQ*3*DIM];
__device__ float g_a [(size_t)NB*SEQ*DIM];
__device__ float g_x1[(size_t)NB*SEQ*DIM];
__device__ float g_q [(size_t)NB*SEQ*DIM];
__device__ float g_kv[(size_t)NB*SEQ*2*DIM];
__device__ float g_h [(size_t)NB*SEQ*4*DIM];
__device__ float g_x2[(size_t)NB*SEQ*DIM];
__device__ float g_t [(size_t)NB*SEQ*DIM];
__device__ float g_wt[(size_t)16*1024*1024];   // 64MB transposed weights

__device__ __forceinline__ float gelu_tanh(float v){
    float u = 0.7978845608028654f * (v + 0.044715f * v * v * v);
    return 0.5f * v * (1.0f + tanhf(u));
}

#define CP_ASYNC16(s, g)  asm volatile("cp.async.cg.shared.global [%0], [%1], 16;" :: "r"(s), "l"(__cvta_generic_to_global(g)))
#define CP_COMMIT()       asm volatile("cp.async.commit_group;")
#define CP_WAIT(n)        asm volatile("cp.async.wait_group %0;" :: "n"(n))

__device__ __forceinline__ uint32_t smem_u32(const void* p) {
    uint32_t a;
    asm("{ .reg .u64 t; cvta.to.shared.u64 t, %1; cvt.u32.u64 %0, t; }" : "=r"(a) : "l"(p));
    return a;
}
__device__ __forceinline__ uint32_t f2tf(float f) {
    uint32_t r;
    asm("cvt.rna.tf32.f32 %0, %1;" : "=r"(r) : "f"(f));
    return r;
}
__device__ __forceinline__ void mma_tf32(float* d, const uint32_t* a, const uint32_t* b) {
    asm volatile(
        "mma.sync.aligned.m16n8k8.row.col.f32.tf32.tf32.f32 "
        "{%0,%1,%2,%3}, {%4,%5,%6,%7}, {%8,%9}, {%0,%1,%2,%3};"
        : "+f"(d[0]), "+f"(d[1]), "+f"(d[2]), "+f"(d[3])
        : "r"(a[0]), "r"(a[1]), "r"(a[2]), "r"(a[3]), "r"(b[0]), "r"(b[1]));
}

// ---------------- tf32 mma.sync GEMM ----------------
// C[M,N] = epi( A[M,K] * B^T )   A: [M,K] K-major, B: [N,K] K-major.
template<int BN, int EPI>
__global__ void __launch_bounds__(256) gemm_mma(
    const float* __restrict__ A, const float* __restrict__ B,
    const float* __restrict__ bias, float* __restrict__ C,
    int K, int lda, int ldb, int ldc,
    long sA1, long sB1, long sC1,
    float scale)
{
    constexpr int BM = 128, BK = 16;
    constexpr int WN = BN / 4;
    constexpr int NT = WN / 8;
    constexpr int SA = BM * 20;
    constexpr int SB = BN * 20;
    constexpr int STG = SA + SB;

    extern __shared__ float smem[];

    const int tid = threadIdx.x;
    const int bz = blockIdx.z;
    A += bz*sA1;  B += bz*sB1;  C += bz*sC1;
    const int row0 = blockIdx.y * BM;
    const int col0 = blockIdx.x * BN;

    const int wid = tid >> 5, lane = tid & 31;
    const int g = lane >> 2, tg = lane & 3;
    const int wm = (wid & 1) * 64;
    const int wn = (wid >> 1) * WN;

    const uint32_t sbase = smem_u32(smem);

    float acc[4][NT][4];
    #pragma unroll
    for (int mt = 0; mt < 4; mt++)
        #pragma unroll
        for (int nt = 0; nt < NT; nt++)
            #pragma unroll
            for (int i = 0; i < 4; i++) acc[mt][nt][i] = 0.f;

    auto load_stage = [&](int step) {
        int st = step & 1;
        long k0 = (long)step * BK;
        uint32_t as = sbase + st*STG*4;
        uint32_t bs = as + SA*4;
        #pragma unroll
        for (int i = 0; i < BM/64; i++) {
            int c = tid + i*256;
            int r = c >> 2, kc = c & 3;
            CP_ASYNC16(as + (uint32_t)(r*20 + kc*4)*4,
                       A + (long)(row0 + r)*lda + k0 + kc*4);
        }
        #pragma unroll
        for (int i = 0; i < BN/64; i++) {
            int c = tid + i*256;
            int r = c >> 2, kc = c & 3;
            CP_ASYNC16(bs + (uint32_t)(r*20 + kc*4)*4,
                       B + (long)(col0 + r)*ldb + k0 + kc*4);
        }
        CP_COMMIT();
    };

    const int nsteps = K / BK;
    load_stage(0);
    if (nsteps > 1) load_stage(1);

    for (int i = 0; i < nsteps; i++) {
        if (i + 2 < nsteps) { CP_WAIT(1); } else { CP_WAIT(0); }
        __syncthreads();

        const float* As = smem + (i & 1)*STG;
        const float* Bs = As + SA;

        #pragma unroll
        for (int kk = 0; kk < 16; kk += 8) {
            uint32_t af[4][4], bf[NT][2];
            #pragma unroll
            for (int mt = 0; mt < 4; mt++) {
                int r = wm + mt*16 + g;
                af[mt][0] = f2tf(As[r*20      + kk + tg    ]);
                af[mt][1] = f2tf(As[(r+8)*20  + kk + tg    ]);
                af[mt][2] = f2tf(As[r*20      + kk + tg + 4]);
                af[mt][3] = f2tf(As[(r+8)*20  + kk + tg + 4]);
            }
            #pragma unroll
            for (int nt = 0; nt < NT; nt++) {
                int c = wn + nt*8 + g;
                bf[nt][0] = f2tf(Bs[c*20 + kk + tg    ]);
                bf[nt][1] = f2tf(Bs[c*20 + kk + tg + 4]);
            }
            #pragma unroll
            for (int mt = 0; mt < 4; mt++)
                #pragma unroll
                for (int nt = 0; nt < NT; nt++)
                    mma_tf32(acc[mt][nt], af[mt], bf[nt]);
        }
        __syncthreads();
        if (i + 2 < nsteps) load_stage(i + 2);
    }

    #pragma unroll
    for (int mt = 0; mt < 4; mt++) {
        #pragma unroll
        for (int nt = 0; nt < NT; nt++) {
            int Rg = row0 + wm + mt*16 + g;
            int cg = col0 + wn + nt*8 + 2*tg;
            #pragma unroll
            for (int half = 0; half < 2; half++) {
                int r = Rg + half*8;
                float v0 = acc[mt][nt][half*2 + 0];
                float v1 = acc[mt][nt][half*2 + 1];
                if (EPI == EPI_BIAS || EPI == EPI_BIAS_GELU) {
                    v0 += bias[cg];  v1 += bias[cg+1];
                    if (EPI == EPI_BIAS_GELU) { v0 = gelu_tanh(v0); v1 = gelu_tanh(v1); }
                }
                float2 o = make_float2(v0, v1);
                *(float2*)&C[(long)r*ldc + cg] = o;
            }
        }
    }
}

// ---------------- fused flash attention (tf32 mma) ----------------
// Q[128 rows/CTA] x K,V tiles of 64 keys. 8 warps x 16 rows.
// Q: [.,ldq] row-major hd-contig slice; K,V: [.,ldkv]; O: [.,DIM].
__global__ void __launch_bounds__(256, 1) flash_attn(
    const float* __restrict__ Q, const float* __restrict__ K,
    const float* __restrict__ V, float* __restrict__ O,
    int ldq, int ldkv, int causal)
{
    constexpr int KST = 68, VST = 72;
    constexpr int STGF = 64*KST + 64*VST;   // floats per stage
    extern __shared__ float sm[];

    const int tid = threadIdx.x;
    const int wid = tid >> 5, lane = tid & 31;
    const int g = lane >> 2, tg = lane & 3;
    const int qt = blockIdx.x;
    const int bh = blockIdx.y, bb = bh >> 4, hh = bh & 15;
    const int wm = wid * 16;

    const float* Qb = Q + (long)bb*SEQ*ldq  + hh*64 + (long)qt*128*ldq;
    const float* Kb = K + (long)bb*SEQ*ldkv + hh*64;
    const float* Vb = V + (long)bb*SEQ*ldkv + hh*64;
    float*       Ob = O + (long)bb*SEQ*DIM  + hh*64 + (long)qt*128*DIM;

    const uint32_t sbase = smem_u32(sm);

    // ---- stage Q, build scaled tf32 A-fragments ----
    #pragma unroll
    for (int i = 0; i < 8; i++) {
        int c = tid + i*256;
        int r = c >> 4, kc = c & 15;
        CP_ASYNC16(sbase + (uint32_t)(r*KST + kc*4)*4, Qb + (long)r*ldq + kc*4);
    }
    CP_COMMIT(); CP_WAIT(0);
    __syncthreads();

    uint32_t aq[8][4];
    #pragma unroll
    for (int kt = 0; kt < 8; kt++) {
        int k0 = kt*8;
        aq[kt][0] = f2tf(sm[(wm+g  )*KST + k0+tg  ] * 0.125f);
        aq[kt][1] = f2tf(sm[(wm+g+8)*KST + k0+tg  ] * 0.125f);
        aq[kt][2] = f2tf(sm[(wm+g  )*KST + k0+tg+4] * 0.125f);
        aq[kt][3] = f2tf(sm[(wm+g+8)*KST + k0+tg+4] * 0.125f);
    }
    __syncthreads();

    float acc_o[8][4];
    #pragma unroll
    for (int nt = 0; nt < 8; nt++)
        #pragma unroll
        for (int i = 0; i < 4; i++) acc_o[nt][i] = 0.f;
    float m0 = -1e30f, m1 = -1e30f, l0 = 0.f, l1 = 0.f;

    const int ntiles = causal ? (2*qt + 2) : (SEQ/64);
    const int rowg0 = qt*128 + wm + g;
    const int rowg1 = rowg0 + 8;

    auto load_kv = [&](int j) {
        uint32_t st = sbase + (uint32_t)((j & 1) * STGF) * 4u;
        const float* Kg = Kb + (long)j*64*ldkv;
        const float* Vg = Vb + (long)j*64*ldkv;
        #pragma unroll
        for (int i = 0; i < 4; i++) {
            int c = tid + i*256;
            int r = c >> 4, kc = c & 15;
            CP_ASYNC16(st + (uint32_t)(r*KST + kc*4)*4, Kg + (long)r*ldkv + kc*4);
        }
        uint32_t vs = st + 64u*KST*4u;
        #pragma unroll
        for (int i = 0; i < 4; i++) {
            int c = tid + i*256;
            int r = c >> 4, kc = c & 15;
            CP_ASYNC16(vs + (uint32_t)(r*VST + kc*4)*4, Vg + (long)r*ldkv + kc*4);
        }
        CP_COMMIT();
    };

    load_kv(0);
    if (ntiles > 1) load_kv(1);

    for (int j = 0; j < ntiles; j++) {
        if (j + 1 < ntiles) { CP_WAIT(1); } else { CP_WAIT(0); }
        __syncthreads();
        const float* Ks = sm + (j & 1)*STGF;
        const float* Vs = Ks + 64*KST;

        // ---- S = (Q*scale) K^T ----
        float s[8][4];
        #pragma unroll
        for (int nt = 0; nt < 8; nt++)
            #pragma unroll
            for (int i = 0; i < 4; i++) s[nt][i] = 0.f;

        #pragma unroll
        for (int kt = 0; kt < 8; kt++) {
            uint32_t bf[8][2];
            #pragma unroll
            for (int nt = 0; nt < 8; nt++) {
                int c = nt*8 + g;
                bf[nt][0] = f2tf(Ks[c*KST + kt*8 + tg    ]);
                bf[nt][1] = f2tf(Ks[c*KST + kt*8 + tg + 4]);
            }
            #pragma unroll
            for (int nt = 0; nt < 8; nt++)
                mma_tf32(s[nt], aq[kt], bf[nt]);
        }

        // ---- causal mask (diagonal tiles only) ----
        if (causal && j >= 2*qt) {
            int kbase = j*64;
            #pragma unroll
            for (int nt = 0; nt < 8; nt++) {
                int kg = kbase + nt*8 + 2*tg;
                if (kg     > rowg0) s[nt][0] = -1e30f;
                if (kg + 1 > rowg0) s[nt][1] = -1e30f;
                if (kg     > rowg1) s[nt][2] = -1e30f;
                if (kg + 1 > rowg1) s[nt][3] = -1e30f;
            }
        }

        // ---- online softmax ----
        float tm0 = -1e30f, tm1 = -1e30f;
        #pragma unroll
        for (int nt = 0; nt < 8; nt++) {
            tm0 = fmaxf(tm0, fmaxf(s[nt][0], s[nt][1]));
            tm1 = fmaxf(tm1, fmaxf(s[nt][2], s[nt][3]));
        }
        tm0 = fmaxf(tm0, __shfl_xor_sync(0xffffffffu, tm0, 1));
        tm0 = fmaxf(tm0, __shfl_xor_sync(0xffffffffu, tm0, 2));
        tm1 = fmaxf(tm1, __shfl_xor_sync(0xffffffffu, tm1, 1));
        tm1 = fmaxf(tm1, __shfl_xor_sync(0xffffffffu, tm1, 2));

        float mn0 = fmaxf(m0, tm0), mn1 = fmaxf(m1, tm1);
        float al0 = __expf(m0 - mn0), al1 = __expf(m1 - mn1);
        float ts0 = 0.f, ts1 = 0.f;
        #pragma unroll
        for (int nt = 0; nt < 8; nt++) {
            s[nt][0] = __expf(s[nt][0] - mn0);
            s[nt][1] = __expf(s[nt][1] - mn0);
            s[nt][2] = __expf(s[nt][2] - mn1);
            s[nt][3] = __expf(s[nt][3] - mn1);
            ts0 += s[nt][0] + s[nt][1];
            ts1 += s[nt][2] + s[nt][3];
        }
        ts0 += __shfl_xor_sync(0xffffffffu, ts0, 1);
        ts0 += __shfl_xor_sync(0xffffffffu, ts0, 2);
        ts1 += __shfl_xor_sync(0xffffffffu, ts1, 1);
        ts1 += __shfl_xor_sync(0xffffffffu, ts1, 2);

        l0 = l0*al0 + ts0;  l1 = l1*al1 + ts1;
        m0 = mn0;  m1 = mn1;

        #pragma unroll
        for (int nt = 0; nt < 8; nt++) {
            acc_o[nt][0] *= al0;  acc_o[nt][1] *= al0;
            acc_o[nt][2] *= al1;  acc_o[nt][3] *= al1;
        }

        // ---- O += P V  (rearrange P C-frags -> A-frags via shuffles) ----
        const int src1 = 4*g + (tg >> 1);
        const int src2 = src1 + 2;
        const bool odd = tg & 1;
        #pragma unroll
        for (int kt = 0; kt < 8; kt++) {
            float x0 = __shfl_sync(0xffffffffu, s[kt][0], src1);
            float x1 = __shfl_sync(0xffffffffu, s[kt][1], src1);
            float x2 = __shfl_sync(0xffffffffu, s[kt][2], src1);
            float x3 = __shfl_sync(0xffffffffu, s[kt][3], src1);
            float y0 = __shfl_sync(0xffffffffu, s[kt][0], src2);
            float y1 = __shfl_sync(0xffffffffu, s[kt][1], src2);
            float y2 = __shfl_sync(0xffffffffu, s[kt][2], src2);
            float y3 = __shfl_sync(0xffffffffu, s[kt][3], src2);
            uint32_t ap[4];
            ap[0] = f2tf(odd ? x1 : x0);
            ap[1] = f2tf(odd ? x3 : x2);
            ap[2] = f2tf(odd ? y1 : y0);
            ap[3] = f2tf(odd ? y3 : y2);
            #pragma unroll
            for (int nt = 0; nt < 8; nt++) {
                int c = nt*8 + g;
                uint32_t bv[2];
                bv[0] = f2tf(Vs[(kt*8 + tg    )*VST + c]);
                bv[1] = f2tf(Vs[(kt*8 + tg + 4)*VST + c]);
                mma_tf32(acc_o[nt], ap, bv);
            }
        }
        __syncthreads();
        if (j + 2 < ntiles) load_kv(j + 2);
    }

    // ---- normalize + store ----
    float r0 = 1.f / l0, r1 = 1.f / l1;
    #pragma unroll
    for (int nt = 0; nt < 8; nt++) {
        int c = nt*8 + 2*tg;
        float2 v0 = make_float2(acc_o[nt][0]*r0, acc_o[nt][1]*r0);
        float2 v1 = make_float2(acc_o[nt][2]*r1, acc_o[nt][3]*r1);
        *(float2*)&Ob[(long)(wm+g  )*DIM + c] = v0;
        *(float2*)&Ob[(long)(wm+g+8)*DIM + c] = v1;
    }
}

// ---------------- batched 32x32 tiled transpose ----------------
__global__ void transpose_b(const float* __restrict__ in, float* __restrict__ out,
                            int ldin, int ldout)
{
    __shared__ float t[32][33];
    int r0 = blockIdx.y*32, c0 = blockIdx.x*32;
    int x = threadIdx.x, y = threadIdx.y;
    #pragma unroll
    for (int i = 0; i < 32; i += 8) t[y+i][x] = in[(long)(r0+y+i)*ldin + c0 + x];
    __syncthreads();
    #pragma unroll
    for (int i = 0; i < 32; i += 8) out[(long)(c0+y+i)*ldout + r0 + x] = t[x][y+i];
}

// ---------------- fused residual add + LayerNorm ----------------
__global__ void __launch_bounds__(256) add_ln(
    const float* __restrict__ x, const float* __restrict__ a,
    const float* __restrict__ g, const float* __restrict__ b,
    float* __restrict__ y)
{
    __shared__ float red[8];
    __shared__ float bc;
    long row = blockIdx.x;
    const float* xr = x + row * DIM;
    const float* ar = a + row * DIM;
    float* yr = y + row * DIM;
    int tid = threadIdx.x, lane = tid & 31, wid = tid >> 5;

    float v[4], s = 0.f;
    #pragma unroll
    for (int i = 0; i < 4; i++) { int c = tid + i*256; v[i] = xr[c] + ar[c]; s += v[i]; }
    #pragma unroll
    for (int o = 16; o > 0; o >>= 1) s += __shfl_xor_sync(0xffffffffu, s, o);
    if (lane == 0) red[wid] = s;
    __syncthreads();
    if (tid == 0) {
        float t = 0.f;
        #pragma unroll
        for (int i = 0; i < 8; i++) t += red[i];
        bc = t * (1.0f / DIM);
    }
    __syncthreads();
    float mu = bc;

    float q = 0.f;
    #pragma unroll
    for (int i = 0; i < 4; i++) { float d = v[i] - mu; q += d * d; }
    #pragma unroll
    for (int o = 16; o > 0; o >>= 1) q += __shfl_xor_sync(0xffffffffu, q, o);
    __syncthreads();
    if (lane == 0) red[wid] = q;
    __syncthreads();
    if (tid == 0) {
        float t = 0.f;
        #pragma unroll
        for (int i = 0; i < 8; i++) t += red[i];
        bc = rsqrtf(t * (1.0f / DIM) + 1e-5f);
    }
    __syncthreads();
    float inv = bc;
    #pragma unroll
    for (int i = 0; i < 4; i++) {
        int c = tid + i*256;
        yr[c] = (v[i] - mu) * inv * g[c] + b[c];
    }
}

// ---------------- host orchestration ----------------
extern "C" void kernel_launch(void* const* d_in, const int* in_sizes, int n_in,
                              void* d_out, int out_size)
{
    const float* x            = (const float*)d_in[0];
    const float* ctx          = (const float*)d_in[1];
    const float* c_attn_w     = (const float*)d_in[2];
    const float* c_attn_b     = (const float*)d_in[3];
    const float* self_proj_w  = (const float*)d_in[4];
    const float* self_proj_b  = (const float*)d_in[5];
    const float* q_w          = (const float*)d_in[6];
    const float* q_b          = (const float*)d_in[7];
    const float* kv_w         = (const float*)d_in[8];
    const float* kv_b         = (const float*)d_in[9];
    const float* cross_proj_w = (const float*)d_in[10];
    const float* cross_proj_b = (const float*)d_in[11];
    const float* fc_w         = (const float*)d_in[12];
    const float* fc_b         = (const float*)d_in[13];
    const float* mlp_proj_w   = (const float*)d_in[14];
    const float* mlp_proj_b   = (const float*)d_in[15];
    const float* ln1_g        = (const float*)d_in[16];
    const float* ln1_b        = (const float*)d_in[17];
    const float* ln2_g        = (const float*)d_in[18];
    const float* ln2_b        = (const float*)d_in[19];
    const float* ln3_g        = (const float*)d_in[20];
    const float* ln3_b        = (const float*)d_in[21];
    float* out = (float*)d_out;

    float *qkv, *abuf, *x1, *q, *kv, *h, *x2, *t, *wtb;
    cudaGetSymbolAddress((void**)&qkv,  g_qkv);
    cudaGetSymbolAddress((void**)&abuf, g_a);
    cudaGetSymbolAddress((void**)&x1,   g_x1);
    cudaGetSymbolAddress((void**)&q,    g_q);
    cudaGetSymbolAddress((void**)&kv,   g_kv);
    cudaGetSymbolAddress((void**)&h,    g_h);
    cudaGetSymbolAddress((void**)&x2,   g_x2);
    cudaGetSymbolAddress((void**)&t,    g_t);
    cudaGetSymbolAddress((void**)&wtb,  g_wt);

    float* cattnT = wtb;                       // [3072,1024]
    float* selfT  = wtb +  3l*1024*1024;
    float* qT     = wtb +  4l*1024*1024;
    float* kvT    = wtb +  5l*1024*1024;       // [2048,1024]
    float* crossT = wtb +  7l*1024*1024;
    float* fcT    = wtb +  8l*1024*1024;       // [4096,1024]
    float* mlpT   = wtb + 12l*1024*1024;       // [1024,4096]

    const int SM128  = (128*20 + 128*20) * 2 * 4;          // 40960 B
    const int SMFLSH = (64*68 + 64*72) * 2 * 4;            // 71680 B
    cudaFuncSetAttribute(flash_attn, cudaFuncAttributeMaxDynamicSharedMemorySize, SMFLSH);

    const int M = NB * SEQ;                  // 4096
    dim3 tb(32, 8);

    // ---- weight transposes (W[K,N] -> WT[N,K]) ----
    transpose_b<<<dim3( 96, 32), tb>>>(c_attn_w,     cattnT, 3*DIM, DIM);
    transpose_b<<<dim3( 32, 32), tb>>>(self_proj_w,  selfT,  DIM,   DIM);
    transpose_b<<<dim3( 32, 32), tb>>>(q_w,          qT,     DIM,   DIM);
    transpose_b<<<dim3( 64, 32), tb>>>(kv_w,         kvT,    2*DIM, DIM);
    transpose_b<<<dim3( 32, 32), tb>>>(cross_proj_w, crossT, DIM,   DIM);
    transpose_b<<<dim3(128, 32), tb>>>(fc_w,         fcT,    4*DIM, DIM);
    transpose_b<<<dim3( 32,128), tb>>>(mlp_proj_w,   mlpT,   DIM,   4*DIM);

    // 1. qkv = x @ c_attn_w + b
    gemm_mma<128, EPI_BIAS><<<dim3(24, 32, 1), 256, SM128>>>(
        x, cattnT, c_attn_b, qkv, DIM, DIM, DIM, 3*DIM, 0,0,0, 0.f);

    // 2-4. fused causal self-attention -> abuf (merged heads)
    flash_attn<<<dim3(8, NB*NHEAD), 256, SMFLSH>>>(
        qkv, qkv + DIM, qkv + 2*DIM, abuf, 3*DIM, 3*DIM, 1);

    // 5. t = a @ self_proj_w + b
    gemm_mma<128, EPI_BIAS><<<dim3(8, 32, 1), 256, SM128>>>(
        abuf, selfT, self_proj_b, t, DIM, DIM, DIM, DIM, 0,0,0, 0.f);

    // 6. x1 = LN(x + t)
    add_ln<<<M, 256>>>(x, t, ln1_g, ln1_b, x1);

    // 7. q = x1 @ q_w + b
    gemm_mma<128, EPI_BIAS><<<dim3(8, 32, 1), 256, SM128>>>(
        x1, qT, q_b, q, DIM, DIM, DIM, DIM, 0,0,0, 0.f);

    // 8. kv = ctx @ kv_w + b
    gemm_mma<128, EPI_BIAS><<<dim3(16, 32, 1), 256, SM128>>>(
        ctx, kvT, kv_b, kv, DIM, DIM, DIM, 2*DIM, 0,0,0, 0.f);

    // 9-11. fused cross-attention -> abuf
    flash_attn<<<dim3(8, NB*NHEAD), 256, SMFLSH>>>(
        q, kv, kv + DIM, abuf, DIM, 2*DIM, 0);

    // 12. t = a @ cross_proj_w + b
    gemm_mma<128, EPI_BIAS><<<dim3(8, 32, 1), 256, SM128>>>(
        abuf, crossT, cross_proj_b, t, DIM, DIM, DIM, DIM, 0,0,0, 0.f);

    // 13. x2 = LN(x1 + t)
    add_ln<<<M, 256>>>(x1, t, ln2_g, ln2_b, x2);

    // 14. h = gelu(x2 @ fc_w + b)
    gemm_mma<128, EPI_BIAS_GELU><<<dim3(32, 32, 1), 256, SM128>>>(
        x2, fcT, fc_b, h, DIM, DIM, DIM, 4*DIM, 0,0,0, 0.f);

    // 15. t = h @ mlp_proj_w + b
    gemm_mma<128, EPI_BIAS><<<dim3(8, 32, 1), 256, SM128>>>(
        h, mlpT, mlp_proj_b, t, 4*DIM, 4*DIM, 4*DIM, DIM, 0,0,0, 0.f);

    // 16. out = LN(x2 + t)
    add_ln<<<M, 256>>>(x2, t, ln3_g, ln3_b, out);
}

// round 8
// speedup vs baseline: 4.3379x; 1.2882x over previous
#include <cuda_runtime.h>
#include <math.h>
#include <stdint.h>

#define SEQ 1024
#define DIM 1024
#define NB  4
#define NHEAD 16
#define HD  64

enum { EPI_NONE=0, EPI_BIAS=1, EPI_BIAS_GELU=2 };

// ---------------- scratch (no allocations allowed) ----------------
__device__ float g_qkv[(size_t)NB*SEQ*3*DIM];
__device__ float g_a [(size_t)NB*SEQ*DIM];
__device__ float g_x1[(size_t)NB*SEQ*DIM];
__device__ float g_q [(size_t)NB*SEQ*DIM];
__device__ float g_kv[(size_t)NB*SEQ*2*DIM];
__device__ float g_h [(size_t)NB*SEQ*4*DIM];
__device__ float g_x2[(size_t)NB*SEQ*DIM];
__device__ float g_t [(size_t)NB*SEQ*DIM];
__device__ float g_wt[(size_t)16*1024*1024];   // 64MB transposed weights

__device__ __forceinline__ float gelu_tanh(float v){
    float u = 0.7978845608028654f * (v + 0.044715f * v * v * v);
    return 0.5f * v * (1.0f + tanhf(u));
}

#define CP_ASYNC16(s, g)  asm volatile("cp.async.cg.shared.global [%0], [%1], 16;" :: "r"(s), "l"(__cvta_generic_to_global(g)))
#define CP_COMMIT()       asm volatile("cp.async.commit_group;")
#define CP_WAIT(n)        asm volatile("cp.async.wait_group %0;" :: "n"(n))

__device__ __forceinline__ uint32_t smem_u32(const void* p) {
    uint32_t a;
    asm("{ .reg .u64 t; cvta.to.shared.u64 t, %1; cvt.u32.u64 %0, t; }" : "=r"(a) : "l"(p));
    return a;
}
// pack two fp32 -> half2 (lo in bits [15:0])
__device__ __forceinline__ uint32_t f2h2(float lo, float hi) {
    uint32_t r;
    asm("cvt.rn.f16x2.f32 %0, %1, %2;" : "=r"(r) : "f"(hi), "f"(lo));
    return r;
}
__device__ __forceinline__ void mma_f16(float* d, const uint32_t* a, const uint32_t* b) {
    asm volatile(
        "mma.sync.aligned.m16n8k16.row.col.f32.f16.f16.f32 "
        "{%0,%1,%2,%3}, {%4,%5,%6,%7}, {%8,%9}, {%0,%1,%2,%3};"
        : "+f"(d[0]), "+f"(d[1]), "+f"(d[2]), "+f"(d[3])
        : "r"(a[0]), "r"(a[1]), "r"(a[2]), "r"(a[3]), "r"(b[0]), "r"(b[1]));
}

// ---------------- fp16 mma.sync GEMM (fp32 in/out, fp32 accum) ----------------
// C[M,N] = epi( A[M,K] * B^T )   A: [M,K] K-major, B: [N,K] K-major.
// CTA tile 128 x BN, K-step 16, 2-stage cp.async double buffer.
template<int BN, int EPI>
__global__ void __launch_bounds__(256) gemm_mma(
    const float* __restrict__ A, const float* __restrict__ B,
    const float* __restrict__ bias, float* __restrict__ C,
    int K, int lda, int ldb, int ldc,
    long sA1, long sB1, long sC1)
{
    constexpr int BM = 128, BK = 16;
    constexpr int WN = BN / 4;
    constexpr int NT = WN / 8;
    constexpr int SA = BM * 24;           // stride 24: conflict-free LDS.64
    constexpr int SB = BN * 24;
    constexpr int STG = SA + SB;

    extern __shared__ float smem[];

    const int tid = threadIdx.x;
    const int bz = blockIdx.z;
    A += bz*sA1;  B += bz*sB1;  C += bz*sC1;
    const int row0 = blockIdx.y * BM;
    const int col0 = blockIdx.x * BN;

    const int wid = tid >> 5, lane = tid & 31;
    const int g = lane >> 2, tg = lane & 3;
    const int wm = (wid & 1) * 64;
    const int wn = (wid >> 1) * WN;

    const uint32_t sbase = smem_u32(smem);

    float acc[4][NT][4];
    #pragma unroll
    for (int mt = 0; mt < 4; mt++)
        #pragma unroll
        for (int nt = 0; nt < NT; nt++)
            #pragma unroll
            for (int i = 0; i < 4; i++) acc[mt][nt][i] = 0.f;

    auto load_stage = [&](int step) {
        int st = step & 1;
        long k0 = (long)step * BK;
        uint32_t as = sbase + st*STG*4;
        uint32_t bs = as + SA*4;
        #pragma unroll
        for (int i = 0; i < BM/64; i++) {
            int c = tid + i*256;
            int r = c >> 2, kc = c & 3;
            CP_ASYNC16(as + (uint32_t)(r*24 + kc*4)*4,
                       A + (long)(row0 + r)*lda + k0 + kc*4);
        }
        #pragma unroll
        for (int i = 0; i < BN/64; i++) {
            int c = tid + i*256;
            int r = c >> 2, kc = c & 3;
            CP_ASYNC16(bs + (uint32_t)(r*24 + kc*4)*4,
                       B + (long)(col0 + r)*ldb + k0 + kc*4);
        }
        CP_COMMIT();
    };

    const int nsteps = K / BK;
    load_stage(0);
    if (nsteps > 1) load_stage(1);

    for (int i = 0; i < nsteps; i++) {
        if (i + 2 < nsteps) { CP_WAIT(1); } else { CP_WAIT(0); }
        __syncthreads();

        const float* As = smem + (i & 1)*STG;
        const float* Bs = As + SA;

        uint32_t af[4][4], bf[NT][2];
        #pragma unroll
        for (int mt = 0; mt < 4; mt++) {
            int r = wm + mt*16 + g;
            float2 a01 = *(const float2*)&As[r*24     + 2*tg    ];
            float2 a23 = *(const float2*)&As[(r+8)*24 + 2*tg    ];
            float2 a45 = *(const float2*)&As[r*24     + 2*tg + 8];
            float2 a67 = *(const float2*)&As[(r+8)*24 + 2*tg + 8];
            af[mt][0] = f2h2(a01.x, a01.y);
            af[mt][1] = f2h2(a23.x, a23.y);
            af[mt][2] = f2h2(a45.x, a45.y);
            af[mt][3] = f2h2(a67.x, a67.y);
        }
        #pragma unroll
        for (int nt = 0; nt < NT; nt++) {
            int c = wn + nt*8 + g;
            float2 b01 = *(const float2*)&Bs[c*24 + 2*tg    ];
            float2 b23 = *(const float2*)&Bs[c*24 + 2*tg + 8];
            bf[nt][0] = f2h2(b01.x, b01.y);
            bf[nt][1] = f2h2(b23.x, b23.y);
        }
        #pragma unroll
        for (int mt = 0; mt < 4; mt++)
            #pragma unroll
            for (int nt = 0; nt < NT; nt++)
                mma_f16(acc[mt][nt], af[mt], bf[nt]);

        __syncthreads();
        if (i + 2 < nsteps) load_stage(i + 2);
    }

    #pragma unroll
    for (int mt = 0; mt < 4; mt++) {
        #pragma unroll
        for (int nt = 0; nt < NT; nt++) {
            int Rg = row0 + wm + mt*16 + g;
            int cg = col0 + wn + nt*8 + 2*tg;
            #pragma unroll
            for (int half = 0; half < 2; half++) {
                int r = Rg + half*8;
                float v0 = acc[mt][nt][half*2 + 0];
                float v1 = acc[mt][nt][half*2 + 1];
                if (EPI == EPI_BIAS || EPI == EPI_BIAS_GELU) {
                    v0 += bias[cg];  v1 += bias[cg+1];
                    if (EPI == EPI_BIAS_GELU) { v0 = gelu_tanh(v0); v1 = gelu_tanh(v1); }
                }
                float2 o = make_float2(v0, v1);
                *(float2*)&C[(long)r*ldc + cg] = o;
            }
        }
    }
}

// ---------------- fused flash attention (fp16 mma, fp32 accum) ----------------
// Q[128 rows/CTA] x K,V tiles of 64 keys. 8 warps x 16 rows.
__global__ void __launch_bounds__(256, 1) flash_attn(
    const float* __restrict__ Q, const float* __restrict__ K,
    const float* __restrict__ V, float* __restrict__ O,
    int ldq, int ldkv, int causal)
{
    constexpr int KST = 72, VST = 68;
    constexpr int STGF = 64*KST + 64*VST;   // floats per stage
    extern __shared__ float sm[];

    const int tid = threadIdx.x;
    const int wid = tid >> 5, lane = tid & 31;
    const int g = lane >> 2, tg = lane & 3;
    const int qt = blockIdx.x;
    const int bh = blockIdx.y, bb = bh >> 4, hh = bh & 15;
    const int wm = wid * 16;

    const float* Qb = Q + (long)bb*SEQ*ldq  + hh*64 + (long)qt*128*ldq;
    const float* Kb = K + (long)bb*SEQ*ldkv + hh*64;
    const float* Vb = V + (long)bb*SEQ*ldkv + hh*64;
    float*       Ob = O + (long)bb*SEQ*DIM  + hh*64 + (long)qt*128*DIM;

    const uint32_t sbase = smem_u32(sm);

    // ---- stage Q (scaled), build fp16 A-fragments: 4 k16 blocks over hd=64 ----
    #pragma unroll
    for (int i = 0; i < 8; i++) {
        int c = tid + i*256;
        int r = c >> 4, kc = c & 15;
        CP_ASYNC16(sbase + (uint32_t)(r*KST + kc*4)*4, Qb + (long)r*ldq + kc*4);
    }
    CP_COMMIT(); CP_WAIT(0);
    __syncthreads();

    uint32_t aq[4][4];
    #pragma unroll
    for (int kt = 0; kt < 4; kt++) {
        int k0 = kt*16;
        const float* q0 = &sm[(wm+g  )*KST + k0];
        const float* q1 = &sm[(wm+g+8)*KST + k0];
        aq[kt][0] = f2h2(q0[2*tg  ]*0.125f, q0[2*tg+1]*0.125f);
        aq[kt][1] = f2h2(q1[2*tg  ]*0.125f, q1[2*tg+1]*0.125f);
        aq[kt][2] = f2h2(q0[2*tg+8]*0.125f, q0[2*tg+9]*0.125f);
        aq[kt][3] = f2h2(q1[2*tg+8]*0.125f, q1[2*tg+9]*0.125f);
    }
    __syncthreads();

    float acc_o[8][4];
    #pragma unroll
    for (int nt = 0; nt < 8; nt++)
        #pragma unroll
        for (int i = 0; i < 4; i++) acc_o[nt][i] = 0.f;
    float m0 = -1e30f, m1 = -1e30f, l0 = 0.f, l1 = 0.f;

    const int ntiles = causal ? (2*qt + 2) : (SEQ/64);
    const int rowg0 = qt*128 + wm + g;
    const int rowg1 = rowg0 + 8;

    auto load_kv = [&](int j) {
        uint32_t st = sbase + (uint32_t)((j & 1) * STGF) * 4u;
        const float* Kg = Kb + (long)j*64*ldkv;
        const float* Vg = Vb + (long)j*64*ldkv;
        #pragma unroll
        for (int i = 0; i < 4; i++) {
            int c = tid + i*256;
            int r = c >> 4, kc = c & 15;
            CP_ASYNC16(st + (uint32_t)(r*KST + kc*4)*4, Kg + (long)r*ldkv + kc*4);
        }
        uint32_t vs = st + 64u*KST*4u;
        #pragma unroll
        for (int i = 0; i < 4; i++) {
            int c = tid + i*256;
            int r = c >> 4, kc = c & 15;
            CP_ASYNC16(vs + (uint32_t)(r*VST + kc*4)*4, Vg + (long)r*ldkv + kc*4);
        }
        CP_COMMIT();
    };

    load_kv(0);
    if (ntiles > 1) load_kv(1);

    for (int j = 0; j < ntiles; j++) {
        if (j + 1 < ntiles) { CP_WAIT(1); } else { CP_WAIT(0); }
        __syncthreads();
        const float* Ks = sm + (j & 1)*STGF;
        const float* Vs = Ks + 64*KST;

        // ---- S = (Q*scale) K^T ----
        float s[8][4];
        #pragma unroll
        for (int nt = 0; nt < 8; nt++)
            #pragma unroll
            for (int i = 0; i < 4; i++) s[nt][i] = 0.f;

        #pragma unroll
        for (int kt = 0; kt < 4; kt++) {
            int k0 = kt*16;
            #pragma unroll
            for (int nt = 0; nt < 8; nt++) {
                int c = nt*8 + g;
                float2 b01 = *(const float2*)&Ks[c*KST + k0 + 2*tg    ];
                float2 b23 = *(const float2*)&Ks[c*KST + k0 + 2*tg + 8];
                uint32_t bf[2];
                bf[0] = f2h2(b01.x, b01.y);
                bf[1] = f2h2(b23.x, b23.y);
                mma_f16(s[nt], aq[kt], bf);
            }
        }

        // ---- causal mask (diagonal tiles only) ----
        if (causal && j >= 2*qt) {
            int kbase = j*64;
            #pragma unroll
            for (int nt = 0; nt < 8; nt++) {
                int kg = kbase + nt*8 + 2*tg;
                if (kg     > rowg0) s[nt][0] = -1e30f;
                if (kg + 1 > rowg0) s[nt][1] = -1e30f;
                if (kg     > rowg1) s[nt][2] = -1e30f;
                if (kg + 1 > rowg1) s[nt][3] = -1e30f;
            }
        }

        // ---- online softmax ----
        float tm0 = -1e30f, tm1 = -1e30f;
        #pragma unroll
        for (int nt = 0; nt < 8; nt++) {
            tm0 = fmaxf(tm0, fmaxf(s[nt][0], s[nt][1]));
            tm1 = fmaxf(tm1, fmaxf(s[nt][2], s[nt][3]));
        }
        tm0 = fmaxf(tm0, __shfl_xor_sync(0xffffffffu, tm0, 1));
        tm0 = fmaxf(tm0, __shfl_xor_sync(0xffffffffu, tm0, 2));
        tm1 = fmaxf(tm1, __shfl_xor_sync(0xffffffffu, tm1, 1));
        tm1 = fmaxf(tm1, __shfl_xor_sync(0xffffffffu, tm1, 2));

        float mn0 = fmaxf(m0, tm0), mn1 = fmaxf(m1, tm1);
        float al0 = __expf(m0 - mn0), al1 = __expf(m1 - mn1);
        float ts0 = 0.f, ts1 = 0.f;
        #pragma unroll
        for (int nt = 0; nt < 8; nt++) {
            s[nt][0] = __expf(s[nt][0] - mn0);
            s[nt][1] = __expf(s[nt][1] - mn0);
            s[nt][2] = __expf(s[nt][2] - mn1);
            s[nt][3] = __expf(s[nt][3] - mn1);
            ts0 += s[nt][0] + s[nt][1];
            ts1 += s[nt][2] + s[nt][3];
        }
        ts0 += __shfl_xor_sync(0xffffffffu, ts0, 1);
        ts0 += __shfl_xor_sync(0xffffffffu, ts0, 2);
        ts1 += __shfl_xor_sync(0xffffffffu, ts1, 1);
        ts1 += __shfl_xor_sync(0xffffffffu, ts1, 2);

        l0 = l0*al0 + ts0;  l1 = l1*al1 + ts1;
        m0 = mn0;  m1 = mn1;

        #pragma unroll
        for (int nt = 0; nt < 8; nt++) {
            acc_o[nt][0] *= al0;  acc_o[nt][1] *= al0;
            acc_o[nt][2] *= al1;  acc_o[nt][3] *= al1;
        }

        // ---- O += P V : P C-frags map directly onto fp16 k16 A-frags ----
        #pragma unroll
        for (int kt = 0; kt < 4; kt++) {
            int k0 = kt*16;
            uint32_t ap[4];
            ap[0] = f2h2(s[2*kt  ][0], s[2*kt  ][1]);
            ap[1] = f2h2(s[2*kt  ][2], s[2*kt  ][3]);
            ap[2] = f2h2(s[2*kt+1][0], s[2*kt+1][1]);
            ap[3] = f2h2(s[2*kt+1][2], s[2*kt+1][3]);
            #pragma unroll
            for (int nt = 0; nt < 8; nt++) {
                int c = nt*8 + g;
                uint32_t bv[2];
                bv[0] = f2h2(Vs[(k0 + 2*tg    )*VST + c], Vs[(k0 + 2*tg + 1)*VST + c]);
                bv[1] = f2h2(Vs[(k0 + 2*tg + 8)*VST + c], Vs[(k0 + 2*tg + 9)*VST + c]);
                mma_f16(acc_o[nt], ap, bv);
            }
        }
        __syncthreads();
        if (j + 2 < ntiles) load_kv(j + 2);
    }

    // ---- normalize + store ----
    float r0 = 1.f / l0, r1 = 1.f / l1;
    #pragma unroll
    for (int nt = 0; nt < 8; nt++) {
        int c = nt*8 + 2*tg;
        float2 v0 = make_float2(acc_o[nt][0]*r0, acc_o[nt][1]*r0);
        float2 v1 = make_float2(acc_o[nt][2]*r1, acc_o[nt][3]*r1);
        *(float2*)&Ob[(long)(wm+g  )*DIM + c] = v0;
        *(float2*)&Ob[(long)(wm+g+8)*DIM + c] = v1;
    }
}

// ---------------- batched 32x32 tiled transpose ----------------
__global__ void transpose_b(const float* __restrict__ in, float* __restrict__ out,
                            int ldin, int ldout)
{
    __shared__ float t[32][33];
    int r0 = blockIdx.y*32, c0 = blockIdx.x*32;
    int x = threadIdx.x, y = threadIdx.y;
    #pragma unroll
    for (int i = 0; i < 32; i += 8) t[y+i][x] = in[(long)(r0+y+i)*ldin + c0 + x];
    __syncthreads();
    #pragma unroll
    for (int i = 0; i < 32; i += 8) out[(long)(c0+y+i)*ldout + r0 + x] = t[x][y+i];
}

// ---------------- fused residual add + LayerNorm ----------------
__global__ void __launch_bounds__(256) add_ln(
    const float* __restrict__ x, const float* __restrict__ a,
    const float* __restrict__ g, const float* __restrict__ b,
    float* __restrict__ y)
{
    __shared__ float red[8];
    __shared__ float bc;
    long row = blockIdx.x;
    const float* xr = x + row * DIM;
    const float* ar = a + row * DIM;
    float* yr = y + row * DIM;
    int tid = threadIdx.x, lane = tid & 31, wid = tid >> 5;

    float v[4], s = 0.f;
    #pragma unroll
    for (int i = 0; i < 4; i++) { int c = tid + i*256; v[i] = xr[c] + ar[c]; s += v[i]; }
    #pragma unroll
    for (int o = 16; o > 0; o >>= 1) s += __shfl_xor_sync(0xffffffffu, s, o);
    if (lane == 0) red[wid] = s;
    __syncthreads();
    if (tid == 0) {
        float t = 0.f;
        #pragma unroll
        for (int i = 0; i < 8; i++) t += red[i];
        bc = t * (1.0f / DIM);
    }
    __syncthreads();
    float mu = bc;

    float q = 0.f;
    #pragma unroll
    for (int i = 0; i < 4; i++) { float d = v[i] - mu; q += d * d; }
    #pragma unroll
    for (int o = 16; o > 0; o >>= 1) q += __shfl_xor_sync(0xffffffffu, q, o);
    __syncthreads();
    if (lane == 0) red[wid] = q;
    __syncthreads();
    if (tid == 0) {
        float t = 0.f;
        #pragma unroll
        for (int i = 0; i < 8; i++) t += red[i];
        bc = rsqrtf(t * (1.0f / DIM) + 1e-5f);
    }
    __syncthreads();
    float inv = bc;
    #pragma unroll
    for (int i = 0; i < 4; i++) {
        int c = tid + i*256;
        yr[c] = (v[i] - mu) * inv * g[c] + b[c];
    }
}

// ---------------- host orchestration ----------------
extern "C" void kernel_launch(void* const* d_in, const int* in_sizes, int n_in,
                              void* d_out, int out_size)
{
    const float* x            = (const float*)d_in[0];
    const float* ctx          = (const float*)d_in[1];
    const float* c_attn_w     = (const float*)d_in[2];
    const float* c_attn_b     = (const float*)d_in[3];
    const float* self_proj_w  = (const float*)d_in[4];
    const float* self_proj_b  = (const float*)d_in[5];
    const float* q_w          = (const float*)d_in[6];
    const float* q_b          = (const float*)d_in[7];
    const float* kv_w         = (const float*)d_in[8];
    const float* kv_b         = (const float*)d_in[9];
    const float* cross_proj_w = (const float*)d_in[10];
    const float* cross_proj_b = (const float*)d_in[11];
    const float* fc_w         = (const float*)d_in[12];
    const float* fc_b         = (const float*)d_in[13];
    const float* mlp_proj_w   = (const float*)d_in[14];
    const float* mlp_proj_b   = (const float*)d_in[15];
    const float* ln1_g        = (const float*)d_in[16];
    const float* ln1_b        = (const float*)d_in[17];
    const float* ln2_g        = (const float*)d_in[18];
    const float* ln2_b        = (const float*)d_in[19];
    const float* ln3_g        = (const float*)d_in[20];
    const float* ln3_b        = (const float*)d_in[21];
    float* out = (float*)d_out;

    float *qkv, *abuf, *x1, *q, *kv, *h, *x2, *t, *wtb;
    cudaGetSymbolAddress((void**)&qkv,  g_qkv);
    cudaGetSymbolAddress((void**)&abuf, g_a);
    cudaGetSymbolAddress((void**)&x1,   g_x1);
    cudaGetSymbolAddress((void**)&q,    g_q);
    cudaGetSymbolAddress((void**)&kv,   g_kv);
    cudaGetSymbolAddress((void**)&h,    g_h);
    cudaGetSymbolAddress((void**)&x2,   g_x2);
    cudaGetSymbolAddress((void**)&t,    g_t);
    cudaGetSymbolAddress((void**)&wtb,  g_wt);

    float* cattnT = wtb;                       // [3072,1024]
    float* selfT  = wtb +  3l*1024*1024;
    float* qT     = wtb +  4l*1024*1024;
    float* kvT    = wtb +  5l*1024*1024;       // [2048,1024]
    float* crossT = wtb +  7l*1024*1024;
    float* fcT    = wtb +  8l*1024*1024;       // [4096,1024]
    float* mlpT   = wtb + 12l*1024*1024;       // [1024,4096]

    const int SM128  = (128*24 + 128*24) * 2 * 4;          // 49152 B
    const int SMFLSH = (64*72 + 64*68) * 2 * 4;            // 71680 B
    cudaFuncSetAttribute(flash_attn, cudaFuncAttributeMaxDynamicSharedMemorySize, SMFLSH);

    const int M = NB * SEQ;                  // 4096
    dim3 tb(32, 8);

    // ---- weight transposes (W[K,N] -> WT[N,K]) ----
    transpose_b<<<dim3( 96, 32), tb>>>(c_attn_w,     cattnT, 3*DIM, DIM);
    transpose_b<<<dim3( 32, 32), tb>>>(self_proj_w,  selfT,  DIM,   DIM);
    transpose_b<<<dim3( 32, 32), tb>>>(q_w,          qT,     DIM,   DIM);
    transpose_b<<<dim3( 64, 32), tb>>>(kv_w,         kvT,    2*DIM, DIM);
    transpose_b<<<dim3( 32, 32), tb>>>(cross_proj_w, crossT, DIM,   DIM);
    transpose_b<<<dim3(128, 32), tb>>>(fc_w,         fcT,    4*DIM, DIM);
    transpose_b<<<dim3( 32,128), tb>>>(mlp_proj_w,   mlpT,   DIM,   4*DIM);

    // 1. qkv = x @ c_attn_w + b
    gemm_mma<128, EPI_BIAS><<<dim3(24, 32, 1), 256, SM128>>>(
        x, cattnT, c_attn_b, qkv, DIM, DIM, DIM, 3*DIM, 0,0,0);

    // 2-4. fused causal self-attention -> abuf (merged heads)
    flash_attn<<<dim3(8, NB*NHEAD), 256, SMFLSH>>>(
        qkv, qkv + DIM, qkv + 2*DIM, abuf, 3*DIM, 3*DIM, 1);

    // 5. t = a @ self_proj_w + b
    gemm_mma<128, EPI_BIAS><<<dim3(8, 32, 1), 256, SM128>>>(
        abuf, selfT, self_proj_b, t, DIM, DIM, DIM, DIM, 0,0,0);

    // 6. x1 = LN(x + t)
    add_ln<<<M, 256>>>(x, t, ln1_g, ln1_b, x1);

    // 7. q = x1 @ q_w + b
    gemm_mma<128, EPI_BIAS><<<dim3(8, 32, 1), 256, SM128>>>(
        x1, qT, q_b, q, DIM, DIM, DIM, DIM, 0,0,0);

    // 8. kv = ctx @ kv_w + b
    gemm_mma<128, EPI_BIAS><<<dim3(16, 32, 1), 256, SM128>>>(
        ctx, kvT, kv_b, kv, DIM, DIM, DIM, 2*DIM, 0,0,0);

    // 9-11. fused cross-attention -> abuf
    flash_attn<<<dim3(8, NB*NHEAD), 256, SMFLSH>>>(
        q, kv, kv + DIM, abuf, DIM, 2*DIM, 0);

    // 12. t = a @ cross_proj_w + b
    gemm_mma<128, EPI_BIAS><<<dim3(8, 32, 1), 256, SM128>>>(
        abuf, crossT, cross_proj_b, t, DIM, DIM, DIM, DIM, 0,0,0);

    // 13. x2 = LN(x1 + t)
    add_ln<<<M, 256>>>(x1, t, ln2_g, ln2_b, x2);

    // 14. h = gelu(x2 @ fc_w + b)
    gemm_mma<128, EPI_BIAS_GELU><<<dim3(32, 32, 1), 256, SM128>>>(
        x2, fcT, fc_b, h, DIM, DIM, DIM, 4*DIM, 0,0,0);

    // 15. t = h @ mlp_proj_w + b
    gemm_mma<128, EPI_BIAS><<<dim3(8, 32, 1), 256, SM128>>>(
        h, mlpT, mlp_proj_b, t, 4*DIM, 4*DIM, 4*DIM, DIM, 0,0,0);

    // 16. out = LN(x2 + t)
    add_ln<<<M, 256>>>(x2, t, ln3_g, ln3_b, out);
}

// round 9
// speedup vs baseline: 6.5117x; 1.5011x over previous
#include <cuda_runtime.h>
#include <cuda_fp16.h>
#include <math.h>
#include <stdint.h>

#define SEQ 1024
#define DIM 1024
#define NB  4
#define NHEAD 16
#define HD  64

enum { EPI_BIAS=1, EPI_BIAS_GELU=2 };

// ---------------- scratch (no allocations allowed) ----------------
__device__ float  g_t [(size_t)NB*SEQ*DIM];
__device__ float  g_x1[(size_t)NB*SEQ*DIM];
__device__ float  g_x2[(size_t)NB*SEQ*DIM];
__device__ __half g_qkvh[(size_t)NB*SEQ*3*DIM];
__device__ __half g_abufh[(size_t)NB*SEQ*DIM];
__device__ __half g_xh [(size_t)NB*SEQ*DIM];
__device__ __half g_ctxh[(size_t)NB*SEQ*DIM];
__device__ __half g_x1h[(size_t)NB*SEQ*DIM];
__device__ __half g_x2h[(size_t)NB*SEQ*DIM];
__device__ __half g_qh [(size_t)NB*SEQ*DIM];
__device__ __half g_kvh[(size_t)NB*SEQ*2*DIM];
__device__ __half g_hh [(size_t)NB*SEQ*4*DIM];
__device__ __half g_wth[(size_t)16*1024*1024];   // 32MB transposed half weights

__device__ __forceinline__ float gelu_tanh(float v){
    float u = 0.7978845608028654f * (v + 0.044715f * v * v * v);
    return 0.5f * v * (1.0f + tanhf(u));
}

#define CP_ASYNC16(s, g)  asm volatile("cp.async.cg.shared.global [%0], [%1], 16;" :: "r"(s), "l"(__cvta_generic_to_global(g)))
#define CP_COMMIT()       asm volatile("cp.async.commit_group;")
#define CP_WAIT(n)        asm volatile("cp.async.wait_group %0;" :: "n"(n))

#define LDSM_X4(r0,r1,r2,r3,addr) \
    asm volatile("ldmatrix.sync.aligned.m8n8.x4.shared.b16 {%0,%1,%2,%3}, [%4];" \
                 : "=r"(r0),"=r"(r1),"=r"(r2),"=r"(r3) : "r"(addr))
#define LDSM_X4T(r0,r1,r2,r3,addr) \
    asm volatile("ldmatrix.sync.aligned.m8n8.x4.trans.shared.b16 {%0,%1,%2,%3}, [%4];" \
                 : "=r"(r0),"=r"(r1),"=r"(r2),"=r"(r3) : "r"(addr))

__device__ __forceinline__ uint32_t smem_u32(const void* p) {
    uint32_t a;
    asm("{ .reg .u64 t; cvta.to.shared.u64 t, %1; cvt.u32.u64 %0, t; }" : "=r"(a) : "l"(p));
    return a;
}
__device__ __forceinline__ uint32_t f2h2(float lo, float hi) {
    uint32_t r;
    asm("cvt.rn.f16x2.f32 %0, %1, %2;" : "=r"(r) : "f"(hi), "f"(lo));
    return r;
}
__device__ __forceinline__ void mma_f16(float* d, const uint32_t* a, const uint32_t* b) {
    asm volatile(
        "mma.sync.aligned.m16n8k16.row.col.f32.f16.f16.f32 "
        "{%0,%1,%2,%3}, {%4,%5,%6,%7}, {%8,%9}, {%0,%1,%2,%3};"
        : "+f"(d[0]), "+f"(d[1]), "+f"(d[2]), "+f"(d[3])
        : "r"(a[0]), "r"(a[1]), "r"(a[2]), "r"(a[3]), "r"(b[0]), "r"(b[1]));
}

// ---------------- fp16 ldmatrix GEMM (half in, fp32 accum, fp32/half out) ----
// C[M,N] = epi( A[M,K] * B^T )  A:[M,K] half K-major, B:[N,K] half K-major.
// Tile 128x128, BK=32, 2-stage cp.async. 8 warps 2x4; warp tile 64x32.
template<int EPI, bool OUTH>
__global__ void __launch_bounds__(256) gemm_mma(
    const __half* __restrict__ A, const __half* __restrict__ B,
    const float* __restrict__ bias, float* __restrict__ C, __half* __restrict__ Ch,
    int K, int lda, int ldb, int ldc)
{
    constexpr int BM = 128, BN = 128, BK = 32;
    constexpr int AST = 40;                 // halves per smem row (32 + 8 pad)
    constexpr int SA = BM * AST, SB = BN * AST, STG = SA + SB;  // halves

    extern __shared__ __half smh[];
    const uint32_t sbase = smem_u32(smh);

    const int tid = threadIdx.x;
    const int row0 = blockIdx.y * BM;
    const int col0 = blockIdx.x * BN;
    const int wid = tid >> 5, lane = tid & 31;
    const int g = lane >> 2, tg = lane & 3;
    const int wm = (wid & 1) * 64;
    const int wn = (wid >> 1) * 32;

    float acc[4][4][4];
    #pragma unroll
    for (int mt = 0; mt < 4; mt++)
        #pragma unroll
        for (int nt = 0; nt < 4; nt++)
            #pragma unroll
            for (int i = 0; i < 4; i++) acc[mt][nt][i] = 0.f;

    auto load_stage = [&](int step) {
        int st = step & 1;
        long k0 = (long)step * BK;
        uint32_t as = sbase + (uint32_t)(st*STG)*2u;
        uint32_t bs = as + (uint32_t)SA*2u;
        #pragma unroll
        for (int i = 0; i < 2; i++) {           // A: 128 rows x 4 chunks
            int c = tid + i*256;
            int r = c >> 2, kc = c & 3;
            CP_ASYNC16(as + (uint32_t)(r*AST + kc*8)*2,
                       A + (long)(row0 + r)*lda + k0 + kc*8);
        }
        #pragma unroll
        for (int i = 0; i < 2; i++) {           // B
            int c = tid + i*256;
            int r = c >> 2, kc = c & 3;
            CP_ASYNC16(bs + (uint32_t)(r*AST + kc*8)*2,
                       B + (long)(col0 + r)*ldb + k0 + kc*8);
        }
        CP_COMMIT();
    };

    const int nsteps = K / BK;
    load_stage(0);
    if (nsteps > 1) load_stage(1);

    const int a_r = lane & 15, a_c8 = (lane >> 4) << 3;
    const int b_r = ((lane >> 4) << 3) + (lane & 7);
    const int b_c8 = ((lane >> 3) & 1) << 3;

    for (int i = 0; i < nsteps; i++) {
        if (i + 2 < nsteps) { CP_WAIT(1); } else { CP_WAIT(0); }
        __syncthreads();

        uint32_t as = sbase + (uint32_t)((i & 1)*STG)*2u;
        uint32_t bs = as + (uint32_t)SA*2u;

        #pragma unroll
        for (int kb = 0; kb < 2; kb++) {
            int kk = kb * 16;
            uint32_t af[4][4], bf[4][2];
            #pragma unroll
            for (int mt = 0; mt < 4; mt++) {
                uint32_t ad = as + (uint32_t)((wm + mt*16 + a_r)*AST + kk + a_c8)*2;
                LDSM_X4(af[mt][0], af[mt][1], af[mt][2], af[mt][3], ad);
            }
            #pragma unroll
            for (int p = 0; p < 2; p++) {
                uint32_t bd = bs + (uint32_t)((wn + p*16 + b_r)*AST + kk + b_c8)*2;
                LDSM_X4(bf[2*p][0], bf[2*p][1], bf[2*p+1][0], bf[2*p+1][1], bd);
            }
            #pragma unroll
            for (int mt = 0; mt < 4; mt++)
                #pragma unroll
                for (int nt = 0; nt < 4; nt++)
                    mma_f16(acc[mt][nt], af[mt], bf[nt]);
        }
        __syncthreads();
        if (i + 2 < nsteps) load_stage(i + 2);
    }

    #pragma unroll
    for (int mt = 0; mt < 4; mt++) {
        #pragma unroll
        for (int nt = 0; nt < 4; nt++) {
            int Rg = row0 + wm + mt*16 + g;
            int cg = col0 + wn + nt*8 + 2*tg;
            #pragma unroll
            for (int half_i = 0; half_i < 2; half_i++) {
                int r = Rg + half_i*8;
                float v0 = acc[mt][nt][half_i*2 + 0] + bias[cg];
                float v1 = acc[mt][nt][half_i*2 + 1] + bias[cg+1];
                if (EPI == EPI_BIAS_GELU) { v0 = gelu_tanh(v0); v1 = gelu_tanh(v1); }
                if (OUTH) {
                    *(uint32_t*)&Ch[(long)r*ldc + cg] = f2h2(v0, v1);
                } else {
                    *(float2*)&C[(long)r*ldc + cg] = make_float2(v0, v1);
                }
            }
        }
    }
}

// ---------------- fused flash attention (half in, fp32 softmax/accum, half out)
// Q 128 rows/CTA; K,V tiles 64 keys; 8 warps x 16 rows.
__global__ void __launch_bounds__(256, 1) flash_attn(
    const __half* __restrict__ Q, const __half* __restrict__ K,
    const __half* __restrict__ V, __half* __restrict__ O,
    int ldq, int ldkv, int causal)
{
    constexpr int ST = 72;                  // halves per row (64 + 8)
    constexpr int QSZ = 128*ST;             // halves
    constexpr int KVSZ = 64*ST;
    constexpr int STGH = 2*KVSZ;            // K + V per stage
    extern __shared__ __half smh[];
    const uint32_t sbase = smem_u32(smh);

    const int tid = threadIdx.x;
    const int wid = tid >> 5, lane = tid & 31;
    const int g = lane >> 2, tg = lane & 3;
    const int qt = blockIdx.x;
    const int bh = blockIdx.y, bb = bh >> 4, hh = bh & 15;
    const int wm = wid * 16;

    const __half* Qb = Q + (long)bb*SEQ*ldq  + hh*64 + (long)qt*128*ldq;
    const __half* Kb = K + (long)bb*SEQ*ldkv + hh*64;
    const __half* Vb = V + (long)bb*SEQ*ldkv + hh*64;
    __half*       Ob = O + (long)bb*SEQ*DIM  + hh*64 + (long)qt*128*DIM;

    // ---- stage Q ----
    #pragma unroll
    for (int i = 0; i < 4; i++) {
        int c = tid + i*256;
        int r = c >> 3, kc = c & 7;
        CP_ASYNC16(sbase + (uint32_t)(r*ST + kc*8)*2, Qb + (long)r*ldq + kc*8);
    }
    CP_COMMIT(); CP_WAIT(0);
    __syncthreads();

    const int a_r = lane & 15, a_c8 = (lane >> 4) << 3;
    const int b_r = ((lane >> 4) << 3) + (lane & 7);
    const int b_c8 = ((lane >> 3) & 1) << 3;
    const int v_r = (((lane >> 3) & 1) << 3) + (lane & 7);
    const int v_c8 = (lane >> 4) << 3;

    uint32_t aq[4][4];
    #pragma unroll
    for (int kt = 0; kt < 4; kt++) {
        uint32_t ad = sbase + (uint32_t)((wm + a_r)*ST + kt*16 + a_c8)*2;
        LDSM_X4(aq[kt][0], aq[kt][1], aq[kt][2], aq[kt][3], ad);
    }
    __syncthreads();

    float acc_o[8][4];
    #pragma unroll
    for (int nt = 0; nt < 8; nt++)
        #pragma unroll
        for (int i = 0; i < 4; i++) acc_o[nt][i] = 0.f;
    float m0 = -1e30f, m1 = -1e30f, l0 = 0.f, l1 = 0.f;

    const int ntiles = causal ? (2*qt + 2) : (SEQ/64);
    const int rowg0 = qt*128 + wm + g;
    const int rowg1 = rowg0 + 8;

    auto load_kv = [&](int j) {
        uint32_t st = sbase + (uint32_t)(QSZ + (j & 1)*STGH)*2u;
        const __half* Kg = Kb + (long)j*64*ldkv;
        const __half* Vg = Vb + (long)j*64*ldkv;
        #pragma unroll
        for (int i = 0; i < 2; i++) {
            int c = tid + i*256;
            int r = c >> 3, kc = c & 7;
            CP_ASYNC16(st + (uint32_t)(r*ST + kc*8)*2, Kg + (long)r*ldkv + kc*8);
        }
        uint32_t vs = st + (uint32_t)KVSZ*2u;
        #pragma unroll
        for (int i = 0; i < 2; i++) {
            int c = tid + i*256;
            int r = c >> 3, kc = c & 7;
            CP_ASYNC16(vs + (uint32_t)(r*ST + kc*8)*2, Vg + (long)r*ldkv + kc*8);
        }
        CP_COMMIT();
    };

    load_kv(0);
    if (ntiles > 1) load_kv(1);

    for (int j = 0; j < ntiles; j++) {
        if (j + 1 < ntiles) { CP_WAIT(1); } else { CP_WAIT(0); }
        __syncthreads();
        uint32_t ks = sbase + (uint32_t)(QSZ + (j & 1)*STGH)*2u;
        uint32_t vs = ks + (uint32_t)KVSZ*2u;

        // ---- S = Q K^T (unscaled) ----
        float s[8][4];
        #pragma unroll
        for (int nt = 0; nt < 8; nt++)
            #pragma unroll
            for (int i = 0; i < 4; i++) s[nt][i] = 0.f;

        #pragma unroll
        for (int kt = 0; kt < 4; kt++) {
            int kk = kt*16;
            #pragma unroll
            for (int p = 0; p < 4; p++) {
                uint32_t bf[2][2];
                uint32_t bd = ks + (uint32_t)((p*16 + b_r)*ST + kk + b_c8)*2;
                LDSM_X4(bf[0][0], bf[0][1], bf[1][0], bf[1][1], bd);
                mma_f16(s[2*p  ], aq[kt], bf[0]);
                mma_f16(s[2*p+1], aq[kt], bf[1]);
            }
        }

        // ---- scale + causal mask ----
        #pragma unroll
        for (int nt = 0; nt < 8; nt++)
            #pragma unroll
            for (int i = 0; i < 4; i++) s[nt][i] *= 0.125f;

        if (causal && j >= 2*qt) {
            int kbase = j*64;
            #pragma unroll
            for (int nt = 0; nt < 8; nt++) {
                int kg = kbase + nt*8 + 2*tg;
                if (kg     > rowg0) s[nt][0] = -1e30f;
                if (kg + 1 > rowg0) s[nt][1] = -1e30f;
                if (kg     > rowg1) s[nt][2] = -1e30f;
                if (kg + 1 > rowg1) s[nt][3] = -1e30f;
            }
        }

        // ---- online softmax ----
        float tm0 = -1e30f, tm1 = -1e30f;
        #pragma unroll
        for (int nt = 0; nt < 8; nt++) {
            tm0 = fmaxf(tm0, fmaxf(s[nt][0], s[nt][1]));
            tm1 = fmaxf(tm1, fmaxf(s[nt][2], s[nt][3]));
        }
        tm0 = fmaxf(tm0, __shfl_xor_sync(0xffffffffu, tm0, 1));
        tm0 = fmaxf(tm0, __shfl_xor_sync(0xffffffffu, tm0, 2));
        tm1 = fmaxf(tm1, __shfl_xor_sync(0xffffffffu, tm1, 1));
        tm1 = fmaxf(tm1, __shfl_xor_sync(0xffffffffu, tm1, 2));

        float mn0 = fmaxf(m0, tm0), mn1 = fmaxf(m1, tm1);
        float al0 = __expf(m0 - mn0), al1 = __expf(m1 - mn1);
        float ts0 = 0.f, ts1 = 0.f;
        #pragma unroll
        for (int nt = 0; nt < 8; nt++) {
            s[nt][0] = __expf(s[nt][0] - mn0);
            s[nt][1] = __expf(s[nt][1] - mn0);
            s[nt][2] = __expf(s[nt][2] - mn1);
            s[nt][3] = __expf(s[nt][3] - mn1);
            ts0 += s[nt][0] + s[nt][1];
            ts1 += s[nt][2] + s[nt][3];
        }
        ts0 += __shfl_xor_sync(0xffffffffu, ts0, 1);
        ts0 += __shfl_xor_sync(0xffffffffu, ts0, 2);
        ts1 += __shfl_xor_sync(0xffffffffu, ts1, 1);
        ts1 += __shfl_xor_sync(0xffffffffu, ts1, 2);

        l0 = l0*al0 + ts0;  l1 = l1*al1 + ts1;
        m0 = mn0;  m1 = mn1;

        #pragma unroll
        for (int nt = 0; nt < 8; nt++) {
            acc_o[nt][0] *= al0;  acc_o[nt][1] *= al0;
            acc_o[nt][2] *= al1;  acc_o[nt][3] *= al1;
        }

        // ---- O += P V ----
        #pragma unroll
        for (int kt = 0; kt < 4; kt++) {
            uint32_t ap[4];
            ap[0] = f2h2(s[2*kt  ][0], s[2*kt  ][1]);
            ap[1] = f2h2(s[2*kt  ][2], s[2*kt  ][3]);
            ap[2] = f2h2(s[2*kt+1][0], s[2*kt+1][1]);
            ap[3] = f2h2(s[2*kt+1][2], s[2*kt+1][3]);
            #pragma unroll
            for (int p = 0; p < 4; p++) {
                uint32_t bv[2][2];
                uint32_t vd = vs + (uint32_t)((kt*16 + v_r)*ST + p*16 + v_c8)*2;
                LDSM_X4T(bv[0][0], bv[0][1], bv[1][0], bv[1][1], vd);
                mma_f16(acc_o[2*p  ], ap, bv[0]);
                mma_f16(acc_o[2*p+1], ap, bv[1]);
            }
        }
        __syncthreads();
        if (j + 2 < ntiles) load_kv(j + 2);
    }

    // ---- normalize + store half ----
    float r0 = 1.f / l0, r1 = 1.f / l1;
    #pragma unroll
    for (int nt = 0; nt < 8; nt++) {
        int c = nt*8 + 2*tg;
        *(uint32_t*)&Ob[(long)(wm+g  )*DIM + c] = f2h2(acc_o[nt][0]*r0, acc_o[nt][1]*r0);
        *(uint32_t*)&Ob[(long)(wm+g+8)*DIM + c] = f2h2(acc_o[nt][2]*r1, acc_o[nt][3]*r1);
    }
}

// ---------------- 32x32 tiled transpose, fp32 -> half ----------------
__global__ void transpose_h(const float* __restrict__ in, __half* __restrict__ out,
                            int ldin, int ldout)
{
    __shared__ float t[32][33];
    int r0 = blockIdx.y*32, c0 = blockIdx.x*32;
    int x = threadIdx.x, y = threadIdx.y;
    #pragma unroll
    for (int i = 0; i < 32; i += 8) t[y+i][x] = in[(long)(r0+y+i)*ldin + c0 + x];
    __syncthreads();
    #pragma unroll
    for (int i = 0; i < 32; i += 8)
        out[(long)(c0+y+i)*ldout + r0 + x] = __float2half(t[x][y+i]);
}

// ---------------- fp32 -> half convert ----------------
__global__ void f2h_kernel(const float* __restrict__ in, __half* __restrict__ out, int n4)
{
    int i = blockIdx.x*blockDim.x + threadIdx.x;
    if (i < n4) {
        float4 v = ((const float4*)in)[i];
        ((uint32_t*)out)[2*i    ] = f2h2(v.x, v.y);
        ((uint32_t*)out)[2*i + 1] = f2h2(v.z, v.w);
    }
}

// ---------------- fused residual add + LayerNorm (fp32 out + optional half out)
__global__ void __launch_bounds__(256) add_ln(
    const float* __restrict__ x, const float* __restrict__ a,
    const float* __restrict__ g, const float* __restrict__ b,
    float* __restrict__ y, __half* __restrict__ yh)
{
    __shared__ float red[8];
    __shared__ float bc;
    long row = blockIdx.x;
    const float* xr = x + row * DIM;
    const float* ar = a + row * DIM;
    float* yr = y + row * DIM;
    int tid = threadIdx.x, lane = tid & 31, wid = tid >> 5;

    float v[4], s = 0.f;
    #pragma unroll
    for (int i = 0; i < 4; i++) { int c = tid + i*256; v[i] = xr[c] + ar[c]; s += v[i]; }
    #pragma unroll
    for (int o = 16; o > 0; o >>= 1) s += __shfl_xor_sync(0xffffffffu, s, o);
    if (lane == 0) red[wid] = s;
    __syncthreads();
    if (tid == 0) {
        float t = 0.f;
        #pragma unroll
        for (int i = 0; i < 8; i++) t += red[i];
        bc = t * (1.0f / DIM);
    }
    __syncthreads();
    float mu = bc;

    float q = 0.f;
    #pragma unroll
    for (int i = 0; i < 4; i++) { float d = v[i] - mu; q += d * d; }
    #pragma unroll
    for (int o = 16; o > 0; o >>= 1) q += __shfl_xor_sync(0xffffffffu, q, o);
    __syncthreads();
    if (lane == 0) red[wid] = q;
    __syncthreads();
    if (tid == 0) {
        float t = 0.f;
        #pragma unroll
        for (int i = 0; i < 8; i++) t += red[i];
        bc = rsqrtf(t * (1.0f / DIM) + 1e-5f);
    }
    __syncthreads();
    float inv = bc;
    #pragma unroll
    for (int i = 0; i < 4; i++) {
        int c = tid + i*256;
        float o = (v[i] - mu) * inv * g[c] + b[c];
        yr[c] = o;
        if (yh) yh[row*DIM + c] = __float2half(o);
    }
}

// ---------------- host orchestration ----------------
extern "C" void kernel_launch(void* const* d_in, const int* in_sizes, int n_in,
                              void* d_out, int out_size)
{
    const float* x            = (const float*)d_in[0];
    const float* ctx          = (const float*)d_in[1];
    const float* c_attn_w     = (const float*)d_in[2];
    const float* c_attn_b     = (const float*)d_in[3];
    const float* self_proj_w  = (const float*)d_in[4];
    const float* self_proj_b  = (const float*)d_in[5];
    const float* q_w          = (const float*)d_in[6];
    const float* q_b          = (const float*)d_in[7];
    const float* kv_w         = (const float*)d_in[8];
    const float* kv_b         = (const float*)d_in[9];
    const float* cross_proj_w = (const float*)d_in[10];
    const float* cross_proj_b = (const float*)d_in[11];
    const float* fc_w         = (const float*)d_in[12];
    const float* fc_b         = (const float*)d_in[13];
    const float* mlp_proj_w   = (const float*)d_in[14];
    const float* mlp_proj_b   = (const float*)d_in[15];
    const float* ln1_g        = (const float*)d_in[16];
    const float* ln1_b        = (const float*)d_in[17];
    const float* ln2_g        = (const float*)d_in[18];
    const float* ln2_b        = (const float*)d_in[19];
    const float* ln3_g        = (const float*)d_in[20];
    const float* ln3_b        = (const float*)d_in[21];
    float* out = (float*)d_out;

    float *t, *x1, *x2;
    __half *qkvh, *abufh, *xh, *ctxh, *x1h, *x2h, *qh, *kvh, *hh, *wth;
    cudaGetSymbolAddress((void**)&t,     g_t);
    cudaGetSymbolAddress((void**)&x1,    g_x1);
    cudaGetSymbolAddress((void**)&x2,    g_x2);
    cudaGetSymbolAddress((void**)&qkvh,  g_qkvh);
    cudaGetSymbolAddress((void**)&abufh, g_abufh);
    cudaGetSymbolAddress((void**)&xh,    g_xh);
    cudaGetSymbolAddress((void**)&ctxh,  g_ctxh);
    cudaGetSymbolAddress((void**)&x1h,   g_x1h);
    cudaGetSymbolAddress((void**)&x2h,   g_x2h);
    cudaGetSymbolAddress((void**)&qh,    g_qh);
    cudaGetSymbolAddress((void**)&kvh,   g_kvh);
    cudaGetSymbolAddress((void**)&hh,    g_hh);
    cudaGetSymbolAddress((void**)&wth,   g_wth);

    __half* cattnT = wth;                        // [3072,1024]
    __half* selfT  = wth +  3l*1024*1024;
    __half* qT     = wth +  4l*1024*1024;
    __half* kvT    = wth +  5l*1024*1024;        // [2048,1024]
    __half* crossT = wth +  7l*1024*1024;
    __half* fcT    = wth +  8l*1024*1024;        // [4096,1024]
    __half* mlpT   = wth + 12l*1024*1024;        // [1024,4096]

    const int SMG = (128*40 + 128*40) * 2 * 2;          // 40960 B
    const int SMF = (128*72 + 2*(64*72 + 64*72)) * 2;   // 55296 B
    cudaFuncSetAttribute(flash_attn, cudaFuncAttributeMaxDynamicSharedMemorySize, SMF);

    const int M = NB * SEQ;                  // 4096
    dim3 tb(32, 8);

    // ---- input converts + weight transposes (fp32 -> half) ----
    f2h_kernel<<<4096, 256>>>(x,   xh,   M*DIM/4);
    f2h_kernel<<<4096, 256>>>(ctx, ctxh, M*DIM/4);
    transpose_h<<<dim3( 96, 32), tb>>>(c_attn_w,     cattnT, 3*DIM, DIM);
    transpose_h<<<dim3( 32, 32), tb>>>(self_proj_w,  selfT,  DIM,   DIM);
    transpose_h<<<dim3( 32, 32), tb>>>(q_w,          qT,     DIM,   DIM);
    transpose_h<<<dim3( 64, 32), tb>>>(kv_w,         kvT,    2*DIM, DIM);
    transpose_h<<<dim3( 32, 32), tb>>>(cross_proj_w, crossT, DIM,   DIM);
    transpose_h<<<dim3(128, 32), tb>>>(fc_w,         fcT,    4*DIM, DIM);
    transpose_h<<<dim3( 32,128), tb>>>(mlp_proj_w,   mlpT,   DIM,   4*DIM);

    // 1. qkv = x @ c_attn_w + b   (half out)
    gemm_mma<EPI_BIAS, true><<<dim3(24, 32), 256, SMG>>>(
        xh, cattnT, c_attn_b, nullptr, qkvh, DIM, DIM, DIM, 3*DIM);

    // 2-4. fused causal self-attention -> abufh
    flash_attn<<<dim3(8, NB*NHEAD), 256, SMF>>>(
        qkvh, qkvh + DIM, qkvh + 2*DIM, abufh, 3*DIM, 3*DIM, 1);

    // 5. t = a @ self_proj_w + b  (fp32 out)
    gemm_mma<EPI_BIAS, false><<<dim3(8, 32), 256, SMG>>>(
        abufh, selfT, self_proj_b, t, nullptr, DIM, DIM, DIM, DIM);

    // 6. x1 = LN(x + t)  (+ half copy)
    add_ln<<<M, 256>>>(x, t, ln1_g, ln1_b, x1, x1h);

    // 7. q = x1 @ q_w + b  (half out)
    gemm_mma<EPI_BIAS, true><<<dim3(8, 32), 256, SMG>>>(
        x1h, qT, q_b, nullptr, qh, DIM, DIM, DIM, DIM);

    // 8. kv = ctx @ kv_w + b  (half out)
    gemm_mma<EPI_BIAS, true><<<dim3(16, 32), 256, SMG>>>(
        ctxh, kvT, kv_b, nullptr, kvh, DIM, DIM, DIM, 2*DIM);

    // 9-11. fused cross-attention -> abufh
    flash_attn<<<dim3(8, NB*NHEAD), 256, SMF>>>(
        qh, kvh, kvh + DIM, abufh, DIM, 2*DIM, 0);

    // 12. t = a @ cross_proj_w + b  (fp32 out)
    gemm_mma<EPI_BIAS, false><<<dim3(8, 32), 256, SMG>>>(
        abufh, crossT, cross_proj_b, t, nullptr, DIM, DIM, DIM, DIM);

    // 13. x2 = LN(x1 + t)  (+ half copy)
    add_ln<<<M, 256>>>(x1, t, ln2_g, ln2_b, x2, x2h);

    // 14. h = gelu(x2 @ fc_w + b)  (half out)
    gemm_mma<EPI_BIAS_GELU, true><<<dim3(32, 32), 256, SMG>>>(
        x2h, fcT, fc_b, nullptr, hh, DIM, DIM, DIM, 4*DIM);

    // 15. t = h @ mlp_proj_w + b  (fp32 out)
    gemm_mma<EPI_BIAS, false><<<dim3(8, 32), 256, SMG>>>(
        hh, mlpT, mlp_proj_b, t, nullptr, 4*DIM, 4*DIM, 4*DIM, DIM);

    // 16. out = LN(x2 + t)
    add_ln<<<M, 256>>>(x2, t, ln3_g, ln3_b, out, nullptr);
}

// round 10
// speedup vs baseline: 6.5326x; 1.0032x over previous
#include <cuda_runtime.h>
#include <cuda_fp16.h>
#include <math.h>
#include <stdint.h>

#define SEQ 1024
#define DIM 1024
#define NB  4
#define NHEAD 16
#define HD  64

enum { EPI_BIAS=1, EPI_BIAS_GELU=2 };

// ---------------- scratch (no allocations allowed) ----------------
__device__ float  g_t [(size_t)NB*SEQ*DIM];
__device__ float  g_x1[(size_t)NB*SEQ*DIM];
__device__ float  g_x2[(size_t)NB*SEQ*DIM];
__device__ __half g_qkvh[(size_t)NB*SEQ*3*DIM];
__device__ __half g_abufh[(size_t)NB*SEQ*DIM];
__device__ __half g_xh [(size_t)NB*SEQ*DIM];
__device__ __half g_ctxh[(size_t)NB*SEQ*DIM];
__device__ __half g_x1h[(size_t)NB*SEQ*DIM];
__device__ __half g_x2h[(size_t)NB*SEQ*DIM];
__device__ __half g_qh [(size_t)NB*SEQ*DIM];
__device__ __half g_kvh[(size_t)NB*SEQ*2*DIM];
__device__ __half g_hh [(size_t)NB*SEQ*4*DIM];
__device__ __half g_wth[(size_t)16*1024*1024];   // 32MB transposed half weights

__device__ __forceinline__ float gelu_tanh(float v){
    float u = 0.7978845608028654f * (v + 0.044715f * v * v * v);
    return 0.5f * v * (1.0f + tanhf(u));
}

#define CP_ASYNC16(s, g)  asm volatile("cp.async.cg.shared.global [%0], [%1], 16;" :: "r"(s), "l"(__cvta_generic_to_global(g)))
#define CP_COMMIT()       asm volatile("cp.async.commit_group;")
#define CP_WAIT(n)        asm volatile("cp.async.wait_group %0;" :: "n"(n))

#define LDSM_X4(r0,r1,r2,r3,addr) \
    asm volatile("ldmatrix.sync.aligned.m8n8.x4.shared.b16 {%0,%1,%2,%3}, [%4];" \
                 : "=r"(r0),"=r"(r1),"=r"(r2),"=r"(r3) : "r"(addr))
#define LDSM_X4T(r0,r1,r2,r3,addr) \
    asm volatile("ldmatrix.sync.aligned.m8n8.x4.trans.shared.b16 {%0,%1,%2,%3}, [%4];" \
                 : "=r"(r0),"=r"(r1),"=r"(r2),"=r"(r3) : "r"(addr))

__device__ __forceinline__ uint32_t smem_u32(const void* p) {
    uint32_t a;
    asm("{ .reg .u64 t; cvta.to.shared.u64 t, %1; cvt.u32.u64 %0, t; }" : "=r"(a) : "l"(p));
    return a;
}
__device__ __forceinline__ uint32_t f2h2(float lo, float hi) {
    uint32_t r;
    asm("cvt.rn.f16x2.f32 %0, %1, %2;" : "=r"(r) : "f"(hi), "f"(lo));
    return r;
}
__device__ __forceinline__ void mma_f16(float* d, const uint32_t* a, const uint32_t* b) {
    asm volatile(
        "mma.sync.aligned.m16n8k16.row.col.f32.f16.f16.f32 "
        "{%0,%1,%2,%3}, {%4,%5,%6,%7}, {%8,%9}, {%0,%1,%2,%3};"
        : "+f"(d[0]), "+f"(d[1]), "+f"(d[2]), "+f"(d[3])
        : "r"(a[0]), "r"(a[1]), "r"(a[2]), "r"(a[3]), "r"(b[0]), "r"(b[1]));
}

// ---------------- fp16 ldmatrix GEMM, 3-stage pipeline, 1 sync/iter ----------
// C[M,N] = epi( A[M,K] * B^T )  A:[M,K] half K-major, B:[N,K] half K-major.
// Tile 128x128, BK=32. 8 warps 2x4; warp tile 64x32.
template<int EPI, bool OUTH>
__global__ void __launch_bounds__(256, 2) gemm_mma(
    const __half* __restrict__ A, const __half* __restrict__ B,
    const float* __restrict__ bias, float* __restrict__ C, __half* __restrict__ Ch,
    int K, int lda, int ldb, int ldc)
{
    constexpr int BM = 128, BN = 128, BK = 32;
    constexpr int AST = 40;                 // halves per smem row (32 + 8 pad)
    constexpr int SA = BM * AST, SB = BN * AST, STG = SA + SB;  // halves

    extern __shared__ __half smh[];
    const uint32_t sbase = smem_u32(smh);

    const int tid = threadIdx.x;
    const int row0 = blockIdx.y * BM;
    const int col0 = blockIdx.x * BN;
    const int wid = tid >> 5, lane = tid & 31;
    const int g = lane >> 2, tg = lane & 3;
    const int wm = (wid & 1) * 64;
    const int wn = (wid >> 1) * 32;

    float acc[4][4][4];
    #pragma unroll
    for (int mt = 0; mt < 4; mt++)
        #pragma unroll
        for (int nt = 0; nt < 4; nt++)
            #pragma unroll
            for (int i = 0; i < 4; i++) acc[mt][nt][i] = 0.f;

    auto load_stage = [&](int step) {
        int st = step % 3;
        long k0 = (long)step * BK;
        uint32_t as = sbase + (uint32_t)(st*STG)*2u;
        uint32_t bs = as + (uint32_t)SA*2u;
        #pragma unroll
        for (int i = 0; i < 2; i++) {
            int c = tid + i*256;
            int r = c >> 2, kc = c & 3;
            CP_ASYNC16(as + (uint32_t)(r*AST + kc*8)*2,
                       A + (long)(row0 + r)*lda + k0 + kc*8);
        }
        #pragma unroll
        for (int i = 0; i < 2; i++) {
            int c = tid + i*256;
            int r = c >> 2, kc = c & 3;
            CP_ASYNC16(bs + (uint32_t)(r*AST + kc*8)*2,
                       B + (long)(col0 + r)*ldb + k0 + kc*8);
        }
        CP_COMMIT();
    };

    const int nsteps = K / BK;
    load_stage(0);
    load_stage(1);

    const int a_r = lane & 15, a_c8 = (lane >> 4) << 3;
    const int b_r = ((lane >> 4) << 3) + (lane & 7);
    const int b_c8 = ((lane >> 3) & 1) << 3;

    for (int i = 0; i < nsteps; i++) {
        if (i + 1 < nsteps) { CP_WAIT(1); } else { CP_WAIT(0); }
        __syncthreads();                 // single barrier per iteration
        if (i + 2 < nsteps) load_stage(i + 2);

        uint32_t as = sbase + (uint32_t)((i % 3)*STG)*2u;
        uint32_t bs = as + (uint32_t)SA*2u;

        #pragma unroll
        for (int kb = 0; kb < 2; kb++) {
            int kk = kb * 16;
            uint32_t af[4][4], bf[4][2];
            #pragma unroll
            for (int mt = 0; mt < 4; mt++) {
                uint32_t ad = as + (uint32_t)((wm + mt*16 + a_r)*AST + kk + a_c8)*2;
                LDSM_X4(af[mt][0], af[mt][1], af[mt][2], af[mt][3], ad);
            }
            #pragma unroll
            for (int p = 0; p < 2; p++) {
                uint32_t bd = bs + (uint32_t)((wn + p*16 + b_r)*AST + kk + b_c8)*2;
                LDSM_X4(bf[2*p][0], bf[2*p][1], bf[2*p+1][0], bf[2*p+1][1], bd);
            }
            #pragma unroll
            for (int mt = 0; mt < 4; mt++)
                #pragma unroll
                for (int nt = 0; nt < 4; nt++)
                    mma_f16(acc[mt][nt], af[mt], bf[nt]);
        }
    }

    #pragma unroll
    for (int mt = 0; mt < 4; mt++) {
        #pragma unroll
        for (int nt = 0; nt < 4; nt++) {
            int Rg = row0 + wm + mt*16 + g;
            int cg = col0 + wn + nt*8 + 2*tg;
            #pragma unroll
            for (int half_i = 0; half_i < 2; half_i++) {
                int r = Rg + half_i*8;
                float v0 = acc[mt][nt][half_i*2 + 0] + bias[cg];
                float v1 = acc[mt][nt][half_i*2 + 1] + bias[cg+1];
                if (EPI == EPI_BIAS_GELU) { v0 = gelu_tanh(v0); v1 = gelu_tanh(v1); }
                if (OUTH) {
                    *(uint32_t*)&Ch[(long)r*ldc + cg] = f2h2(v0, v1);
                } else {
                    *(float2*)&C[(long)r*ldc + cg] = make_float2(v0, v1);
                }
            }
        }
    }
}

// ---------------- fused flash attention, 3-stage KV pipeline, 1 sync/tile ----
__global__ void __launch_bounds__(256, 1) flash_attn(
    const __half* __restrict__ Q, const __half* __restrict__ K,
    const __half* __restrict__ V, __half* __restrict__ O,
    int ldq, int ldkv, int causal)
{
    constexpr int ST = 72;                  // halves per row (64 + 8)
    constexpr int QSZ = 128*ST;             // halves
    constexpr int KVSZ = 64*ST;
    constexpr int STGH = 2*KVSZ;            // K + V per stage
    extern __shared__ __half smh[];
    const uint32_t sbase = smem_u32(smh);

    const int tid = threadIdx.x;
    const int wid = tid >> 5, lane = tid & 31;
    const int g = lane >> 2, tg = lane & 3;
    const int qt = blockIdx.x;
    const int bh = blockIdx.y, bb = bh >> 4, hh = bh & 15;
    const int wm = wid * 16;

    const __half* Qb = Q + (long)bb*SEQ*ldq  + hh*64 + (long)qt*128*ldq;
    const __half* Kb = K + (long)bb*SEQ*ldkv + hh*64;
    const __half* Vb = V + (long)bb*SEQ*ldkv + hh*64;
    __half*       Ob = O + (long)bb*SEQ*DIM  + hh*64 + (long)qt*128*DIM;

    // ---- stage Q ----
    #pragma unroll
    for (int i = 0; i < 4; i++) {
        int c = tid + i*256;
        int r = c >> 3, kc = c & 7;
        CP_ASYNC16(sbase + (uint32_t)(r*ST + kc*8)*2, Qb + (long)r*ldq + kc*8);
    }
    CP_COMMIT(); CP_WAIT(0);
    __syncthreads();

    const int a_r = lane & 15, a_c8 = (lane >> 4) << 3;
    const int b_r = ((lane >> 4) << 3) + (lane & 7);
    const int b_c8 = ((lane >> 3) & 1) << 3;
    const int v_r = (((lane >> 3) & 1) << 3) + (lane & 7);
    const int v_c8 = (lane >> 4) << 3;

    uint32_t aq[4][4];
    #pragma unroll
    for (int kt = 0; kt < 4; kt++) {
        uint32_t ad = sbase + (uint32_t)((wm + a_r)*ST + kt*16 + a_c8)*2;
        LDSM_X4(aq[kt][0], aq[kt][1], aq[kt][2], aq[kt][3], ad);
    }
    __syncthreads();

    float acc_o[8][4];
    #pragma unroll
    for (int nt = 0; nt < 8; nt++)
        #pragma unroll
        for (int i = 0; i < 4; i++) acc_o[nt][i] = 0.f;
    float m0 = -1e30f, m1 = -1e30f, l0 = 0.f, l1 = 0.f;

    const int ntiles = causal ? (2*qt + 2) : (SEQ/64);
    const int rowg0 = qt*128 + wm + g;
    const int rowg1 = rowg0 + 8;

    auto load_kv = [&](int j) {
        uint32_t st = sbase + (uint32_t)(QSZ + (j % 3)*STGH)*2u;
        const __half* Kg = Kb + (long)j*64*ldkv;
        const __half* Vg = Vb + (long)j*64*ldkv;
        #pragma unroll
        for (int i = 0; i < 2; i++) {
            int c = tid + i*256;
            int r = c >> 3, kc = c & 7;
            CP_ASYNC16(st + (uint32_t)(r*ST + kc*8)*2, Kg + (long)r*ldkv + kc*8);
        }
        uint32_t vs = st + (uint32_t)KVSZ*2u;
        #pragma unroll
        for (int i = 0; i < 2; i++) {
            int c = tid + i*256;
            int r = c >> 3, kc = c & 7;
            CP_ASYNC16(vs + (uint32_t)(r*ST + kc*8)*2, Vg + (long)r*ldkv + kc*8);
        }
        CP_COMMIT();
    };

    load_kv(0);
    if (ntiles > 1) load_kv(1);

    for (int j = 0; j < ntiles; j++) {
        if (j + 1 < ntiles) { CP_WAIT(1); } else { CP_WAIT(0); }
        __syncthreads();                 // single barrier per tile
        if (j + 2 < ntiles) load_kv(j + 2);

        uint32_t ks = sbase + (uint32_t)(QSZ + (j % 3)*STGH)*2u;
        uint32_t vs = ks + (uint32_t)KVSZ*2u;

        // ---- S = Q K^T (unscaled) ----
        float s[8][4];
        #pragma unroll
        for (int nt = 0; nt < 8; nt++)
            #pragma unroll
            for (int i = 0; i < 4; i++) s[nt][i] = 0.f;

        #pragma unroll
        for (int kt = 0; kt < 4; kt++) {
            int kk = kt*16;
            #pragma unroll
            for (int p = 0; p < 4; p++) {
                uint32_t bf[2][2];
                uint32_t bd = ks + (uint32_t)((p*16 + b_r)*ST + kk + b_c8)*2;
                LDSM_X4(bf[0][0], bf[0][1], bf[1][0], bf[1][1], bd);
                mma_f16(s[2*p  ], aq[kt], bf[0]);
                mma_f16(s[2*p+1], aq[kt], bf[1]);
            }
        }

        // ---- scale + causal mask ----
        #pragma unroll
        for (int nt = 0; nt < 8; nt++)
            #pragma unroll
            for (int i = 0; i < 4; i++) s[nt][i] *= 0.125f;

        if (causal && j >= 2*qt) {
            int kbase = j*64;
            #pragma unroll
            for (int nt = 0; nt < 8; nt++) {
                int kg = kbase + nt*8 + 2*tg;
                if (kg     > rowg0) s[nt][0] = -1e30f;
                if (kg + 1 > rowg0) s[nt][1] = -1e30f;
                if (kg     > rowg1) s[nt][2] = -1e30f;
                if (kg + 1 > rowg1) s[nt][3] = -1e30f;
            }
        }

        // ---- online softmax ----
        float tm0 = -1e30f, tm1 = -1e30f;
        #pragma unroll
        for (int nt = 0; nt < 8; nt++) {
            tm0 = fmaxf(tm0, fmaxf(s[nt][0], s[nt][1]));
            tm1 = fmaxf(tm1, fmaxf(s[nt][2], s[nt][3]));
        }
        tm0 = fmaxf(tm0, __shfl_xor_sync(0xffffffffu, tm0, 1));
        tm0 = fmaxf(tm0, __shfl_xor_sync(0xffffffffu, tm0, 2));
        tm1 = fmaxf(tm1, __shfl_xor_sync(0xffffffffu, tm1, 1));
        tm1 = fmaxf(tm1, __shfl_xor_sync(0xffffffffu, tm1, 2));

        float mn0 = fmaxf(m0, tm0), mn1 = fmaxf(m1, tm1);
        float al0 = __expf(m0 - mn0), al1 = __expf(m1 - mn1);
        float ts0 = 0.f, ts1 = 0.f;
        #pragma unroll
        for (int nt = 0; nt < 8; nt++) {
            s[nt][0] = __expf(s[nt][0] - mn0);
            s[nt][1] = __expf(s[nt][1] - mn0);
            s[nt][2] = __expf(s[nt][2] - mn1);
            s[nt][3] = __expf(s[nt][3] - mn1);
            ts0 += s[nt][0] + s[nt][1];
            ts1 += s[nt][2] + s[nt][3];
        }
        ts0 += __shfl_xor_sync(0xffffffffu, ts0, 1);
        ts0 += __shfl_xor_sync(0xffffffffu, ts0, 2);
        ts1 += __shfl_xor_sync(0xffffffffu, ts1, 1);
        ts1 += __shfl_xor_sync(0xffffffffu, ts1, 2);

        l0 = l0*al0 + ts0;  l1 = l1*al1 + ts1;
        m0 = mn0;  m1 = mn1;

        #pragma unroll
        for (int nt = 0; nt < 8; nt++) {
            acc_o[nt][0] *= al0;  acc_o[nt][1] *= al0;
            acc_o[nt][2] *= al1;  acc_o[nt][3] *= al1;
        }

        // ---- O += P V ----
        #pragma unroll
        for (int kt = 0; kt < 4; kt++) {
            uint32_t ap[4];
            ap[0] = f2h2(s[2*kt  ][0], s[2*kt  ][1]);
            ap[1] = f2h2(s[2*kt  ][2], s[2*kt  ][3]);
            ap[2] = f2h2(s[2*kt+1][0], s[2*kt+1][1]);
            ap[3] = f2h2(s[2*kt+1][2], s[2*kt+1][3]);
            #pragma unroll
            for (int p = 0; p < 4; p++) {
                uint32_t bv[2][2];
                uint32_t vd = vs + (uint32_t)((kt*16 + v_r)*ST + p*16 + v_c8)*2;
                LDSM_X4T(bv[0][0], bv[0][1], bv[1][0], bv[1][1], vd);
                mma_f16(acc_o[2*p  ], ap, bv[0]);
                mma_f16(acc_o[2*p+1], ap, bv[1]);
            }
        }
    }

    // ---- normalize + store half ----
    float r0 = 1.f / l0, r1 = 1.f / l1;
    #pragma unroll
    for (int nt = 0; nt < 8; nt++) {
        int c = nt*8 + 2*tg;
        *(uint32_t*)&Ob[(long)(wm+g  )*DIM + c] = f2h2(acc_o[nt][0]*r0, acc_o[nt][1]*r0);
        *(uint32_t*)&Ob[(long)(wm+g+8)*DIM + c] = f2h2(acc_o[nt][2]*r1, acc_o[nt][3]*r1);
    }
}

// ---------------- merged weight transposes (7 segments, flat grid) ----------
// segment s: transpose in[rows x cols] (ld=cols) -> out[cols x rows] as half
__global__ void prep_weights(
    const float* w0, const float* w1, const float* w2, const float* w3,
    const float* w4, const float* w5, const float* w6,
    __half* o0, __half* o1, __half* o2, __half* o3,
    __half* o4, __half* o5, __half* o6)
{
    // tiles-x (cols/32), tiles-y (rows/32) per segment; offsets cumulative
    const int gx[7]  = {96, 32, 32, 64, 32, 128, 32};
    const int off[8] = {0, 3072, 4096, 5120, 7168, 8192, 12288, 16384};
    const int ldi[7] = {3072, 1024, 1024, 2048, 1024, 4096, 1024};
    const int ldo[7] = {1024, 1024, 1024, 1024, 1024, 1024, 4096};

    int bid = blockIdx.x;
    int seg = 0;
    #pragma unroll
    for (int s = 1; s < 7; s++) if (bid >= off[s]) seg = s;
    int lt = bid - off[seg];
    int bx = lt % gx[seg], by = lt / gx[seg];

    const float* in  = (seg==0)?w0:(seg==1)?w1:(seg==2)?w2:(seg==3)?w3:(seg==4)?w4:(seg==5)?w5:w6;
    __half*      out = (seg==0)?o0:(seg==1)?o1:(seg==2)?o2:(seg==3)?o3:(seg==4)?o4:(seg==5)?o5:o6;
    int ldin = ldi[seg], ldout = ldo[seg];

    __shared__ float t[32][33];
    int r0 = by*32, c0 = bx*32;
    int x = threadIdx.x, y = threadIdx.y;
    #pragma unroll
    for (int i = 0; i < 32; i += 8) t[y+i][x] = in[(long)(r0+y+i)*ldin + c0 + x];
    __syncthreads();
    #pragma unroll
    for (int i = 0; i < 32; i += 8)
        out[(long)(c0+y+i)*ldout + r0 + x] = __float2half(t[x][y+i]);
}

// ---------------- merged fp32 -> half convert (x and ctx) ----------------
__global__ void f2h_dual(const float* __restrict__ a, __half* __restrict__ ah,
                         const float* __restrict__ b, __half* __restrict__ bh, int n4)
{
    int i = blockIdx.x*blockDim.x + threadIdx.x;
    const float* in; __half* out;
    if (i < n4) { in = a; out = ah; }
    else        { in = b; out = bh; i -= n4; if (i >= n4) return; }
    float4 v = ((const float4*)in)[i];
    ((uint32_t*)out)[2*i    ] = f2h2(v.x, v.y);
    ((uint32_t*)out)[2*i + 1] = f2h2(v.z, v.w);
}

// ---------------- fused residual add + LayerNorm ----------------
__global__ void __launch_bounds__(256) add_ln(
    const float* __restrict__ x, const float* __restrict__ a,
    const float* __restrict__ g, const float* __restrict__ b,
    float* __restrict__ y, __half* __restrict__ yh)
{
    __shared__ float red[8];
    __shared__ float bc;
    long row = blockIdx.x;
    const float* xr = x + row * DIM;
    const float* ar = a + row * DIM;
    float* yr = y + row * DIM;
    int tid = threadIdx.x, lane = tid & 31, wid = tid >> 5;

    float v[4], s = 0.f;
    #pragma unroll
    for (int i = 0; i < 4; i++) { int c = tid + i*256; v[i] = xr[c] + ar[c]; s += v[i]; }
    #pragma unroll
    for (int o = 16; o > 0; o >>= 1) s += __shfl_xor_sync(0xffffffffu, s, o);
    if (lane == 0) red[wid] = s;
    __syncthreads();
    if (tid == 0) {
        float t = 0.f;
        #pragma unroll
        for (int i = 0; i < 8; i++) t += red[i];
        bc = t * (1.0f / DIM);
    }
    __syncthreads();
    float mu = bc;

    float q = 0.f;
    #pragma unroll
    for (int i = 0; i < 4; i++) { float d = v[i] - mu; q += d * d; }
    #pragma unroll
    for (int o = 16; o > 0; o >>= 1) q += __shfl_xor_sync(0xffffffffu, q, o);
    __syncthreads();
    if (lane == 0) red[wid] = q;
    __syncthreads();
    if (tid == 0) {
        float t = 0.f;
        #pragma unroll
        for (int i = 0; i < 8; i++) t += red[i];
        bc = rsqrtf(t * (1.0f / DIM) + 1e-5f);
    }
    __syncthreads();
    float inv = bc;
    #pragma unroll
    for (int i = 0; i < 4; i++) {
        int c = tid + i*256;
        float o = (v[i] - mu) * inv * g[c] + b[c];
        yr[c] = o;
        if (yh) yh[row*DIM + c] = __float2half(o);
    }
}

// ---------------- host orchestration ----------------
extern "C" void kernel_launch(void* const* d_in, const int* in_sizes, int n_in,
                              void* d_out, int out_size)
{
    const float* x            = (const float*)d_in[0];
    const float* ctx          = (const float*)d_in[1];
    const float* c_attn_w     = (const float*)d_in[2];
    const float* c_attn_b     = (const float*)d_in[3];
    const float* self_proj_w  = (const float*)d_in[4];
    const float* self_proj_b  = (const float*)d_in[5];
    const float* q_w          = (const float*)d_in[6];
    const float* q_b          = (const float*)d_in[7];
    const float* kv_w         = (const float*)d_in[8];
    const float* kv_b         = (const float*)d_in[9];
    const float* cross_proj_w = (const float*)d_in[10];
    const float* cross_proj_b = (const float*)d_in[11];
    const float* fc_w         = (const float*)d_in[12];
    const float* fc_b         = (const float*)d_in[13];
    const float* mlp_proj_w   = (const float*)d_in[14];
    const float* mlp_proj_b   = (const float*)d_in[15];
    const float* ln1_g        = (const float*)d_in[16];
    const float* ln1_b        = (const float*)d_in[17];
    const float* ln2_g        = (const float*)d_in[18];
    const float* ln2_b        = (const float*)d_in[19];
    const float* ln3_g        = (const float*)d_in[20];
    const float* ln3_b        = (const float*)d_in[21];
    float* out = (float*)d_out;

    float *t, *x1, *x2;
    __half *qkvh, *abufh, *xh, *ctxh, *x1h, *x2h, *qh, *kvh, *hh, *wth;
    cudaGetSymbolAddress((void**)&t,     g_t);
    cudaGetSymbolAddress((void**)&x1,    g_x1);
    cudaGetSymbolAddress((void**)&x2,    g_x2);
    cudaGetSymbolAddress((void**)&qkvh,  g_qkvh);
    cudaGetSymbolAddress((void**)&abufh, g_abufh);
    cudaGetSymbolAddress((void**)&xh,    g_xh);
    cudaGetSymbolAddress((void**)&ctxh,  g_ctxh);
    cudaGetSymbolAddress((void**)&x1h,   g_x1h);
    cudaGetSymbolAddress((void**)&x2h,   g_x2h);
    cudaGetSymbolAddress((void**)&qh,    g_qh);
    cudaGetSymbolAddress((void**)&kvh,   g_kvh);
    cudaGetSymbolAddress((void**)&hh,    g_hh);
    cudaGetSymbolAddress((void**)&wth,   g_wth);

    __half* cattnT = wth;                        // [3072,1024]
    __half* selfT  = wth +  3l*1024*1024;
    __half* qT     = wth +  4l*1024*1024;
    __half* kvT    = wth +  5l*1024*1024;        // [2048,1024]
    __half* crossT = wth +  7l*1024*1024;
    __half* fcT    = wth +  8l*1024*1024;        // [4096,1024]
    __half* mlpT   = wth + 12l*1024*1024;        // [1024,4096]

    const int SMG = (128*40 + 128*40) * 3 * 2;          // 61440 B (3 stages)
    const int SMF = (128*72 + 3*(64*72 + 64*72)) * 2;   // 73728 B (Q + 3 stages)
    cudaFuncSetAttribute(gemm_mma<EPI_BIAS, true>,      cudaFuncAttributeMaxDynamicSharedMemorySize, SMG);
    cudaFuncSetAttribute(gemm_mma<EPI_BIAS, false>,     cudaFuncAttributeMaxDynamicSharedMemorySize, SMG);
    cudaFuncSetAttribute(gemm_mma<EPI_BIAS_GELU, true>, cudaFuncAttributeMaxDynamicSharedMemorySize, SMG);
    cudaFuncSetAttribute(flash_attn, cudaFuncAttributeMaxDynamicSharedMemorySize, SMF);

    const int M = NB * SEQ;                  // 4096

    // ---- merged prologue: input converts + all weight transposes ----
    f2h_dual<<<8192, 256>>>(x, xh, ctx, ctxh, M*DIM/4);
    prep_weights<<<16384, dim3(32, 8)>>>(
        c_attn_w, self_proj_w, q_w, kv_w, cross_proj_w, fc_w, mlp_proj_w,
        cattnT, selfT, qT, kvT, crossT, fcT, mlpT);

    // 1. qkv = x @ c_attn_w + b   (half out)
    gemm_mma<EPI_BIAS, true><<<dim3(24, 32), 256, SMG>>>(
        xh, cattnT, c_attn_b, nullptr, qkvh, DIM, DIM, DIM, 3*DIM);

    // 2-4. fused causal self-attention -> abufh
    flash_attn<<<dim3(8, NB*NHEAD), 256, SMF>>>(
        qkvh, qkvh + DIM, qkvh + 2*DIM, abufh, 3*DIM, 3*DIM, 1);

    // 5. t = a @ self_proj_w + b  (fp32 out)
    gemm_mma<EPI_BIAS, false><<<dim3(8, 32), 256, SMG>>>(
        abufh, selfT, self_proj_b, t, nullptr, DIM, DIM, DIM, DIM);

    // 6. x1 = LN(x + t)  (+ half copy)
    add_ln<<<M, 256>>>(x, t, ln1_g, ln1_b, x1, x1h);

    // 7. q = x1 @ q_w + b  (half out)
    gemm_mma<EPI_BIAS, true><<<dim3(8, 32), 256, SMG>>>(
        x1h, qT, q_b, nullptr, qh, DIM, DIM, DIM, DIM);

    // 8. kv = ctx @ kv_w + b  (half out)
    gemm_mma<EPI_BIAS, true><<<dim3(16, 32), 256, SMG>>>(
        ctxh, kvT, kv_b, nullptr, kvh, DIM, DIM, DIM, 2*DIM);

    // 9-11. fused cross-attention -> abufh
    flash_attn<<<dim3(8, NB*NHEAD), 256, SMF>>>(
        qh, kvh, kvh + DIM, abufh, DIM, 2*DIM, 0);

    // 12. t = a @ cross_proj_w + b  (fp32 out)
    gemm_mma<EPI_BIAS, false><<<dim3(8, 32), 256, SMG>>>(
        abufh, crossT, cross_proj_b, t, nullptr, DIM, DIM, DIM, DIM);

    // 13. x2 = LN(x1 + t)  (+ half copy)
    add_ln<<<M, 256>>>(x1, t, ln2_g, ln2_b, x2, x2h);

    // 14. h = gelu(x2 @ fc_w + b)  (half out)
    gemm_mma<EPI_BIAS_GELU, true><<<dim3(32, 32), 256, SMG>>>(
        x2h, fcT, fc_b, nullptr, hh, DIM, DIM, DIM, 4*DIM);

    // 15. t = h @ mlp_proj_w + b  (fp32 out)
    gemm_mma<EPI_BIAS, false><<<dim3(8, 32), 256, SMG>>>(
        hh, mlpT, mlp_proj_b, t, nullptr, 4*DIM, 4*DIM, 4*DIM, DIM);

    // 16. out = LN(x2 + t)
    add_ln<<<M, 256>>>(x2, t, ln3_g, ln3_b, out, nullptr);
}

// round 12
// speedup vs baseline: 6.8443x; 1.0477x over previous
#include <cuda_runtime.h>
#include <cuda_fp16.h>
#include <math.h>
#include <stdint.h>

#define SEQ 1024
#define DIM 1024
#define NB  4
#define NHEAD 16
#define HD  64

enum { EPI_BIAS=1, EPI_BIAS_GELU=2 };

// ---------------- scratch (no allocations allowed) ----------------
__device__ float  g_t [(size_t)NB*SEQ*DIM];
__device__ float  g_x1[(size_t)NB*SEQ*DIM];
__device__ float  g_x2[(size_t)NB*SEQ*DIM];
__device__ __half g_qkvh[(size_t)NB*SEQ*3*DIM];
__device__ __half g_abufh[(size_t)NB*SEQ*DIM];
__device__ __half g_xh [(size_t)NB*SEQ*DIM];
__device__ __half g_ctxh[(size_t)NB*SEQ*DIM];
__device__ __half g_x1h[(size_t)NB*SEQ*DIM];
__device__ __half g_x2h[(size_t)NB*SEQ*DIM];
__device__ __half g_qh [(size_t)NB*SEQ*DIM];
__device__ __half g_kvh[(size_t)NB*SEQ*2*DIM];
__device__ __half g_hh [(size_t)NB*SEQ*4*DIM];
__device__ __half g_wth[(size_t)16*1024*1024];   // 32MB transposed half weights

__device__ __forceinline__ float gelu_tanh(float v){
    float u = 0.7978845608028654f * (v + 0.044715f * v * v * v);
    return 0.5f * v * (1.0f + tanhf(u));
}

#define CP_ASYNC16(s, g)  asm volatile("cp.async.cg.shared.global [%0], [%1], 16;" :: "r"(s), "l"(__cvta_generic_to_global(g)))
#define CP_COMMIT()       asm volatile("cp.async.commit_group;")
#define CP_WAIT(n)        asm volatile("cp.async.wait_group %0;" :: "n"(n))

#define LDSM_X4(r0,r1,r2,r3,addr) \
    asm volatile("ldmatrix.sync.aligned.m8n8.x4.shared.b16 {%0,%1,%2,%3}, [%4];" \
                 : "=r"(r0),"=r"(r1),"=r"(r2),"=r"(r3) : "r"(addr))
#define LDSM_X4T(r0,r1,r2,r3,addr) \
    asm volatile("ldmatrix.sync.aligned.m8n8.x4.trans.shared.b16 {%0,%1,%2,%3}, [%4];" \
                 : "=r"(r0),"=r"(r1),"=r"(r2),"=r"(r3) : "r"(addr))

__device__ __forceinline__ uint32_t smem_u32(const void* p) {
    uint32_t a;
    asm("{ .reg .u64 t; cvta.to.shared.u64 t, %1; cvt.u32.u64 %0, t; }" : "=r"(a) : "l"(p));
    return a;
}
__device__ __forceinline__ uint32_t f2h2(float lo, float hi) {
    uint32_t r;
    asm("cvt.rn.f16x2.f32 %0, %1, %2;" : "=r"(r) : "f"(hi), "f"(lo));
    return r;
}
__device__ __forceinline__ void mma_f16(float* d, const uint32_t* a, const uint32_t* b) {
    asm volatile(
        "mma.sync.aligned.m16n8k16.row.col.f32.f16.f16.f32 "
        "{%0,%1,%2,%3}, {%4,%5,%6,%7}, {%8,%9}, {%0,%1,%2,%3};"
        : "+f"(d[0]), "+f"(d[1]), "+f"(d[2]), "+f"(d[3])
        : "r"(a[0]), "r"(a[1]), "r"(a[2]), "r"(a[3]), "r"(b[0]), "r"(b[1]));
}

// ---------------- fp16 ldmatrix GEMM, 3-stage pipeline, 1 sync/iter ----------
// C[M,N] = epi( A[M,K] * B^T )  A:[M,K] half K-major, B:[N,K] half K-major.
// Tile 128x128, BK=32. 8 warps 2x4; warp tile 64x32.
template<int EPI, bool OUTH>
__global__ void __launch_bounds__(256, 2) gemm_mma(
    const __half* __restrict__ A, const __half* __restrict__ B,
    const float* __restrict__ bias, float* __restrict__ C, __half* __restrict__ Ch,
    int K, int lda, int ldb, int ldc)
{
    constexpr int BM = 128, BN = 128, BK = 32;
    constexpr int AST = 40;                 // halves per smem row (32 + 8 pad)
    constexpr int SA = BM * AST, SB = BN * AST, STG = SA + SB;  // halves

    extern __shared__ __half smh[];
    const uint32_t sbase = smem_u32(smh);

    const int tid = threadIdx.x;
    const int row0 = blockIdx.y * BM;
    const int col0 = blockIdx.x * BN;
    const int wid = tid >> 5, lane = tid & 31;
    const int g = lane >> 2, tg = lane & 3;
    const int wm = (wid & 1) * 64;
    const int wn = (wid >> 1) * 32;

    float acc[4][4][4];
    #pragma unroll
    for (int mt = 0; mt < 4; mt++)
        #pragma unroll
        for (int nt = 0; nt < 4; nt++)
            #pragma unroll
            for (int i = 0; i < 4; i++) acc[mt][nt][i] = 0.f;

    auto load_stage = [&](int step) {
        int st = step % 3;
        long k0 = (long)step * BK;
        uint32_t as = sbase + (uint32_t)(st*STG)*2u;
        uint32_t bs = as + (uint32_t)SA*2u;
        #pragma unroll
        for (int i = 0; i < 2; i++) {
            int c = tid + i*256;
            int r = c >> 2, kc = c & 3;
            CP_ASYNC16(as + (uint32_t)(r*AST + kc*8)*2,
                       A + (long)(row0 + r)*lda + k0 + kc*8);
        }
        #pragma unroll
        for (int i = 0; i < 2; i++) {
            int c = tid + i*256;
            int r = c >> 2, kc = c & 3;
            CP_ASYNC16(bs + (uint32_t)(r*AST + kc*8)*2,
                       B + (long)(col0 + r)*ldb + k0 + kc*8);
        }
        CP_COMMIT();
    };

    const int nsteps = K / BK;
    load_stage(0);
    load_stage(1);

    const int a_r = lane & 15, a_c8 = (lane >> 4) << 3;
    const int b_r = ((lane >> 4) << 3) + (lane & 7);
    const int b_c8 = ((lane >> 3) & 1) << 3;

    for (int i = 0; i < nsteps; i++) {
        if (i + 1 < nsteps) { CP_WAIT(1); } else { CP_WAIT(0); }
        __syncthreads();                 // single barrier per iteration
        if (i + 2 < nsteps) load_stage(i + 2);

        uint32_t as = sbase + (uint32_t)((i % 3)*STG)*2u;
        uint32_t bs = as + (uint32_t)SA*2u;

        #pragma unroll
        for (int kb = 0; kb < 2; kb++) {
            int kk = kb * 16;
            uint32_t af[4][4], bf[4][2];
            #pragma unroll
            for (int mt = 0; mt < 4; mt++) {
                uint32_t ad = as + (uint32_t)((wm + mt*16 + a_r)*AST + kk + a_c8)*2;
                LDSM_X4(af[mt][0], af[mt][1], af[mt][2], af[mt][3], ad);
            }
            #pragma unroll
            for (int p = 0; p < 2; p++) {
                uint32_t bd = bs + (uint32_t)((wn + p*16 + b_r)*AST + kk + b_c8)*2;
                LDSM_X4(bf[2*p][0], bf[2*p][1], bf[2*p+1][0], bf[2*p+1][1], bd);
            }
            #pragma unroll
            for (int mt = 0; mt < 4; mt++)
                #pragma unroll
                for (int nt = 0; nt < 4; nt++)
                    mma_f16(acc[mt][nt], af[mt], bf[nt]);
        }
    }

    #pragma unroll
    for (int mt = 0; mt < 4; mt++) {
        #pragma unroll
        for (int nt = 0; nt < 4; nt++) {
            int Rg = row0 + wm + mt*16 + g;
            int cg = col0 + wn + nt*8 + 2*tg;
            #pragma unroll
            for (int half_i = 0; half_i < 2; half_i++) {
                int r = Rg + half_i*8;
                float v0 = acc[mt][nt][half_i*2 + 0] + bias[cg];
                float v1 = acc[mt][nt][half_i*2 + 1] + bias[cg+1];
                if (EPI == EPI_BIAS_GELU) { v0 = gelu_tanh(v0); v1 = gelu_tanh(v1); }
                if (OUTH) {
                    *(uint32_t*)&Ch[(long)r*ldc + cg] = f2h2(v0, v1);
                } else {
                    *(float2*)&C[(long)r*ldc + cg] = make_float2(v0, v1);
                }
            }
        }
    }
}

// ---------------- fused flash attention: 128 threads, 64 Q rows/CTA ---------
// 4 warps x 16 rows; 3-stage KV pipeline; 3 CTAs/SM for latency hiding.
__global__ void __launch_bounds__(128, 3) flash_attn(
    const __half* __restrict__ Q, const __half* __restrict__ K,
    const __half* __restrict__ V, __half* __restrict__ O,
    int ldq, int ldkv, int causal)
{
    constexpr int ST = 72;                  // halves per row (64 + 8)
    constexpr int QSZ = 64*ST;              // halves
    constexpr int KVSZ = 64*ST;
    constexpr int STGH = 2*KVSZ;            // K + V per stage
    extern __shared__ __half smh[];
    const uint32_t sbase = smem_u32(smh);

    const int tid = threadIdx.x;
    const int wid = tid >> 5, lane = tid & 31;
    const int g = lane >> 2, tg = lane & 3;
    // heavy-first for causal: high-qt CTAs (most KV tiles) scheduled first
    const int qt = causal ? (int)(gridDim.x - 1 - blockIdx.x) : (int)blockIdx.x;
    const int bh = blockIdx.y, bb = bh >> 4, hh = bh & 15;
    const int wm = wid * 16;

    const __half* Qb = Q + (long)bb*SEQ*ldq  + hh*64 + (long)qt*64*ldq;
    const __half* Kb = K + (long)bb*SEQ*ldkv + hh*64;
    const __half* Vb = V + (long)bb*SEQ*ldkv + hh*64;
    __half*       Ob = O + (long)bb*SEQ*DIM  + hh*64 + (long)qt*64*DIM;

    // ---- stage Q (64 rows) ----
    #pragma unroll
    for (int i = 0; i < 4; i++) {
        int c = tid + i*128;
        int r = c >> 3, kc = c & 7;
        CP_ASYNC16(sbase + (uint32_t)(r*ST + kc*8)*2, Qb + (long)r*ldq + kc*8);
    }
    CP_COMMIT(); CP_WAIT(0);
    __syncthreads();

    const int a_r = lane & 15, a_c8 = (lane >> 4) << 3;
    const int b_r = ((lane >> 4) << 3) + (lane & 7);
    const int b_c8 = ((lane >> 3) & 1) << 3;
    const int v_r = (((lane >> 3) & 1) << 3) + (lane & 7);
    const int v_c8 = (lane >> 4) << 3;

    uint32_t aq[4][4];
    #pragma unroll
    for (int kt = 0; kt < 4; kt++) {
        uint32_t ad = sbase + (uint32_t)((wm + a_r)*ST + kt*16 + a_c8)*2;
        LDSM_X4(aq[kt][0], aq[kt][1], aq[kt][2], aq[kt][3], ad);
    }
    __syncthreads();

    float acc_o[8][4];
    #pragma unroll
    for (int nt = 0; nt < 8; nt++)
        #pragma unroll
        for (int i = 0; i < 4; i++) acc_o[nt][i] = 0.f;
    float m0 = -1e30f, m1 = -1e30f, l0 = 0.f, l1 = 0.f;

    const int ntiles = causal ? (qt + 1) : (SEQ/64);
    const int rowg0 = qt*64 + wm + g;
    const int rowg1 = rowg0 + 8;

    auto load_kv = [&](int j) {
        uint32_t st = sbase + (uint32_t)(QSZ + (j % 3)*STGH)*2u;
        const __half* Kg = Kb + (long)j*64*ldkv;
        const __half* Vg = Vb + (long)j*64*ldkv;
        #pragma unroll
        for (int i = 0; i < 4; i++) {
            int c = tid + i*128;
            int r = c >> 3, kc = c & 7;
            CP_ASYNC16(st + (uint32_t)(r*ST + kc*8)*2, Kg + (long)r*ldkv + kc*8);
        }
        uint32_t vs = st + (uint32_t)KVSZ*2u;
        #pragma unroll
        for (int i = 0; i < 4; i++) {
            int c = tid + i*128;
            int r = c >> 3, kc = c & 7;
            CP_ASYNC16(vs + (uint32_t)(r*ST + kc*8)*2, Vg + (long)r*ldkv + kc*8);
        }
        CP_COMMIT();
    };

    load_kv(0);
    if (ntiles > 1) load_kv(1);

    for (int j = 0; j < ntiles; j++) {
        if (j + 1 < ntiles) { CP_WAIT(1); } else { CP_WAIT(0); }
        __syncthreads();                 // single barrier per tile
        if (j + 2 < ntiles) load_kv(j + 2);

        uint32_t ks = sbase + (uint32_t)(QSZ + (j % 3)*STGH)*2u;
        uint32_t vs = ks + (uint32_t)KVSZ*2u;

        // ---- S = Q K^T (unscaled) ----
        float s[8][4];
        #pragma unroll
        for (int nt = 0; nt < 8; nt++)
            #pragma unroll
            for (int i = 0; i < 4; i++) s[nt][i] = 0.f;

        #pragma unroll
        for (int kt = 0; kt < 4; kt++) {
            int kk = kt*16;
            #pragma unroll
            for (int p = 0; p < 4; p++) {
                uint32_t bf[2][2];
                uint32_t bd = ks + (uint32_t)((p*16 + b_r)*ST + kk + b_c8)*2;
                LDSM_X4(bf[0][0], bf[0][1], bf[1][0], bf[1][1], bd);
                mma_f16(s[2*p  ], aq[kt], bf[0]);
                mma_f16(s[2*p+1], aq[kt], bf[1]);
            }
        }

        // ---- scale + causal mask (only the diagonal tile j == qt) ----
        #pragma unroll
        for (int nt = 0; nt < 8; nt++)
            #pragma unroll
            for (int i = 0; i < 4; i++) s[nt][i] *= 0.125f;

        if (causal && j == qt) {
            int kbase = j*64;
            #pragma unroll
            for (int nt = 0; nt < 8; nt++) {
                int kg = kbase + nt*8 + 2*tg;
                if (kg     > rowg0) s[nt][0] = -1e30f;
                if (kg + 1 > rowg0) s[nt][1] = -1e30f;
                if (kg     > rowg1) s[nt][2] = -1e30f;
                if (kg + 1 > rowg1) s[nt][3] = -1e30f;
            }
        }

        // ---- online softmax ----
        float tm0 = -1e30f, tm1 = -1e30f;
        #pragma unroll
        for (int nt = 0; nt < 8; nt++) {
            tm0 = fmaxf(tm0, fmaxf(s[nt][0], s[nt][1]));
            tm1 = fmaxf(tm1, fmaxf(s[nt][2], s[nt][3]));
        }
        tm0 = fmaxf(tm0, __shfl_xor_sync(0xffffffffu, tm0, 1));
        tm0 = fmaxf(tm0, __shfl_xor_sync(0xffffffffu, tm0, 2));
        tm1 = fmaxf(tm1, __shfl_xor_sync(0xffffffffu, tm1, 1));
        tm1 = fmaxf(tm1, __shfl_xor_sync(0xffffffffu, tm1, 2));

        float mn0 = fmaxf(m0, tm0), mn1 = fmaxf(m1, tm1);
        float al0 = __expf(m0 - mn0), al1 = __expf(m1 - mn1);
        float ts0 = 0.f, ts1 = 0.f;
        #pragma unroll
        for (int nt = 0; nt < 8; nt++) {
            s[nt][0] = __expf(s[nt][0] - mn0);
            s[nt][1] = __expf(s[nt][1] - mn0);
            s[nt][2] = __expf(s[nt][2] - mn1);
            s[nt][3] = __expf(s[nt][3] - mn1);
            ts0 += s[nt][0] + s[nt][1];
            ts1 += s[nt][2] + s[nt][3];
        }
        ts0 += __shfl_xor_sync(0xffffffffu, ts0, 1);
        ts0 += __shfl_xor_sync(0xffffffffu, ts0, 2);
        ts1 += __shfl_xor_sync(0xffffffffu, ts1, 1);
        ts1 += __shfl_xor_sync(0xffffffffu, ts1, 2);

        l0 = l0*al0 + ts0;  l1 = l1*al1 + ts1;
        m0 = mn0;  m1 = mn1;

        #pragma unroll
        for (int nt = 0; nt < 8; nt++) {
            acc_o[nt][0] *= al0;  acc_o[nt][1] *= al0;
            acc_o[nt][2] *= al1;  acc_o[nt][3] *= al1;
        }

        // ---- O += P V ----
        #pragma unroll
        for (int kt = 0; kt < 4; kt++) {
            uint32_t ap[4];
            ap[0] = f2h2(s[2*kt  ][0], s[2*kt  ][1]);
            ap[1] = f2h2(s[2*kt  ][2], s[2*kt  ][3]);
            ap[2] = f2h2(s[2*kt+1][0], s[2*kt+1][1]);
            ap[3] = f2h2(s[2*kt+1][2], s[2*kt+1][3]);
            #pragma unroll
            for (int p = 0; p < 4; p++) {
                uint32_t bv[2][2];
                uint32_t vd = vs + (uint32_t)((kt*16 + v_r)*ST + p*16 + v_c8)*2;
                LDSM_X4T(bv[0][0], bv[0][1], bv[1][0], bv[1][1], vd);
                mma_f16(acc_o[2*p  ], ap, bv[0]);
                mma_f16(acc_o[2*p+1], ap, bv[1]);
            }
        }
    }

    // ---- normalize + store half ----
    float r0 = 1.f / l0, r1 = 1.f / l1;
    #pragma unroll
    for (int nt = 0; nt < 8; nt++) {
        int c = nt*8 + 2*tg;
        *(uint32_t*)&Ob[(long)(wm+g  )*DIM + c] = f2h2(acc_o[nt][0]*r0, acc_o[nt][1]*r0);
        *(uint32_t*)&Ob[(long)(wm+g+8)*DIM + c] = f2h2(acc_o[nt][2]*r1, acc_o[nt][3]*r1);
    }
}

// ---------------- merged weight transposes (7 segments, flat grid) ----------
__global__ void prep_weights(
    const float* w0, const float* w1, const float* w2, const float* w3,
    const float* w4, const float* w5, const float* w6,
    __half* o0, __half* o1, __half* o2, __half* o3,
    __half* o4, __half* o5, __half* o6)
{
    const int gx[7]  = {96, 32, 32, 64, 32, 128, 32};
    const int off[8] = {0, 3072, 4096, 5120, 7168, 8192, 12288, 16384};
    const int ldi[7] = {3072, 1024, 1024, 2048, 1024, 4096, 1024};
    const int ldo[7] = {1024, 1024, 1024, 1024, 1024, 1024, 4096};

    int bid = blockIdx.x;
    int seg = 0;
    #pragma unroll
    for (int s = 1; s < 7; s++) if (bid >= off[s]) seg = s;
    int lt = bid - off[seg];
    int bx = lt % gx[seg], by = lt / gx[seg];

    const float* in  = (seg==0)?w0:(seg==1)?w1:(seg==2)?w2:(seg==3)?w3:(seg==4)?w4:(seg==5)?w5:w6;
    __half*      out = (seg==0)?o0:(seg==1)?o1:(seg==2)?o2:(seg==3)?o3:(seg==4)?o4:(seg==5)?o5:o6;
    int ldin = ldi[seg], ldout = ldo[seg];

    __shared__ float t[32][33];
    int r0 = by*32, c0 = bx*32;
    int x = threadIdx.x, y = threadIdx.y;
    #pragma unroll
    for (int i = 0; i < 32; i += 8) t[y+i][x] = in[(long)(r0+y+i)*ldin + c0 + x];
    __syncthreads();
    #pragma unroll
    for (int i = 0; i < 32; i += 8)
        out[(long)(c0+y+i)*ldout + r0 + x] = __float2half(t[x][y+i]);
}

// ---------------- merged fp32 -> half convert (x and ctx) ----------------
__global__ void f2h_dual(const float* __restrict__ a, __half* __restrict__ ah,
                         const float* __restrict__ b, __half* __restrict__ bh, int n4)
{
    int i = blockIdx.x*blockDim.x + threadIdx.x;
    const float* in; __half* out;
    if (i < n4) { in = a; out = ah; }
    else        { in = b; out = bh; i -= n4; if (i >= n4) return; }
    float4 v = ((const float4*)in)[i];
    ((uint32_t*)out)[2*i    ] = f2h2(v.x, v.y);
    ((uint32_t*)out)[2*i + 1] = f2h2(v.z, v.w);
}

// ---------------- fused residual add + LayerNorm ----------------
__global__ void __launch_bounds__(256) add_ln(
    const float* __restrict__ x, const float* __restrict__ a,
    const float* __restrict__ g, const float* __restrict__ b,
    float* __restrict__ y, __half* __restrict__ yh)
{
    __shared__ float red[8];
    __shared__ float bc;
    long row = blockIdx.x;
    const float* xr = x + row * DIM;
    const float* ar = a + row * DIM;
    float* yr = y + row * DIM;
    int tid = threadIdx.x, lane = tid & 31, wid = tid >> 5;

    float v[4], s = 0.f;
    #pragma unroll
    for (int i = 0; i < 4; i++) { int c = tid + i*256; v[i] = xr[c] + ar[c]; s += v[i]; }
    #pragma unroll
    for (int o = 16; o > 0; o >>= 1) s += __shfl_xor_sync(0xffffffffu, s, o);
    if (lane == 0) red[wid] = s;
    __syncthreads();
    if (tid == 0) {
        float t = 0.f;
        #pragma unroll
        for (int i = 0; i < 8; i++) t += red[i];
        bc = t * (1.0f / DIM);
    }
    __syncthreads();
    float mu = bc;

    float q = 0.f;
    #pragma unroll
    for (int i = 0; i < 4; i++) { float d = v[i] - mu; q += d * d; }
    #pragma unroll
    for (int o = 16; o > 0; o >>= 1) q += __shfl_xor_sync(0xffffffffu, q, o);
    __syncthreads();
    if (lane == 0) red[wid] = q;
    __syncthreads();
    if (tid == 0) {
        float t = 0.f;
        #pragma unroll
        for (int i = 0; i < 8; i++) t += red[i];
        bc = rsqrtf(t * (1.0f / DIM) + 1e-5f);
    }
    __syncthreads();
    float inv = bc;
    #pragma unroll
    for (int i = 0; i < 4; i++) {
        int c = tid + i*256;
        float o = (v[i] - mu) * inv * g[c] + b[c];
        yr[c] = o;
        if (yh) yh[row*DIM + c] = __float2half(o);
    }
}

// ---------------- host orchestration ----------------
extern "C" void kernel_launch(void* const* d_in, const int* in_sizes, int n_in,
                              void* d_out, int out_size)
{
    const float* x            = (const float*)d_in[0];
    const float* ctx          = (const float*)d_in[1];
    const float* c_attn_w     = (const float*)d_in[2];
    const float* c_attn_b     = (const float*)d_in[3];
    const float* self_proj_w  = (const float*)d_in[4];
    const float* self_proj_b  = (const float*)d_in[5];
    const float* q_w          = (const float*)d_in[6];
    const float* q_b          = (const float*)d_in[7];
    const float* kv_w         = (const float*)d_in[8];
    const float* kv_b         = (const float*)d_in[9];
    const float* cross_proj_w = (const float*)d_in[10];
    const float* cross_proj_b = (const float*)d_in[11];
    const float* fc_w         = (const float*)d_in[12];
    const float* fc_b         = (const float*)d_in[13];
    const float* mlp_proj_w   = (const float*)d_in[14];
    const float* mlp_proj_b   = (const float*)d_in[15];
    const float* ln1_g        = (const float*)d_in[16];
    const float* ln1_b        = (const float*)d_in[17];
    const float* ln2_g        = (const float*)d_in[18];
    const float* ln2_b        = (const float*)d_in[19];
    const float* ln3_g        = (const float*)d_in[20];
    const float* ln3_b        = (const float*)d_in[21];
    float* out = (float*)d_out;

    float *t, *x1, *x2;
    __half *qkvh, *abufh, *xh, *ctxh, *x1h, *x2h, *qh, *kvh, *hh, *wth;
    cudaGetSymbolAddress((void**)&t,     g_t);
    cudaGetSymbolAddress((void**)&x1,    g_x1);
    cudaGetSymbolAddress((void**)&x2,    g_x2);
    cudaGetSymbolAddress((void**)&qkvh,  g_qkvh);
    cudaGetSymbolAddress((void**)&abufh, g_abufh);
    cudaGetSymbolAddress((void**)&xh,    g_xh);
    cudaGetSymbolAddress((void**)&ctxh,  g_ctxh);
    cudaGetSymbolAddress((void**)&x1h,   g_x1h);
    cudaGetSymbolAddress((void**)&x2h,   g_x2h);
    cudaGetSymbolAddress((void**)&qh,    g_qh);
    cudaGetSymbolAddress((void**)&kvh,   g_kvh);
    cudaGetSymbolAddress((void**)&hh,    g_hh);
    cudaGetSymbolAddress((void**)&wth,   g_wth);

    __half* cattnT = wth;                        // [3072,1024]
    __half* selfT  = wth +  3l*1024*1024;
    __half* qT     = wth +  4l*1024*1024;
    __half* kvT    = wth +  5l*1024*1024;        // [2048,1024]
    __half* crossT = wth +  7l*1024*1024;
    __half* fcT    = wth +  8l*1024*1024;        // [4096,1024]
    __half* mlpT   = wth + 12l*1024*1024;        // [1024,4096]

    const int SMG = (128*40 + 128*40) * 3 * 2;          // 61440 B (3 stages)
    const int SMF = (64*72 + 3*(2*64*72)) * 2;          // 64512 B (Q + 3 KV stages)
    cudaFuncSetAttribute(gemm_mma<EPI_BIAS, true>,      cudaFuncAttributeMaxDynamicSharedMemorySize, SMG);
    cudaFuncSetAttribute(gemm_mma<EPI_BIAS, false>,     cudaFuncAttributeMaxDynamicSharedMemorySize, SMG);
    cudaFuncSetAttribute(gemm_mma<EPI_BIAS_GELU, true>, cudaFuncAttributeMaxDynamicSharedMemorySize, SMG);
    cudaFuncSetAttribute(flash_attn, cudaFuncAttributeMaxDynamicSharedMemorySize, SMF);

    const int M = NB * SEQ;                  // 4096

    // ---- merged prologue: input converts + all weight transposes ----
    f2h_dual<<<8192, 256>>>(x, xh, ctx, ctxh, M*DIM/4);
    prep_weights<<<16384, dim3(32, 8)>>>(
        c_attn_w, self_proj_w, q_w, kv_w, cross_proj_w, fc_w, mlp_proj_w,
        cattnT, selfT, qT, kvT, crossT, fcT, mlpT);

    // 1. qkv = x @ c_attn_w + b   (half out)
    gemm_mma<EPI_BIAS, true><<<dim3(24, 32), 256, SMG>>>(
        xh, cattnT, c_attn_b, nullptr, qkvh, DIM, DIM, DIM, 3*DIM);

    // 2-4. fused causal self-attention -> abufh (64-row Q tiles)
    flash_attn<<<dim3(16, NB*NHEAD), 128, SMF>>>(
        qkvh, qkvh + DIM, qkvh + 2*DIM, abufh, 3*DIM, 3*DIM, 1);

    // 5. t = a @ self_proj_w + b  (fp32 out)
    gemm_mma<EPI_BIAS, false><<<dim3(8, 32), 256, SMG>>>(
        abufh, selfT, self_proj_b, t, nullptr, DIM, DIM, DIM, DIM);

    // 6. x1 = LN(x + t)  (+ half copy)
    add_ln<<<M, 256>>>(x, t, ln1_g, ln1_b, x1, x1h);

    // 7. q = x1 @ q_w + b  (half out)
    gemm_mma<EPI_BIAS, true><<<dim3(8, 32), 256, SMG>>>(
        x1h, qT, q_b, nullptr, qh, DIM, DIM, DIM, DIM);

    // 8. kv = ctx @ kv_w + b  (half out)
    gemm_mma<EPI_BIAS, true><<<dim3(16, 32), 256, SMG>>>(
        ctxh, kvT, kv_b, nullptr, kvh, DIM, DIM, DIM, 2*DIM);

    // 9-11. fused cross-attention -> abufh
    flash_attn<<<dim3(16, NB*NHEAD), 128, SMF>>>(
        qh, kvh, kvh + DIM, abufh, DIM, 2*DIM, 0);

    // 12. t = a @ cross_proj_w + b  (fp32 out)
    gemm_mma<EPI_BIAS, false><<<dim3(8, 32), 256, SMG>>>(
        abufh, crossT, cross_proj_b, t, nullptr, DIM, DIM, DIM, DIM);

    // 13. x2 = LN(x1 + t)  (+ half copy)
    add_ln<<<M, 256>>>(x1, t, ln2_g, ln2_b, x2, x2h);

    // 14. h = gelu(x2 @ fc_w + b)  (half out)
    gemm_mma<EPI_BIAS_GELU, true><<<dim3(32, 32), 256, SMG>>>(
        x2h, fcT, fc_b, nullptr, hh, DIM, DIM, DIM, 4*DIM);

    // 15. t = h @ mlp_proj_w + b  (fp32 out)
    gemm_mma<EPI_BIAS, false><<<dim3(8, 32), 256, SMG>>>(
        hh, mlpT, mlp_proj_b, t, nullptr, 4*DIM, 4*DIM, 4*DIM, DIM);

    // 16. out = LN(x2 + t)
    add_ln<<<M, 256>>>(x2, t, ln3_g, ln3_b, out, nullptr);
}

// round 13
// speedup vs baseline: 7.1292x; 1.0416x over previous
#include <cuda_runtime.h>
#include <cuda_fp16.h>
#include <math.h>
#include <stdint.h>

#define SEQ 1024
#define DIM 1024
#define NB  4
#define NHEAD 16
#define HD  64

enum { EPI_BIAS=1, EPI_BIAS_GELU=2 };

// ---------------- scratch (no allocations allowed) ----------------
__device__ float  g_t [(size_t)NB*SEQ*DIM];
__device__ float  g_x1[(size_t)NB*SEQ*DIM];
__device__ float  g_x2[(size_t)NB*SEQ*DIM];
__device__ __half g_qkvh[(size_t)NB*SEQ*3*DIM];
__device__ __half g_abufh[(size_t)NB*SEQ*DIM];
__device__ __half g_xh [(size_t)NB*SEQ*DIM];
__device__ __half g_ctxh[(size_t)NB*SEQ*DIM];
__device__ __half g_x1h[(size_t)NB*SEQ*DIM];
__device__ __half g_x2h[(size_t)NB*SEQ*DIM];
__device__ __half g_qh [(size_t)NB*SEQ*DIM];
__device__ __half g_kvh[(size_t)NB*SEQ*2*DIM];
__device__ __half g_hh [(size_t)NB*SEQ*4*DIM];
__device__ __half g_wth[(size_t)16*1024*1024];   // 32MB transposed half weights

__device__ __forceinline__ float gelu_tanh(float v){
    float u = 0.7978845608028654f * (v + 0.044715f * v * v * v);
    return 0.5f * v * (1.0f + tanhf(u));
}

#define CP_ASYNC16(s, g)  asm volatile("cp.async.cg.shared.global [%0], [%1], 16;" :: "r"(s), "l"(__cvta_generic_to_global(g)))
#define CP_COMMIT()       asm volatile("cp.async.commit_group;")
#define CP_WAIT(n)        asm volatile("cp.async.wait_group %0;" :: "n"(n))

#define LDSM_X4(r0,r1,r2,r3,addr) \
    asm volatile("ldmatrix.sync.aligned.m8n8.x4.shared.b16 {%0,%1,%2,%3}, [%4];" \
                 : "=r"(r0),"=r"(r1),"=r"(r2),"=r"(r3) : "r"(addr))
#define LDSM_X4T(r0,r1,r2,r3,addr) \
    asm volatile("ldmatrix.sync.aligned.m8n8.x4.trans.shared.b16 {%0,%1,%2,%3}, [%4];" \
                 : "=r"(r0),"=r"(r1),"=r"(r2),"=r"(r3) : "r"(addr))

__device__ __forceinline__ uint32_t smem_u32(const void* p) {
    uint32_t a;
    asm("{ .reg .u64 t; cvta.to.shared.u64 t, %1; cvt.u32.u64 %0, t; }" : "=r"(a) : "l"(p));
    return a;
}
__device__ __forceinline__ uint32_t f2h2(float lo, float hi) {
    uint32_t r;
    asm("cvt.rn.f16x2.f32 %0, %1, %2;" : "=r"(r) : "f"(hi), "f"(lo));
    return r;
}
__device__ __forceinline__ void mma_f16(float* d, const uint32_t* a, const uint32_t* b) {
    asm volatile(
        "mma.sync.aligned.m16n8k16.row.col.f32.f16.f16.f32 "
        "{%0,%1,%2,%3}, {%4,%5,%6,%7}, {%8,%9}, {%0,%1,%2,%3};"
        : "+f"(d[0]), "+f"(d[1]), "+f"(d[2]), "+f"(d[3])
        : "r"(a[0]), "r"(a[1]), "r"(a[2]), "r"(a[3]), "r"(b[0]), "r"(b[1]));
}

// ---------------- fp16 ldmatrix GEMM, 3-stage pipeline, 1 sync/iter ----------
template<int EPI, bool OUTH>
__global__ void __launch_bounds__(256, 2) gemm_mma(
    const __half* __restrict__ A, const __half* __restrict__ B,
    const float* __restrict__ bias, float* __restrict__ C, __half* __restrict__ Ch,
    int K, int lda, int ldb, int ldc)
{
    constexpr int BM = 128, BN = 128, BK = 32;
    constexpr int AST = 40;
    constexpr int SA = BM * AST, SB = BN * AST, STG = SA + SB;

    extern __shared__ __half smh[];
    const uint32_t sbase = smem_u32(smh);

    const int tid = threadIdx.x;
    const int row0 = blockIdx.y * BM;
    const int col0 = blockIdx.x * BN;
    const int wid = tid >> 5, lane = tid & 31;
    const int g = lane >> 2, tg = lane & 3;
    const int wm = (wid & 1) * 64;
    const int wn = (wid >> 1) * 32;

    float acc[4][4][4];
    #pragma unroll
    for (int mt = 0; mt < 4; mt++)
        #pragma unroll
        for (int nt = 0; nt < 4; nt++)
            #pragma unroll
            for (int i = 0; i < 4; i++) acc[mt][nt][i] = 0.f;

    auto load_stage = [&](int step) {
        int st = step % 3;
        long k0 = (long)step * BK;
        uint32_t as = sbase + (uint32_t)(st*STG)*2u;
        uint32_t bs = as + (uint32_t)SA*2u;
        #pragma unroll
        for (int i = 0; i < 2; i++) {
            int c = tid + i*256;
            int r = c >> 2, kc = c & 3;
            CP_ASYNC16(as + (uint32_t)(r*AST + kc*8)*2,
                       A + (long)(row0 + r)*lda + k0 + kc*8);
        }
        #pragma unroll
        for (int i = 0; i < 2; i++) {
            int c = tid + i*256;
            int r = c >> 2, kc = c & 3;
            CP_ASYNC16(bs + (uint32_t)(r*AST + kc*8)*2,
                       B + (long)(col0 + r)*ldb + k0 + kc*8);
        }
        CP_COMMIT();
    };

    const int nsteps = K / BK;
    load_stage(0);
    load_stage(1);

    const int a_r = lane & 15, a_c8 = (lane >> 4) << 3;
    const int b_r = ((lane >> 4) << 3) + (lane & 7);
    const int b_c8 = ((lane >> 3) & 1) << 3;

    for (int i = 0; i < nsteps; i++) {
        if (i + 1 < nsteps) { CP_WAIT(1); } else { CP_WAIT(0); }
        __syncthreads();
        if (i + 2 < nsteps) load_stage(i + 2);

        uint32_t as = sbase + (uint32_t)((i % 3)*STG)*2u;
        uint32_t bs = as + (uint32_t)SA*2u;

        #pragma unroll
        for (int kb = 0; kb < 2; kb++) {
            int kk = kb * 16;
            uint32_t af[4][4], bf[4][2];
            #pragma unroll
            for (int mt = 0; mt < 4; mt++) {
                uint32_t ad = as + (uint32_t)((wm + mt*16 + a_r)*AST + kk + a_c8)*2;
                LDSM_X4(af[mt][0], af[mt][1], af[mt][2], af[mt][3], ad);
            }
            #pragma unroll
            for (int p = 0; p < 2; p++) {
                uint32_t bd = bs + (uint32_t)((wn + p*16 + b_r)*AST + kk + b_c8)*2;
                LDSM_X4(bf[2*p][0], bf[2*p][1], bf[2*p+1][0], bf[2*p+1][1], bd);
            }
            #pragma unroll
            for (int mt = 0; mt < 4; mt++)
                #pragma unroll
                for (int nt = 0; nt < 4; nt++)
                    mma_f16(acc[mt][nt], af[mt], bf[nt]);
        }
    }

    #pragma unroll
    for (int mt = 0; mt < 4; mt++) {
        #pragma unroll
        for (int nt = 0; nt < 4; nt++) {
            int Rg = row0 + wm + mt*16 + g;
            int cg = col0 + wn + nt*8 + 2*tg;
            #pragma unroll
            for (int half_i = 0; half_i < 2; half_i++) {
                int r = Rg + half_i*8;
                float v0 = acc[mt][nt][half_i*2 + 0] + bias[cg];
                float v1 = acc[mt][nt][half_i*2 + 1] + bias[cg+1];
                if (EPI == EPI_BIAS_GELU) { v0 = gelu_tanh(v0); v1 = gelu_tanh(v1); }
                if (OUTH) {
                    *(uint32_t*)&Ch[(long)r*ldc + cg] = f2h2(v0, v1);
                } else {
                    *(float2*)&C[(long)r*ldc + cg] = make_float2(v0, v1);
                }
            }
        }
    }
}

// ---------------- fused flash attention: 128 threads, 64 Q rows/CTA ---------
__global__ void __launch_bounds__(128, 3) flash_attn(
    const __half* __restrict__ Q, const __half* __restrict__ K,
    const __half* __restrict__ V, __half* __restrict__ O,
    int ldq, int ldkv, int causal)
{
    constexpr int ST = 72;
    constexpr int QSZ = 64*ST;
    constexpr int KVSZ = 64*ST;
    constexpr int STGH = 2*KVSZ;
    extern __shared__ __half smh[];
    const uint32_t sbase = smem_u32(smh);

    const int tid = threadIdx.x;
    const int wid = tid >> 5, lane = tid & 31;
    const int g = lane >> 2, tg = lane & 3;
    const int qt = causal ? (int)(gridDim.x - 1 - blockIdx.x) : (int)blockIdx.x;
    const int bh = blockIdx.y, bb = bh >> 4, hh = bh & 15;
    const int wm = wid * 16;

    const __half* Qb = Q + (long)bb*SEQ*ldq  + hh*64 + (long)qt*64*ldq;
    const __half* Kb = K + (long)bb*SEQ*ldkv + hh*64;
    const __half* Vb = V + (long)bb*SEQ*ldkv + hh*64;
    __half*       Ob = O + (long)bb*SEQ*DIM  + hh*64 + (long)qt*64*DIM;

    #pragma unroll
    for (int i = 0; i < 4; i++) {
        int c = tid + i*128;
        int r = c >> 3, kc = c & 7;
        CP_ASYNC16(sbase + (uint32_t)(r*ST + kc*8)*2, Qb + (long)r*ldq + kc*8);
    }
    CP_COMMIT(); CP_WAIT(0);
    __syncthreads();

    const int a_r = lane & 15, a_c8 = (lane >> 4) << 3;
    const int b_r = ((lane >> 4) << 3) + (lane & 7);
    const int b_c8 = ((lane >> 3) & 1) << 3;
    const int v_r = (((lane >> 3) & 1) << 3) + (lane & 7);
    const int v_c8 = (lane >> 4) << 3;

    uint32_t aq[4][4];
    #pragma unroll
    for (int kt = 0; kt < 4; kt++) {
        uint32_t ad = sbase + (uint32_t)((wm + a_r)*ST + kt*16 + a_c8)*2;
        LDSM_X4(aq[kt][0], aq[kt][1], aq[kt][2], aq[kt][3], ad);
    }
    __syncthreads();

    float acc_o[8][4];
    #pragma unroll
    for (int nt = 0; nt < 8; nt++)
        #pragma unroll
        for (int i = 0; i < 4; i++) acc_o[nt][i] = 0.f;
    float m0 = -1e30f, m1 = -1e30f, l0 = 0.f, l1 = 0.f;

    const int ntiles = causal ? (qt + 1) : (SEQ/64);
    const int rowg0 = qt*64 + wm + g;
    const int rowg1 = rowg0 + 8;

    auto load_kv = [&](int j) {
        uint32_t st = sbase + (uint32_t)(QSZ + (j % 3)*STGH)*2u;
        const __half* Kg = Kb + (long)j*64*ldkv;
        const __half* Vg = Vb + (long)j*64*ldkv;
        #pragma unroll
        for (int i = 0; i < 4; i++) {
            int c = tid + i*128;
            int r = c >> 3, kc = c & 7;
            CP_ASYNC16(st + (uint32_t)(r*ST + kc*8)*2, Kg + (long)r*ldkv + kc*8);
        }
        uint32_t vs = st + (uint32_t)KVSZ*2u;
        #pragma unroll
        for (int i = 0; i < 4; i++) {
            int c = tid + i*128;
            int r = c >> 3, kc = c & 7;
            CP_ASYNC16(vs + (uint32_t)(r*ST + kc*8)*2, Vg + (long)r*ldkv + kc*8);
        }
        CP_COMMIT();
    };

    load_kv(0);
    if (ntiles > 1) load_kv(1);

    for (int j = 0; j < ntiles; j++) {
        if (j + 1 < ntiles) { CP_WAIT(1); } else { CP_WAIT(0); }
        __syncthreads();
        if (j + 2 < ntiles) load_kv(j + 2);

        uint32_t ks = sbase + (uint32_t)(QSZ + (j % 3)*STGH)*2u;
        uint32_t vs = ks + (uint32_t)KVSZ*2u;

        float s[8][4];
        #pragma unroll
        for (int nt = 0; nt < 8; nt++)
            #pragma unroll
            for (int i = 0; i < 4; i++) s[nt][i] = 0.f;

        #pragma unroll
        for (int kt = 0; kt < 4; kt++) {
            int kk = kt*16;
            #pragma unroll
            for (int p = 0; p < 4; p++) {
                uint32_t bf[2][2];
                uint32_t bd = ks + (uint32_t)((p*16 + b_r)*ST + kk + b_c8)*2;
                LDSM_X4(bf[0][0], bf[0][1], bf[1][0], bf[1][1], bd);
                mma_f16(s[2*p  ], aq[kt], bf[0]);
                mma_f16(s[2*p+1], aq[kt], bf[1]);
            }
        }

        #pragma unroll
        for (int nt = 0; nt < 8; nt++)
            #pragma unroll
            for (int i = 0; i < 4; i++) s[nt][i] *= 0.125f;

        if (causal && j == qt) {
            int kbase = j*64;
            #pragma unroll
            for (int nt = 0; nt < 8; nt++) {
                int kg = kbase + nt*8 + 2*tg;
                if (kg     > rowg0) s[nt][0] = -1e30f;
                if (kg + 1 > rowg0) s[nt][1] = -1e30f;
                if (kg     > rowg1) s[nt][2] = -1e30f;
                if (kg + 1 > rowg1) s[nt][3] = -1e30f;
            }
        }

        float tm0 = -1e30f, tm1 = -1e30f;
        #pragma unroll
        for (int nt = 0; nt < 8; nt++) {
            tm0 = fmaxf(tm0, fmaxf(s[nt][0], s[nt][1]));
            tm1 = fmaxf(tm1, fmaxf(s[nt][2], s[nt][3]));
        }
        tm0 = fmaxf(tm0, __shfl_xor_sync(0xffffffffu, tm0, 1));
        tm0 = fmaxf(tm0, __shfl_xor_sync(0xffffffffu, tm0, 2));
        tm1 = fmaxf(tm1, __shfl_xor_sync(0xffffffffu, tm1, 1));
        tm1 = fmaxf(tm1, __shfl_xor_sync(0xffffffffu, tm1, 2));

        float mn0 = fmaxf(m0, tm0), mn1 = fmaxf(m1, tm1);
        float al0 = __expf(m0 - mn0), al1 = __expf(m1 - mn1);
        float ts0 = 0.f, ts1 = 0.f;
        #pragma unroll
        for (int nt = 0; nt < 8; nt++) {
            s[nt][0] = __expf(s[nt][0] - mn0);
            s[nt][1] = __expf(s[nt][1] - mn0);
            s[nt][2] = __expf(s[nt][2] - mn1);
            s[nt][3] = __expf(s[nt][3] - mn1);
            ts0 += s[nt][0] + s[nt][1];
            ts1 += s[nt][2] + s[nt][3];
        }
        ts0 += __shfl_xor_sync(0xffffffffu, ts0, 1);
        ts0 += __shfl_xor_sync(0xffffffffu, ts0, 2);
        ts1 += __shfl_xor_sync(0xffffffffu, ts1, 1);
        ts1 += __shfl_xor_sync(0xffffffffu, ts1, 2);

        l0 = l0*al0 + ts0;  l1 = l1*al1 + ts1;
        m0 = mn0;  m1 = mn1;

        #pragma unroll
        for (int nt = 0; nt < 8; nt++) {
            acc_o[nt][0] *= al0;  acc_o[nt][1] *= al0;
            acc_o[nt][2] *= al1;  acc_o[nt][3] *= al1;
        }

        #pragma unroll
        for (int kt = 0; kt < 4; kt++) {
            uint32_t ap[4];
            ap[0] = f2h2(s[2*kt  ][0], s[2*kt  ][1]);
            ap[1] = f2h2(s[2*kt  ][2], s[2*kt  ][3]);
            ap[2] = f2h2(s[2*kt+1][0], s[2*kt+1][1]);
            ap[3] = f2h2(s[2*kt+1][2], s[2*kt+1][3]);
            #pragma unroll
            for (int p = 0; p < 4; p++) {
                uint32_t bv[2][2];
                uint32_t vd = vs + (uint32_t)((kt*16 + v_r)*ST + p*16 + v_c8)*2;
                LDSM_X4T(bv[0][0], bv[0][1], bv[1][0], bv[1][1], vd);
                mma_f16(acc_o[2*p  ], ap, bv[0]);
                mma_f16(acc_o[2*p+1], ap, bv[1]);
            }
        }
    }

    float r0 = 1.f / l0, r1 = 1.f / l1;
    #pragma unroll
    for (int nt = 0; nt < 8; nt++) {
        int c = nt*8 + 2*tg;
        *(uint32_t*)&Ob[(long)(wm+g  )*DIM + c] = f2h2(acc_o[nt][0]*r0, acc_o[nt][1]*r0);
        *(uint32_t*)&Ob[(long)(wm+g+8)*DIM + c] = f2h2(acc_o[nt][2]*r1, acc_o[nt][3]*r1);
    }
}

// ---------------- merged weight transposes (7 segments, flat grid) ----------
__global__ void prep_weights(
    const float* w0, const float* w1, const float* w2, const float* w3,
    const float* w4, const float* w5, const float* w6,
    __half* o0, __half* o1, __half* o2, __half* o3,
    __half* o4, __half* o5, __half* o6)
{
    const int gx[7]  = {96, 32, 32, 64, 32, 128, 32};
    const int off[8] = {0, 3072, 4096, 5120, 7168, 8192, 12288, 16384};
    const int ldi[7] = {3072, 1024, 1024, 2048, 1024, 4096, 1024};
    const int ldo[7] = {1024, 1024, 1024, 1024, 1024, 1024, 4096};

    int bid = blockIdx.x;
    int seg = 0;
    #pragma unroll
    for (int s = 1; s < 7; s++) if (bid >= off[s]) seg = s;
    int lt = bid - off[seg];
    int bx = lt % gx[seg], by = lt / gx[seg];

    const float* in  = (seg==0)?w0:(seg==1)?w1:(seg==2)?w2:(seg==3)?w3:(seg==4)?w4:(seg==5)?w5:w6;
    __half*      out = (seg==0)?o0:(seg==1)?o1:(seg==2)?o2:(seg==3)?o3:(seg==4)?o4:(seg==5)?o5:o6;
    int ldin = ldi[seg], ldout = ldo[seg];

    __shared__ float t[32][33];
    int r0 = by*32, c0 = bx*32;
    int x = threadIdx.x, y = threadIdx.y;
    #pragma unroll
    for (int i = 0; i < 32; i += 8) t[y+i][x] = in[(long)(r0+y+i)*ldin + c0 + x];
    __syncthreads();
    #pragma unroll
    for (int i = 0; i < 32; i += 8)
        out[(long)(c0+y+i)*ldout + r0 + x] = __float2half(t[x][y+i]);
}

// ---------------- merged fp32 -> half convert (x and ctx) ----------------
__global__ void f2h_dual(const float* __restrict__ a, __half* __restrict__ ah,
                         const float* __restrict__ b, __half* __restrict__ bh, int n4)
{
    int i = blockIdx.x*blockDim.x + threadIdx.x;
    const float* in; __half* out;
    if (i < n4) { in = a; out = ah; }
    else        { in = b; out = bh; i -= n4; if (i >= n4) return; }
    float4 v = ((const float4*)in)[i];
    ((uint32_t*)out)[2*i    ] = f2h2(v.x, v.y);
    ((uint32_t*)out)[2*i + 1] = f2h2(v.z, v.w);
}

// ---------------- fused residual add + LayerNorm ----------------
__global__ void __launch_bounds__(256) add_ln(
    const float* __restrict__ x, const float* __restrict__ a,
    const float* __restrict__ g, const float* __restrict__ b,
    float* __restrict__ y, __half* __restrict__ yh)
{
    __shared__ float red[8];
    __shared__ float bc;
    long row = blockIdx.x;
    const float* xr = x + row * DIM;
    const float* ar = a + row * DIM;
    float* yr = y + row * DIM;
    int tid = threadIdx.x, lane = tid & 31, wid = tid >> 5;

    float v[4], s = 0.f;
    #pragma unroll
    for (int i = 0; i < 4; i++) { int c = tid + i*256; v[i] = xr[c] + ar[c]; s += v[i]; }
    #pragma unroll
    for (int o = 16; o > 0; o >>= 1) s += __shfl_xor_sync(0xffffffffu, s, o);
    if (lane == 0) red[wid] = s;
    __syncthreads();
    if (tid == 0) {
        float t = 0.f;
        #pragma unroll
        for (int i = 0; i < 8; i++) t += red[i];
        bc = t * (1.0f / DIM);
    }
    __syncthreads();
    float mu = bc;

    float q = 0.f;
    #pragma unroll
    for (int i = 0; i < 4; i++) { float d = v[i] - mu; q += d * d; }
    #pragma unroll
    for (int o = 16; o > 0; o >>= 1) q += __shfl_xor_sync(0xffffffffu, q, o);
    __syncthreads();
    if (lane == 0) red[wid] = q;
    __syncthreads();
    if (tid == 0) {
        float t = 0.f;
        #pragma unroll
        for (int i = 0; i < 8; i++) t += red[i];
        bc = rsqrtf(t * (1.0f / DIM) + 1e-5f);
    }
    __syncthreads();
    float inv = bc;
    #pragma unroll
    for (int i = 0; i < 4; i++) {
        int c = tid + i*256;
        float o = (v[i] - mu) * inv * g[c] + b[c];
        yr[c] = o;
        if (yh) yh[row*DIM + c] = __float2half(o);
    }
}

// ---------------- host orchestration (two-stream graph) ----------------
extern "C" void kernel_launch(void* const* d_in, const int* in_sizes, int n_in,
                              void* d_out, int out_size)
{
    const float* x            = (const float*)d_in[0];
    const float* ctx          = (const float*)d_in[1];
    const float* c_attn_w     = (const float*)d_in[2];
    const float* c_attn_b     = (const float*)d_in[3];
    const float* self_proj_w  = (const float*)d_in[4];
    const float* self_proj_b  = (const float*)d_in[5];
    const float* q_w          = (const float*)d_in[6];
    const float* q_b          = (const float*)d_in[7];
    const float* kv_w         = (const float*)d_in[8];
    const float* kv_b         = (const float*)d_in[9];
    const float* cross_proj_w = (const float*)d_in[10];
    const float* cross_proj_b = (const float*)d_in[11];
    const float* fc_w         = (const float*)d_in[12];
    const float* fc_b         = (const float*)d_in[13];
    const float* mlp_proj_w   = (const float*)d_in[14];
    const float* mlp_proj_b   = (const float*)d_in[15];
    const float* ln1_g        = (const float*)d_in[16];
    const float* ln1_b        = (const float*)d_in[17];
    const float* ln2_g        = (const float*)d_in[18];
    const float* ln2_b        = (const float*)d_in[19];
    const float* ln3_g        = (const float*)d_in[20];
    const float* ln3_b        = (const float*)d_in[21];
    float* out = (float*)d_out;

    float *t, *x1, *x2;
    __half *qkvh, *abufh, *xh, *ctxh, *x1h, *x2h, *qh, *kvh, *hh, *wth;
    cudaGetSymbolAddress((void**)&t,     g_t);
    cudaGetSymbolAddress((void**)&x1,    g_x1);
    cudaGetSymbolAddress((void**)&x2,    g_x2);
    cudaGetSymbolAddress((void**)&qkvh,  g_qkvh);
    cudaGetSymbolAddress((void**)&abufh, g_abufh);
    cudaGetSymbolAddress((void**)&xh,    g_xh);
    cudaGetSymbolAddress((void**)&ctxh,  g_ctxh);
    cudaGetSymbolAddress((void**)&x1h,   g_x1h);
    cudaGetSymbolAddress((void**)&x2h,   g_x2h);
    cudaGetSymbolAddress((void**)&qh,    g_qh);
    cudaGetSymbolAddress((void**)&kvh,   g_kvh);
    cudaGetSymbolAddress((void**)&hh,    g_hh);
    cudaGetSymbolAddress((void**)&wth,   g_wth);

    __half* cattnT = wth;                        // [3072,1024]
    __half* selfT  = wth +  3l*1024*1024;
    __half* qT     = wth +  4l*1024*1024;
    __half* kvT    = wth +  5l*1024*1024;        // [2048,1024]
    __half* crossT = wth +  7l*1024*1024;
    __half* fcT    = wth +  8l*1024*1024;        // [4096,1024]
    __half* mlpT   = wth + 12l*1024*1024;        // [1024,4096]

    const int SMG = (128*40 + 128*40) * 3 * 2;          // 61440 B (3 stages)
    const int SMF = (64*72 + 3*(2*64*72)) * 2;          // 64512 B (Q + 3 KV stages)

    static bool init_done = false;
    static cudaStream_t s2;
    static cudaEvent_t evStart, evF, evW, evKV;
    if (!init_done) {
        cudaFuncSetAttribute(gemm_mma<EPI_BIAS, true>,      cudaFuncAttributeMaxDynamicSharedMemorySize, SMG);
        cudaFuncSetAttribute(gemm_mma<EPI_BIAS, false>,     cudaFuncAttributeMaxDynamicSharedMemorySize, SMG);
        cudaFuncSetAttribute(gemm_mma<EPI_BIAS_GELU, true>, cudaFuncAttributeMaxDynamicSharedMemorySize, SMG);
        cudaFuncSetAttribute(flash_attn, cudaFuncAttributeMaxDynamicSharedMemorySize, SMF);
        cudaStreamCreateWithFlags(&s2, cudaStreamNonBlocking);
        cudaEventCreateWithFlags(&evStart, cudaEventDisableTiming);
        cudaEventCreateWithFlags(&evF,     cudaEventDisableTiming);
        cudaEventCreateWithFlags(&evW,     cudaEventDisableTiming);
        cudaEventCreateWithFlags(&evKV,    cudaEventDisableTiming);
        init_done = true;
    }

    const int M = NB * SEQ;                  // 4096

    // ---- fork: side stream does weight prep, then the kv projection ----
    cudaEventRecord(evStart, 0);
    cudaStreamWaitEvent(s2, evStart, 0);

    // main: input converts (xh, ctxh)
    f2h_dual<<<8192, 256>>>(x, xh, ctx, ctxh, M*DIM/4);
    cudaEventRecord(evF, 0);

    // side: all weight transposes
    prep_weights<<<16384, dim3(32, 8), 0, s2>>>(
        c_attn_w, self_proj_w, q_w, kv_w, cross_proj_w, fc_w, mlp_proj_w,
        cattnT, selfT, qT, kvT, crossT, fcT, mlpT);
    cudaEventRecord(evW, s2);

    // side: kv = ctx @ kv_w + b  (needs ctxh from main + kvT local)
    cudaStreamWaitEvent(s2, evF, 0);
    gemm_mma<EPI_BIAS, true><<<dim3(16, 32), 256, SMG, s2>>>(
        ctxh, kvT, kv_b, nullptr, kvh, DIM, DIM, DIM, 2*DIM);
    cudaEventRecord(evKV, s2);

    // main waits for weights (cattnT) before qkv
    cudaStreamWaitEvent(0, evW, 0);

    // 1. qkv = x @ c_attn_w + b   (half out)
    gemm_mma<EPI_BIAS, true><<<dim3(24, 32), 256, SMG>>>(
        xh, cattnT, c_attn_b, nullptr, qkvh, DIM, DIM, DIM, 3*DIM);

    // 2-4. fused causal self-attention -> abufh
    flash_attn<<<dim3(16, NB*NHEAD), 128, SMF>>>(
        qkvh, qkvh + DIM, qkvh + 2*DIM, abufh, 3*DIM, 3*DIM, 1);

    // 5. t = a @ self_proj_w + b  (fp32 out)
    gemm_mma<EPI_BIAS, false><<<dim3(8, 32), 256, SMG>>>(
        abufh, selfT, self_proj_b, t, nullptr, DIM, DIM, DIM, DIM);

    // 6. x1 = LN(x + t)  (+ half copy)
    add_ln<<<M, 256>>>(x, t, ln1_g, ln1_b, x1, x1h);

    // 7. q = x1 @ q_w + b  (half out)
    gemm_mma<EPI_BIAS, true><<<dim3(8, 32), 256, SMG>>>(
        x1h, qT, q_b, nullptr, qh, DIM, DIM, DIM, DIM);

    // join: cross-attention needs kv from side stream
    cudaStreamWaitEvent(0, evKV, 0);

    // 9-11. fused cross-attention -> abufh
    flash_attn<<<dim3(16, NB*NHEAD), 128, SMF>>>(
        qh, kvh, kvh + DIM, abufh, DIM, 2*DIM, 0);

    // 12. t = a @ cross_proj_w + b  (fp32 out)
    gemm_mma<EPI_BIAS, false><<<dim3(8, 32), 256, SMG>>>(
        abufh, crossT, cross_proj_b, t, nullptr, DIM, DIM, DIM, DIM);

    // 13. x2 = LN(x1 + t)  (+ half copy)
    add_ln<<<M, 256>>>(x1, t, ln2_g, ln2_b, x2, x2h);

    // 14. h = gelu(x2 @ fc_w + b)  (half out)
    gemm_mma<EPI_BIAS_GELU, true><<<dim3(32, 32), 256, SMG>>>(
        x2h, fcT, fc_b, nullptr, hh, DIM, DIM, DIM, 4*DIM);

    // 15. t = h @ mlp_proj_w + b  (fp32 out)
    gemm_mma<EPI_BIAS, false><<<dim3(8, 32), 256, SMG>>>(
        hh, mlpT, mlp_proj_b, t, nullptr, 4*DIM, 4*DIM, 4*DIM, DIM);

    // 16. out = LN(x2 + t)
    add_ln<<<M, 256>>>(x2, t, ln3_g, ln3_b, out, nullptr);
}